// round 1
// baseline (speedup 1.0000x reference)
#include <cuda_runtime.h>
#include <math.h>

#define T_TOK 4096
#define C_DIM 256
#define C3    768
#define FF    1024
#define HEADS 8
#define HD    32
#define EPS   1e-5f

// ---------------- scratch (device globals; no allocation) ----------------
__device__ float g_tok0[T_TOK * C_DIM];   // BN'd tokens [t][c]
__device__ float g_tok [T_TOK * C_DIM];   // after proj_in
__device__ float g_y   [T_TOK * C_DIM];   // LN1 output
__device__ float g_qkv [T_TOK * C3];      // qkv
__device__ float g_o   [T_TOK * C_DIM];   // attention output (pre-proj)
__device__ float g_tok2[T_TOK * C_DIM];   // after attn residuals
__device__ float g_z   [T_TOK * C_DIM];   // LN2 output
__device__ float g_h1  [T_TOK * FF];      // FF1+gelu
__device__ float g_tok3[T_TOK * C_DIM];   // after FFN residual
__device__ float g_tmp [T_TOK * C_DIM];   // proj_out (token layout)

// ---------------- BN (folded) + transpose [C,T] -> [T,C] ----------------
__global__ void bn_transpose_k(const float* __restrict__ x,
                               const float* __restrict__ gamma,
                               const float* __restrict__ beta,
                               const float* __restrict__ mean,
                               const float* __restrict__ var,
                               float* __restrict__ tok0) {
    __shared__ float sm[32][33];
    int c0 = blockIdx.x * 32, t0 = blockIdx.y * 32;
    int tx = threadIdx.x, ty = threadIdx.y;
    int c = c0 + ty;
    float a  = gamma[c] * rsqrtf(var[c] + EPS);
    float bb = beta[c] - mean[c] * a;
    sm[ty][tx] = x[c * T_TOK + t0 + tx] * a + bb;
    __syncthreads();
    tok0[(t0 + ty) * C_DIM + c0 + tx] = sm[tx][ty];
}

// ---------------- transpose back + image residual ----------------
__global__ void out_transpose_k(const float* __restrict__ tmp,   // [t][c]
                                const float* __restrict__ xin,   // [c][t]
                                float* __restrict__ out) {       // [c][t]
    __shared__ float sm[32][33];
    int c0 = blockIdx.x * 32, t0 = blockIdx.y * 32;
    int tx = threadIdx.x, ty = threadIdx.y;
    sm[ty][tx] = tmp[(t0 + ty) * C_DIM + c0 + tx];
    __syncthreads();
    int c = c0 + ty, t = t0 + tx;
    out[c * T_TOK + t] = sm[tx][ty] + xin[c * T_TOK + t];
}

// ---------------- LayerNorm over last dim (256), warp per row ----------------
__global__ void ln_k(const float* __restrict__ x,
                     const float* __restrict__ g,
                     const float* __restrict__ b,
                     float* __restrict__ y) {
    int row  = blockIdx.x * 8 + (threadIdx.x >> 5);
    int lane = threadIdx.x & 31;
    const float* xr = x + row * C_DIM;
    float v[8], s = 0.f, s2 = 0.f;
#pragma unroll
    for (int i = 0; i < 8; i++) {
        v[i] = xr[lane + 32 * i];
        s += v[i];
        s2 += v[i] * v[i];
    }
#pragma unroll
    for (int off = 16; off > 0; off >>= 1) {
        s  += __shfl_xor_sync(0xffffffffu, s,  off);
        s2 += __shfl_xor_sync(0xffffffffu, s2, off);
    }
    float mu  = s * (1.f / C_DIM);
    float varr = s2 * (1.f / C_DIM) - mu * mu;
    float r = rsqrtf(varr + EPS);
    float* yr = y + row * C_DIM;
#pragma unroll
    for (int i = 0; i < 8; i++) {
        int c = lane + 32 * i;
        yr[c] = (v[i] - mu) * r * g[c] + b[c];
    }
}

// ---------------- generic GEMM: out[m][n] = act(A[m,:].W[n,:] + bias + adds) ----
// BM=128, BN=64, BK=16, 256 threads, 8x4 microtile.
__global__ __launch_bounds__(256)
void gemm_k(const float* __restrict__ A, const float* __restrict__ W,
            const float* __restrict__ bias,
            const float* __restrict__ add1, const float* __restrict__ add2,
            float* __restrict__ out, int M, int N, int K, int act) {
    __shared__ float As[16][132];   // [k][m], padded (132 floats = 16B aligned rows)
    __shared__ float Ws[16][68];    // [k][n]
    int tid = threadIdx.x;
    int tx = tid & 15, ty = tid >> 4;     // 16x16 thread grid
    int m0 = blockIdx.y * 128, n0 = blockIdx.x * 64;
    int lk = tid & 15, lr = tid >> 4;
    float acc[8][4];
#pragma unroll
    for (int i = 0; i < 8; i++)
#pragma unroll
        for (int j = 0; j < 4; j++) acc[i][j] = 0.f;

    for (int k0 = 0; k0 < K; k0 += 16) {
#pragma unroll
        for (int i = 0; i < 8; i++) {
            int m = lr + i * 16;
            As[lk][m] = A[(size_t)(m0 + m) * K + k0 + lk];
        }
#pragma unroll
        for (int i = 0; i < 4; i++) {
            int n = lr + i * 16;
            Ws[lk][n] = W[(size_t)(n0 + n) * K + k0 + lk];
        }
        __syncthreads();
#pragma unroll
        for (int kk = 0; kk < 16; kk++) {
            float a[8], b[4];
            const float4* ap = reinterpret_cast<const float4*>(&As[kk][ty * 8]);
            float4 a0 = ap[0], a1 = ap[1];
            a[0]=a0.x; a[1]=a0.y; a[2]=a0.z; a[3]=a0.w;
            a[4]=a1.x; a[5]=a1.y; a[6]=a1.z; a[7]=a1.w;
            const float4* bp = reinterpret_cast<const float4*>(&Ws[kk][tx * 4]);
            float4 b0 = bp[0];
            b[0]=b0.x; b[1]=b0.y; b[2]=b0.z; b[3]=b0.w;
#pragma unroll
            for (int i = 0; i < 8; i++)
#pragma unroll
                for (int j = 0; j < 4; j++) acc[i][j] += a[i] * b[j];
        }
        __syncthreads();
    }

#pragma unroll
    for (int i = 0; i < 8; i++) {
        int m = m0 + ty * 8 + i;
#pragma unroll
        for (int j = 0; j < 4; j++) {
            int n = n0 + tx * 4 + j;
            float v = acc[i][j] + bias[n];
            size_t idx = (size_t)m * N + n;
            if (add1) v += add1[idx];
            if (add2) v += add2[idx];
            if (act == 1) v = 0.5f * v * (1.0f + erff(v * 0.70710678118654752f));
            out[idx] = v;
        }
    }
}

// ---------------- flash attention (fp32): 8 heads, T=4096, hd=32 ----------------
// grid (64 qblocks, 8 heads), 256 threads. Each thread: 1 q row (4 threads/row),
// owns 8 output dims; processes 16 keys per key-block for the score phase.
__global__ __launch_bounds__(256)
void attn_k(const float* __restrict__ qkv, float* __restrict__ o) {
    const int h  = blockIdx.y;
    const int q0 = blockIdx.x * 64;
    const int tid = threadIdx.x;
    const int tq = tid >> 2;   // 0..63
    const int g  = tid & 3;    // 0..3

    __shared__ float Ksm[64][36];   // 36-float rows: 16B aligned, conflict-friendly
    __shared__ float Vsm[64][36];
    __shared__ float Psm[64][65];

    const float scale = 0.17677669529663689f;  // 1/sqrt(32)
    float q[32];
    const float* qrow = qkv + (size_t)(q0 + tq) * C3 + h * HD;
#pragma unroll
    for (int d = 0; d < 32; d++) q[d] = qrow[d] * scale;

    float acc[8];
#pragma unroll
    for (int d = 0; d < 8; d++) acc[d] = 0.f;
    float m_i = -1e30f, l_i = 0.f;

    for (int kb = 0; kb < 64; kb++) {
        __syncthreads();
        // load K,V tiles (64 x 32 each)
#pragma unroll
        for (int i = 0; i < 8; i++) {
            int e = tid + i * 256;
            int r = e >> 5, cd = e & 31;
            size_t gidx = (size_t)(kb * 64 + r) * C3 + h * HD + cd;
            Ksm[r][cd] = qkv[C_DIM + gidx];
            Vsm[r][cd] = qkv[2 * C_DIM + gidx];
        }
        __syncthreads();

        // scores for 16 keys
        float s[16], mx = -1e30f;
#pragma unroll
        for (int j = 0; j < 16; j++) {
            int key = g * 16 + j;
            const float4* kr = reinterpret_cast<const float4*>(&Ksm[key][0]);
            float acc_s = 0.f;
#pragma unroll
            for (int dv = 0; dv < 8; dv++) {
                float4 kv = kr[dv];
                acc_s += q[dv*4+0]*kv.x + q[dv*4+1]*kv.y + q[dv*4+2]*kv.z + q[dv*4+3]*kv.w;
            }
            s[j] = acc_s;
            mx = fmaxf(mx, acc_s);
        }
        mx = fmaxf(mx, __shfl_xor_sync(0xffffffffu, mx, 1));
        mx = fmaxf(mx, __shfl_xor_sync(0xffffffffu, mx, 2));

        float m_new = fmaxf(m_i, mx);
        float corr  = __expf(m_i - m_new);
        float psum = 0.f;
#pragma unroll
        for (int j = 0; j < 16; j++) {
            float p = __expf(s[j] - m_new);
            Psm[tq][g * 16 + j] = p;
            psum += p;
        }
        psum += __shfl_xor_sync(0xffffffffu, psum, 1);
        psum += __shfl_xor_sync(0xffffffffu, psum, 2);
        l_i = l_i * corr + psum;
        m_i = m_new;
#pragma unroll
        for (int d = 0; d < 8; d++) acc[d] *= corr;
        __syncthreads();

        // PV accumulate: acc[d] += sum_key P[tq][key] * V[key][g*8+d]
#pragma unroll 4
        for (int key = 0; key < 64; key++) {
            float p = Psm[tq][key];
            const float4* vr = reinterpret_cast<const float4*>(&Vsm[key][0]);
            float4 v0 = vr[g * 2], v1 = vr[g * 2 + 1];
            acc[0] += p * v0.x; acc[1] += p * v0.y;
            acc[2] += p * v0.z; acc[3] += p * v0.w;
            acc[4] += p * v1.x; acc[5] += p * v1.y;
            acc[6] += p * v1.z; acc[7] += p * v1.w;
        }
    }

    float inv = 1.f / l_i;
    float* orow = o + (size_t)(q0 + tq) * C_DIM + h * HD + g * 8;
#pragma unroll
    for (int d = 0; d < 8; d++) orow[d] = acc[d] * inv;
}

// ---------------- launch ----------------
template <typename Sym>
static float* dev_ptr(const Sym& sym) {
    void* p = nullptr;
    cudaGetSymbolAddress(&p, sym);
    return (float*)p;
}

extern "C" void kernel_launch(void* const* d_in, const int* in_sizes, int n_in,
                              void* d_out, int out_size) {
    (void)in_sizes; (void)n_in; (void)out_size;
    const float* x        = (const float*)d_in[0];
    const float* bn_gamma = (const float*)d_in[1];
    const float* bn_beta  = (const float*)d_in[2];
    const float* bn_mean  = (const float*)d_in[3];
    const float* bn_var   = (const float*)d_in[4];
    const float* w_in     = (const float*)d_in[5];
    const float* b_in     = (const float*)d_in[6];
    const float* ln1_g    = (const float*)d_in[7];
    const float* ln1_b    = (const float*)d_in[8];
    const float* w_qkv    = (const float*)d_in[9];
    const float* b_qkv    = (const float*)d_in[10];
    const float* w_ap     = (const float*)d_in[11];
    const float* b_ap     = (const float*)d_in[12];
    const float* ln2_g    = (const float*)d_in[13];
    const float* ln2_b    = (const float*)d_in[14];
    const float* w_ff1    = (const float*)d_in[15];
    const float* b_ff1    = (const float*)d_in[16];
    const float* w_ff2    = (const float*)d_in[17];
    const float* b_ff2    = (const float*)d_in[18];
    const float* w_out    = (const float*)d_in[19];
    const float* b_out    = (const float*)d_in[20];
    float* out = (float*)d_out;

    float* tok0 = dev_ptr(g_tok0);
    float* tok  = dev_ptr(g_tok);
    float* y    = dev_ptr(g_y);
    float* qkv  = dev_ptr(g_qkv);
    float* ov   = dev_ptr(g_o);
    float* tok2 = dev_ptr(g_tok2);
    float* z    = dev_ptr(g_z);
    float* h1   = dev_ptr(g_h1);
    float* tok3 = dev_ptr(g_tok3);
    float* tmp  = dev_ptr(g_tmp);

    // 1) BN + transpose to tokens
    bn_transpose_k<<<dim3(C_DIM / 32, T_TOK / 32), dim3(32, 32)>>>(
        x, bn_gamma, bn_beta, bn_mean, bn_var, tok0);
    // 2) proj_in
    gemm_k<<<dim3(C_DIM / 64, T_TOK / 128), 256>>>(
        tok0, w_in, b_in, nullptr, nullptr, tok, T_TOK, C_DIM, C_DIM, 0);
    // 3) LN1
    ln_k<<<T_TOK / 8, 256>>>(tok, ln1_g, ln1_b, y);
    // 4) QKV
    gemm_k<<<dim3(C3 / 64, T_TOK / 128), 256>>>(
        y, w_qkv, b_qkv, nullptr, nullptr, qkv, T_TOK, C3, C_DIM, 0);
    // 5) attention
    attn_k<<<dim3(T_TOK / 64, HEADS), 256>>>(qkv, ov);
    // 6) attn proj + y + tok residuals
    gemm_k<<<dim3(C_DIM / 64, T_TOK / 128), 256>>>(
        ov, w_ap, b_ap, y, tok, tok2, T_TOK, C_DIM, C_DIM, 0);
    // 7) LN2
    ln_k<<<T_TOK / 8, 256>>>(tok2, ln2_g, ln2_b, z);
    // 8) FF1 + gelu
    gemm_k<<<dim3(FF / 64, T_TOK / 128), 256>>>(
        z, w_ff1, b_ff1, nullptr, nullptr, h1, T_TOK, FF, C_DIM, 1);
    // 9) FF2 + tok2 residual
    gemm_k<<<dim3(C_DIM / 64, T_TOK / 128), 256>>>(
        h1, w_ff2, b_ff2, tok2, nullptr, tok3, T_TOK, C_DIM, FF, 0);
    // 10) proj_out (token layout)
    gemm_k<<<dim3(C_DIM / 64, T_TOK / 128), 256>>>(
        tok3, w_out, b_out, nullptr, nullptr, tmp, T_TOK, C_DIM, C_DIM, 0);
    // 11) transpose back + image residual
    out_transpose_k<<<dim3(C_DIM / 32, T_TOK / 32), dim3(32, 32)>>>(tmp, x, out);
}

// round 3
// speedup vs baseline: 8.1232x; 8.1232x over previous
#include <cuda_runtime.h>
#include <math.h>

#define T_TOK 4096
#define C_DIM 256
#define C3    768
#define FF    1024
#define HEADS 8
#define HD    32
#define EPS   1e-5f

// ---------------- scratch (device globals; no allocation) ----------------
__device__ float g_tok0[T_TOK * C_DIM];
__device__ float g_tok [T_TOK * C_DIM];
__device__ float g_y   [T_TOK * C_DIM];
__device__ float g_qkv [T_TOK * C3];
__device__ float g_ov  [T_TOK * C_DIM];
__device__ float g_tok2[T_TOK * C_DIM];
__device__ float g_z   [T_TOK * C_DIM];
__device__ float g_h1  [T_TOK * FF];
__device__ float g_tok3[T_TOK * C_DIM];
__device__ float g_tmp [T_TOK * C_DIM];

// ---------------- helpers ----------------
__device__ __forceinline__ float to_tf32(float x) {
    unsigned u;
    asm("cvt.rna.tf32.f32 %0, %1;" : "=r"(u) : "f"(x));
    return __uint_as_float(u);
}
__device__ __forceinline__ unsigned ldu(const float* p) {
    return *reinterpret_cast<const unsigned*>(p);
}
__device__ __forceinline__ void mma_tf32(float c[4], const unsigned a[4], const unsigned b[2]) {
    asm volatile(
        "mma.sync.aligned.m16n8k8.row.col.f32.tf32.tf32.f32 "
        "{%0,%1,%2,%3}, {%4,%5,%6,%7}, {%8,%9}, {%0,%1,%2,%3};"
        : "+f"(c[0]), "+f"(c[1]), "+f"(c[2]), "+f"(c[3])
        : "r"(a[0]), "r"(a[1]), "r"(a[2]), "r"(a[3]), "r"(b[0]), "r"(b[1]));
}

// ---------------- BN (folded) + transpose [C,T] -> [T,C] ----------------
__global__ void bn_transpose_k(const float* __restrict__ x,
                               const float* __restrict__ gamma,
                               const float* __restrict__ beta,
                               const float* __restrict__ mean,
                               const float* __restrict__ var,
                               float* __restrict__ tok0) {
    __shared__ float sm[32][33];
    int c0 = blockIdx.x * 32, t0 = blockIdx.y * 32;
    int tx = threadIdx.x, ty = threadIdx.y;
    int c = c0 + ty;
    float a  = gamma[c] * rsqrtf(var[c] + EPS);
    float bb = beta[c] - mean[c] * a;
    sm[ty][tx] = x[c * T_TOK + t0 + tx] * a + bb;
    __syncthreads();
    tok0[(t0 + ty) * C_DIM + c0 + tx] = sm[tx][ty];
}

// ---------------- transpose back + image residual ----------------
__global__ void out_transpose_k(const float* __restrict__ tmp,
                                const float* __restrict__ xin,
                                float* __restrict__ out) {
    __shared__ float sm[32][33];
    int c0 = blockIdx.x * 32, t0 = blockIdx.y * 32;
    int tx = threadIdx.x, ty = threadIdx.y;
    sm[ty][tx] = tmp[(t0 + ty) * C_DIM + c0 + tx];
    __syncthreads();
    int c = c0 + ty, t = t0 + tx;
    out[c * T_TOK + t] = sm[tx][ty] + xin[c * T_TOK + t];
}

// ---------------- LayerNorm over last dim (256), warp per row ----------------
__global__ void ln_k(const float* __restrict__ x,
                     const float* __restrict__ g,
                     const float* __restrict__ b,
                     float* __restrict__ y) {
    int row  = blockIdx.x * 8 + (threadIdx.x >> 5);
    int lane = threadIdx.x & 31;
    const float* xr = x + row * C_DIM;
    float v[8], s = 0.f, s2 = 0.f;
#pragma unroll
    for (int i = 0; i < 8; i++) {
        v[i] = xr[lane + 32 * i];
        s += v[i]; s2 += v[i] * v[i];
    }
#pragma unroll
    for (int off = 16; off > 0; off >>= 1) {
        s  += __shfl_xor_sync(0xffffffffu, s,  off);
        s2 += __shfl_xor_sync(0xffffffffu, s2, off);
    }
    float mu = s * (1.f / C_DIM);
    float va = s2 * (1.f / C_DIM) - mu * mu;
    float r = rsqrtf(va + EPS);
#pragma unroll
    for (int i = 0; i < 8; i++) {
        int c = lane + 32 * i;
        y[row * C_DIM + c] = (v[i] - mu) * r * g[c] + b[c];
    }
}

// ---------------- tf32 tensor-core GEMM ----------------
// out[m][n] = act(A[m,:] . W[n,:] + bias[n] + add1 + add2)
// A: [M,K] fp32 row-major, W: [N,K] fp32 row-major (tf32-rounded into smem).
// BM=128 BN=64 BK=32, 256 threads (8 warps, 4x2 warp grid, 32x32 warp tile)
__global__ __launch_bounds__(256)
void gemm_k(const float* __restrict__ A, const float* __restrict__ W,
            const float* __restrict__ bias,
            const float* __restrict__ add1, const float* __restrict__ add2,
            float* __restrict__ out, int M, int N, int K, int act) {
    __shared__ float As[128][36];
    __shared__ float Ws[64][36];
    const int tid = threadIdx.x;
    const int warp = tid >> 5, l = tid & 31;
    const int wm = warp >> 1, wn = warp & 1;
    const int r = l >> 2, tig = l & 3;
    const int m0 = blockIdx.y * 128, n0 = blockIdx.x * 64;

    float acc[2][4][4];
#pragma unroll
    for (int tm = 0; tm < 2; tm++)
#pragma unroll
        for (int j = 0; j < 4; j++)
#pragma unroll
            for (int i = 0; i < 4; i++) acc[tm][j][i] = 0.f;

    for (int k0 = 0; k0 < K; k0 += 32) {
#pragma unroll
        for (int i = 0; i < 4; i++) {
            int s = tid + i * 256;               // 1024 float4 slots
            int row = s >> 3, c4 = (s & 7) * 4;
            float4 v = *reinterpret_cast<const float4*>(A + (size_t)(m0 + row) * K + k0 + c4);
            As[row][c4 + 0] = to_tf32(v.x); As[row][c4 + 1] = to_tf32(v.y);
            As[row][c4 + 2] = to_tf32(v.z); As[row][c4 + 3] = to_tf32(v.w);
        }
#pragma unroll
        for (int i = 0; i < 2; i++) {
            int s = tid + i * 256;               // 512 float4 slots
            int row = s >> 3, c4 = (s & 7) * 4;
            float4 v = *reinterpret_cast<const float4*>(W + (size_t)(n0 + row) * K + k0 + c4);
            Ws[row][c4 + 0] = to_tf32(v.x); Ws[row][c4 + 1] = to_tf32(v.y);
            Ws[row][c4 + 2] = to_tf32(v.z); Ws[row][c4 + 3] = to_tf32(v.w);
        }
        __syncthreads();
#pragma unroll
        for (int kk = 0; kk < 4; kk++) {
            unsigned au[2][4], bu[4][2];
#pragma unroll
            for (int tm = 0; tm < 2; tm++) {
                int mr = wm * 32 + tm * 16 + r;
                au[tm][0] = ldu(&As[mr][kk * 8 + tig]);
                au[tm][1] = ldu(&As[mr + 8][kk * 8 + tig]);
                au[tm][2] = ldu(&As[mr][kk * 8 + tig + 4]);
                au[tm][3] = ldu(&As[mr + 8][kk * 8 + tig + 4]);
            }
#pragma unroll
            for (int j = 0; j < 4; j++) {
                int nr = wn * 32 + 8 * j + r;
                bu[j][0] = ldu(&Ws[nr][kk * 8 + tig]);
                bu[j][1] = ldu(&Ws[nr][kk * 8 + tig + 4]);
            }
#pragma unroll
            for (int tm = 0; tm < 2; tm++)
#pragma unroll
                for (int j = 0; j < 4; j++)
                    mma_tf32(acc[tm][j], au[tm], bu[j]);
        }
        __syncthreads();
    }

    // epilogue
#pragma unroll
    for (int tm = 0; tm < 2; tm++) {
#pragma unroll
        for (int j = 0; j < 4; j++) {
            int rr0 = m0 + wm * 32 + tm * 16 + r;
            int cc = n0 + wn * 32 + 8 * j + tig * 2;
#pragma unroll
            for (int half = 0; half < 2; half++) {
                int rr = rr0 + half * 8;
                float v0 = acc[tm][j][half * 2 + 0] + bias[cc];
                float v1 = acc[tm][j][half * 2 + 1] + bias[cc + 1];
                size_t idx = (size_t)rr * N + cc;
                if (add1) { v0 += add1[idx]; v1 += add1[idx + 1]; }
                if (add2) { v0 += add2[idx]; v1 += add2[idx + 1]; }
                if (act == 1) {
                    v0 = 0.5f * v0 * (1.0f + erff(v0 * 0.70710678118654752f));
                    v1 = 0.5f * v1 * (1.0f + erff(v1 * 0.70710678118654752f));
                }
                out[idx] = v0; out[idx + 1] = v1;
            }
        }
    }
}

// ---------------- flash attention, tf32 tensor cores ----------------
// grid (64 qblocks, 8 heads), 128 threads (4 warps). Warp w owns 16 query rows.
__global__ __launch_bounds__(128)
void attn_k(const float* __restrict__ qkv, float* __restrict__ o) {
    const int h = blockIdx.y, q0 = blockIdx.x * 64;
    const int tid = threadIdx.x;
    const int w = tid >> 5, l = tid & 31;
    const int r = l >> 2, tig = l & 3;
    const float scale = 0.17677669529663689f;  // 1/sqrt(32)

    __shared__ float Qs[64][36];
    __shared__ float Ks[64][36];
    __shared__ float Vs[64][36];
    __shared__ float Psm[64][72];   // per-warp-private 16-row slabs

    // load Q tile (64 x 32)
#pragma unroll
    for (int i = 0; i < 4; i++) {
        int s = tid + i * 128;                   // 512 float4 slots
        int row = s >> 3, c4 = (s & 7) * 4;
        float4 v = *reinterpret_cast<const float4*>(qkv + (size_t)(q0 + row) * C3 + h * HD + c4);
        Qs[row][c4 + 0] = to_tf32(v.x); Qs[row][c4 + 1] = to_tf32(v.y);
        Qs[row][c4 + 2] = to_tf32(v.z); Qs[row][c4 + 3] = to_tf32(v.w);
    }
    __syncthreads();

    unsigned aq[4][4];
#pragma unroll
    for (int kk = 0; kk < 4; kk++) {
        int mr = w * 16 + r;
        aq[kk][0] = ldu(&Qs[mr][kk * 8 + tig]);
        aq[kk][1] = ldu(&Qs[mr + 8][kk * 8 + tig]);
        aq[kk][2] = ldu(&Qs[mr][kk * 8 + tig + 4]);
        aq[kk][3] = ldu(&Qs[mr + 8][kk * 8 + tig + 4]);
    }

    float oa[4][4];
#pragma unroll
    for (int jd = 0; jd < 4; jd++)
#pragma unroll
        for (int i = 0; i < 4; i++) oa[jd][i] = 0.f;
    float m0 = -1e30f, m1 = -1e30f, l0 = 0.f, l1 = 0.f;

    for (int kb = 0; kb < 64; kb++) {
        __syncthreads();
#pragma unroll
        for (int i = 0; i < 4; i++) {
            int s = tid + i * 128;
            int row = s >> 3, c4 = (s & 7) * 4;
            const float* kp = qkv + (size_t)(kb * 64 + row) * C3 + C_DIM + h * HD + c4;
            float4 kv = *reinterpret_cast<const float4*>(kp);
            Ks[row][c4 + 0] = to_tf32(kv.x); Ks[row][c4 + 1] = to_tf32(kv.y);
            Ks[row][c4 + 2] = to_tf32(kv.z); Ks[row][c4 + 3] = to_tf32(kv.w);
            float4 vv = *reinterpret_cast<const float4*>(kp + C_DIM);
            Vs[row][c4 + 0] = to_tf32(vv.x); Vs[row][c4 + 1] = to_tf32(vv.y);
            Vs[row][c4 + 2] = to_tf32(vv.z); Vs[row][c4 + 3] = to_tf32(vv.w);
        }
        __syncthreads();

        // S = Q K^T  (warp: 16 x 64)
        float st[8][4];
#pragma unroll
        for (int j = 0; j < 8; j++) {
#pragma unroll
            for (int i = 0; i < 4; i++) st[j][i] = 0.f;
#pragma unroll
            for (int kk = 0; kk < 4; kk++) {
                unsigned bk[2];
                int nr = 8 * j + r;
                bk[0] = ldu(&Ks[nr][kk * 8 + tig]);
                bk[1] = ldu(&Ks[nr][kk * 8 + tig + 4]);
                mma_tf32(st[j], aq[kk], bk);
            }
        }
        // scale + online softmax
        float mxa = -1e30f, mxb = -1e30f;
#pragma unroll
        for (int j = 0; j < 8; j++) {
            st[j][0] *= scale; st[j][1] *= scale;
            st[j][2] *= scale; st[j][3] *= scale;
            mxa = fmaxf(mxa, fmaxf(st[j][0], st[j][1]));
            mxb = fmaxf(mxb, fmaxf(st[j][2], st[j][3]));
        }
        mxa = fmaxf(mxa, __shfl_xor_sync(0xffffffffu, mxa, 1));
        mxa = fmaxf(mxa, __shfl_xor_sync(0xffffffffu, mxa, 2));
        mxb = fmaxf(mxb, __shfl_xor_sync(0xffffffffu, mxb, 1));
        mxb = fmaxf(mxb, __shfl_xor_sync(0xffffffffu, mxb, 2));

        float m0n = fmaxf(m0, mxa), m1n = fmaxf(m1, mxb);
        float corr0 = __expf(m0 - m0n), corr1 = __expf(m1 - m1n);
        float s0 = 0.f, s1 = 0.f;
#pragma unroll
        for (int j = 0; j < 8; j++) {
            st[j][0] = __expf(st[j][0] - m0n);
            st[j][1] = __expf(st[j][1] - m0n);
            st[j][2] = __expf(st[j][2] - m1n);
            st[j][3] = __expf(st[j][3] - m1n);
            s0 += st[j][0] + st[j][1];
            s1 += st[j][2] + st[j][3];
        }
        s0 += __shfl_xor_sync(0xffffffffu, s0, 1);
        s0 += __shfl_xor_sync(0xffffffffu, s0, 2);
        s1 += __shfl_xor_sync(0xffffffffu, s1, 1);
        s1 += __shfl_xor_sync(0xffffffffu, s1, 2);
        l0 = l0 * corr0 + s0; m0 = m0n;
        l1 = l1 * corr1 + s1; m1 = m1n;
#pragma unroll
        for (int jd = 0; jd < 4; jd++) {
            oa[jd][0] *= corr0; oa[jd][1] *= corr0;
            oa[jd][2] *= corr1; oa[jd][3] *= corr1;
        }

        // stage P through per-warp-private smem slab (accum layout -> A-frag layout)
        {
            int pr = w * 16 + r;
#pragma unroll
            for (int j = 0; j < 8; j++) {
                int pc = 8 * j + 2 * tig;
                float2 lo = make_float2(to_tf32(st[j][0]), to_tf32(st[j][1]));
                float2 hi = make_float2(to_tf32(st[j][2]), to_tf32(st[j][3]));
                *reinterpret_cast<float2*>(&Psm[pr][pc])     = lo;
                *reinterpret_cast<float2*>(&Psm[pr + 8][pc]) = hi;
            }
        }
        __syncwarp();

        // O += P V  (warp: 16 x 32, K = 64 keys)
#pragma unroll
        for (int kk = 0; kk < 8; kk++) {
            unsigned ap[4];
            int pr = w * 16 + r;
            ap[0] = ldu(&Psm[pr][kk * 8 + tig]);
            ap[1] = ldu(&Psm[pr + 8][kk * 8 + tig]);
            ap[2] = ldu(&Psm[pr][kk * 8 + tig + 4]);
            ap[3] = ldu(&Psm[pr + 8][kk * 8 + tig + 4]);
#pragma unroll
            for (int jd = 0; jd < 4; jd++) {
                unsigned bv[2];
                bv[0] = ldu(&Vs[kk * 8 + tig][8 * jd + r]);
                bv[1] = ldu(&Vs[kk * 8 + tig + 4][8 * jd + r]);
                mma_tf32(oa[jd], ap, bv);
            }
        }
        __syncwarp();
    }

    float inv0 = 1.f / l0, inv1 = 1.f / l1;
    int row0 = q0 + w * 16 + r;
#pragma unroll
    for (int jd = 0; jd < 4; jd++) {
        int col = h * HD + 8 * jd + tig * 2;
        *reinterpret_cast<float2*>(o + (size_t)row0 * C_DIM + col) =
            make_float2(oa[jd][0] * inv0, oa[jd][1] * inv0);
        *reinterpret_cast<float2*>(o + (size_t)(row0 + 8) * C_DIM + col) =
            make_float2(oa[jd][2] * inv1, oa[jd][3] * inv1);
    }
}

// ---------------- launch ----------------
template <typename Sym>
static float* dev_ptr(const Sym& sym) {
    void* p = nullptr;
    cudaGetSymbolAddress(&p, sym);
    return (float*)p;
}

extern "C" void kernel_launch(void* const* d_in, const int* in_sizes, int n_in,
                              void* d_out, int out_size) {
    (void)in_sizes; (void)n_in; (void)out_size;
    const float* x        = (const float*)d_in[0];
    const float* bn_gamma = (const float*)d_in[1];
    const float* bn_beta  = (const float*)d_in[2];
    const float* bn_mean  = (const float*)d_in[3];
    const float* bn_var   = (const float*)d_in[4];
    const float* w_in     = (const float*)d_in[5];
    const float* b_in     = (const float*)d_in[6];
    const float* ln1_g    = (const float*)d_in[7];
    const float* ln1_b    = (const float*)d_in[8];
    const float* w_qkv    = (const float*)d_in[9];
    const float* b_qkv    = (const float*)d_in[10];
    const float* w_ap     = (const float*)d_in[11];
    const float* b_ap     = (const float*)d_in[12];
    const float* ln2_g    = (const float*)d_in[13];
    const float* ln2_b    = (const float*)d_in[14];
    const float* w_ff1    = (const float*)d_in[15];
    const float* b_ff1    = (const float*)d_in[16];
    const float* w_ff2    = (const float*)d_in[17];
    const float* b_ff2    = (const float*)d_in[18];
    const float* w_out    = (const float*)d_in[19];
    const float* b_out    = (const float*)d_in[20];
    float* out = (float*)d_out;

    float* tok0 = dev_ptr(g_tok0);
    float* tok  = dev_ptr(g_tok);
    float* y    = dev_ptr(g_y);
    float* qkv  = dev_ptr(g_qkv);
    float* ov   = dev_ptr(g_ov);
    float* tok2 = dev_ptr(g_tok2);
    float* z    = dev_ptr(g_z);
    float* h1   = dev_ptr(g_h1);
    float* tok3 = dev_ptr(g_tok3);
    float* tmp  = dev_ptr(g_tmp);

    // 1) BN + transpose
    bn_transpose_k<<<dim3(C_DIM / 32, T_TOK / 32), dim3(32, 32)>>>(
        x, bn_gamma, bn_beta, bn_mean, bn_var, tok0);
    // 2) proj_in
    gemm_k<<<dim3(C_DIM / 64, T_TOK / 128), 256>>>(
        tok0, w_in, b_in, nullptr, nullptr, tok, T_TOK, C_DIM, C_DIM, 0);
    // 3) LN1
    ln_k<<<T_TOK / 8, 256>>>(tok, ln1_g, ln1_b, y);
    // 4) QKV
    gemm_k<<<dim3(C3 / 64, T_TOK / 128), 256>>>(
        y, w_qkv, b_qkv, nullptr, nullptr, qkv, T_TOK, C3, C_DIM, 0);
    // 5) attention
    attn_k<<<dim3(T_TOK / 64, HEADS), 128>>>(qkv, ov);
    // 6) attn proj + y + tok residuals
    gemm_k<<<dim3(C_DIM / 64, T_TOK / 128), 256>>>(
        ov, w_ap, b_ap, y, tok, tok2, T_TOK, C_DIM, C_DIM, 0);
    // 7) LN2
    ln_k<<<T_TOK / 8, 256>>>(tok2, ln2_g, ln2_b, z);
    // 8) FF1 + gelu
    gemm_k<<<dim3(FF / 64, T_TOK / 128), 256>>>(
        z, w_ff1, b_ff1, nullptr, nullptr, h1, T_TOK, FF, C_DIM, 1);
    // 9) FF2 + tok2 residual
    gemm_k<<<dim3(C_DIM / 64, T_TOK / 128), 256>>>(
        h1, w_ff2, b_ff2, tok2, nullptr, tok3, T_TOK, C_DIM, FF, 0);
    // 10) proj_out
    gemm_k<<<dim3(C_DIM / 64, T_TOK / 128), 256>>>(
        tok3, w_out, b_out, nullptr, nullptr, tmp, T_TOK, C_DIM, C_DIM, 0);
    // 11) transpose back + image residual
    out_transpose_k<<<dim3(C_DIM / 32, T_TOK / 32), dim3(32, 32)>>>(tmp, x, out);
}

// round 4
// speedup vs baseline: 8.3191x; 1.0241x over previous
#include <cuda_runtime.h>
#include <math.h>

#define T_TOK 4096
#define C_DIM 256
#define C3    768
#define FF    1024
#define HEADS 8
#define HD    32
#define EPS   1e-5f

// ---------------- scratch (device globals; no allocation) ----------------
__device__ float g_tok0[T_TOK * C_DIM];
__device__ float g_tok [T_TOK * C_DIM];
__device__ float g_y   [T_TOK * C_DIM];
__device__ float g_qkv [T_TOK * C3];
__device__ float g_ov  [T_TOK * C_DIM];
__device__ float g_tok2[T_TOK * C_DIM];
__device__ float g_z   [T_TOK * C_DIM];
__device__ float g_h1  [T_TOK * FF];
__device__ float g_tok3[T_TOK * C_DIM];
__device__ float g_tmp [T_TOK * C_DIM];

// ---------------- helpers ----------------
__device__ __forceinline__ float to_tf32(float x) {
    unsigned u;
    asm("cvt.rna.tf32.f32 %0, %1;" : "=r"(u) : "f"(x));
    return __uint_as_float(u);
}
__device__ __forceinline__ unsigned ldu(const float* p) {
    return *reinterpret_cast<const unsigned*>(p);
}
__device__ __forceinline__ void mma_tf32(float c[4], const unsigned a[4], const unsigned b[2]) {
    asm volatile(
        "mma.sync.aligned.m16n8k8.row.col.f32.tf32.tf32.f32 "
        "{%0,%1,%2,%3}, {%4,%5,%6,%7}, {%8,%9}, {%0,%1,%2,%3};"
        : "+f"(c[0]), "+f"(c[1]), "+f"(c[2]), "+f"(c[3])
        : "r"(a[0]), "r"(a[1]), "r"(a[2]), "r"(a[3]), "r"(b[0]), "r"(b[1]));
}

// ---------------- BN (folded) + transpose [C,T] -> [T,C] ----------------
__global__ void bn_transpose_k(const float* __restrict__ x,
                               const float* __restrict__ gamma,
                               const float* __restrict__ beta,
                               const float* __restrict__ mean,
                               const float* __restrict__ var,
                               float* __restrict__ tok0) {
    __shared__ float sm[32][33];
    int c0 = blockIdx.x * 32, t0 = blockIdx.y * 32;
    int tx = threadIdx.x, ty = threadIdx.y;
    int c = c0 + ty;
    float a  = gamma[c] * rsqrtf(var[c] + EPS);
    float bb = beta[c] - mean[c] * a;
    sm[ty][tx] = x[c * T_TOK + t0 + tx] * a + bb;
    __syncthreads();
    tok0[(t0 + ty) * C_DIM + c0 + tx] = sm[tx][ty];
}

// ---------------- transpose back + image residual ----------------
__global__ void out_transpose_k(const float* __restrict__ tmp,
                                const float* __restrict__ xin,
                                float* __restrict__ out) {
    __shared__ float sm[32][33];
    int c0 = blockIdx.x * 32, t0 = blockIdx.y * 32;
    int tx = threadIdx.x, ty = threadIdx.y;
    sm[ty][tx] = tmp[(t0 + ty) * C_DIM + c0 + tx];
    __syncthreads();
    int c = c0 + ty, t = t0 + tx;
    out[c * T_TOK + t] = sm[tx][ty] + xin[c * T_TOK + t];
}

// ---------------- LayerNorm over last dim (256), warp per row ----------------
__global__ void ln_k(const float* __restrict__ x,
                     const float* __restrict__ g,
                     const float* __restrict__ b,
                     float* __restrict__ y) {
    int row  = blockIdx.x * 8 + (threadIdx.x >> 5);
    int lane = threadIdx.x & 31;
    const float* xr = x + row * C_DIM;
    float v[8], s = 0.f, s2 = 0.f;
#pragma unroll
    for (int i = 0; i < 8; i++) {
        v[i] = xr[lane + 32 * i];
        s += v[i]; s2 += v[i] * v[i];
    }
#pragma unroll
    for (int off = 16; off > 0; off >>= 1) {
        s  += __shfl_xor_sync(0xffffffffu, s,  off);
        s2 += __shfl_xor_sync(0xffffffffu, s2, off);
    }
    float mu = s * (1.f / C_DIM);
    float va = s2 * (1.f / C_DIM) - mu * mu;
    float r = rsqrtf(va + EPS);
#pragma unroll
    for (int i = 0; i < 8; i++) {
        int c = lane + 32 * i;
        y[row * C_DIM + c] = (v[i] - mu) * r * g[c] + b[c];
    }
}

// ---------------- tf32 tensor-core GEMM, register-prefetch pipelined --------
// BM=128 BN=64 BK=32, 256 threads (8 warps, 4x2 warp grid, 32x32 warp tile)
__global__ __launch_bounds__(256)
void gemm_k(const float* __restrict__ A, const float* __restrict__ W,
            const float* __restrict__ bias,
            const float* __restrict__ add1, const float* __restrict__ add2,
            float* __restrict__ out, int M, int N, int K, int act) {
    __shared__ float As[128][36];
    __shared__ float Ws[64][36];
    const int tid = threadIdx.x;
    const int warp = tid >> 5, l = tid & 31;
    const int wm = warp >> 1, wn = warp & 1;
    const int r = l >> 2, tig = l & 3;
    const int m0 = blockIdx.y * 128, n0 = blockIdx.x * 64;
    const int arow = tid >> 3, ac4 = (tid & 7) * 4;         // A: 4 chunks/thread
    const int wrow = tid >> 3, wc4 = (tid & 7) * 4;         // W: 2 chunks/thread

    float acc[2][4][4];
#pragma unroll
    for (int tm = 0; tm < 2; tm++)
#pragma unroll
        for (int j = 0; j < 4; j++)
#pragma unroll
            for (int i = 0; i < 4; i++) acc[tm][j][i] = 0.f;

    float4 pa[4], pw[2];
    // prefetch tile 0
#pragma unroll
    for (int i = 0; i < 4; i++)
        pa[i] = *reinterpret_cast<const float4*>(A + (size_t)(m0 + arow + i * 32) * K + ac4);
#pragma unroll
    for (int i = 0; i < 2; i++)
        pw[i] = *reinterpret_cast<const float4*>(W + (size_t)(n0 + wrow + i * 32) * K + wc4);
#pragma unroll
    for (int i = 0; i < 4; i++) {
        As[arow + i * 32][ac4 + 0] = to_tf32(pa[i].x); As[arow + i * 32][ac4 + 1] = to_tf32(pa[i].y);
        As[arow + i * 32][ac4 + 2] = to_tf32(pa[i].z); As[arow + i * 32][ac4 + 3] = to_tf32(pa[i].w);
    }
#pragma unroll
    for (int i = 0; i < 2; i++) {
        Ws[wrow + i * 32][wc4 + 0] = to_tf32(pw[i].x); Ws[wrow + i * 32][wc4 + 1] = to_tf32(pw[i].y);
        Ws[wrow + i * 32][wc4 + 2] = to_tf32(pw[i].z); Ws[wrow + i * 32][wc4 + 3] = to_tf32(pw[i].w);
    }
    __syncthreads();

    const int nt = K >> 5;
    for (int t = 0; t < nt; t++) {
        if (t + 1 < nt) {
            int k0 = (t + 1) * 32;
#pragma unroll
            for (int i = 0; i < 4; i++)
                pa[i] = *reinterpret_cast<const float4*>(A + (size_t)(m0 + arow + i * 32) * K + k0 + ac4);
#pragma unroll
            for (int i = 0; i < 2; i++)
                pw[i] = *reinterpret_cast<const float4*>(W + (size_t)(n0 + wrow + i * 32) * K + k0 + wc4);
        }
#pragma unroll
        for (int kk = 0; kk < 4; kk++) {
            unsigned au[2][4], bu[4][2];
#pragma unroll
            for (int tm = 0; tm < 2; tm++) {
                int mr = wm * 32 + tm * 16 + r;
                au[tm][0] = ldu(&As[mr][kk * 8 + tig]);
                au[tm][1] = ldu(&As[mr + 8][kk * 8 + tig]);
                au[tm][2] = ldu(&As[mr][kk * 8 + tig + 4]);
                au[tm][3] = ldu(&As[mr + 8][kk * 8 + tig + 4]);
            }
#pragma unroll
            for (int j = 0; j < 4; j++) {
                int nr = wn * 32 + 8 * j + r;
                bu[j][0] = ldu(&Ws[nr][kk * 8 + tig]);
                bu[j][1] = ldu(&Ws[nr][kk * 8 + tig + 4]);
            }
#pragma unroll
            for (int tm = 0; tm < 2; tm++)
#pragma unroll
                for (int j = 0; j < 4; j++)
                    mma_tf32(acc[tm][j], au[tm], bu[j]);
        }
        __syncthreads();
        if (t + 1 < nt) {
#pragma unroll
            for (int i = 0; i < 4; i++) {
                As[arow + i * 32][ac4 + 0] = to_tf32(pa[i].x); As[arow + i * 32][ac4 + 1] = to_tf32(pa[i].y);
                As[arow + i * 32][ac4 + 2] = to_tf32(pa[i].z); As[arow + i * 32][ac4 + 3] = to_tf32(pa[i].w);
            }
#pragma unroll
            for (int i = 0; i < 2; i++) {
                Ws[wrow + i * 32][wc4 + 0] = to_tf32(pw[i].x); Ws[wrow + i * 32][wc4 + 1] = to_tf32(pw[i].y);
                Ws[wrow + i * 32][wc4 + 2] = to_tf32(pw[i].z); Ws[wrow + i * 32][wc4 + 3] = to_tf32(pw[i].w);
            }
            __syncthreads();
        }
    }

    // epilogue
#pragma unroll
    for (int tm = 0; tm < 2; tm++) {
#pragma unroll
        for (int j = 0; j < 4; j++) {
            int rr0 = m0 + wm * 32 + tm * 16 + r;
            int cc = n0 + wn * 32 + 8 * j + tig * 2;
#pragma unroll
            for (int half = 0; half < 2; half++) {
                int rr = rr0 + half * 8;
                float v0 = acc[tm][j][half * 2 + 0] + bias[cc];
                float v1 = acc[tm][j][half * 2 + 1] + bias[cc + 1];
                size_t idx = (size_t)rr * N + cc;
                if (add1) { v0 += add1[idx]; v1 += add1[idx + 1]; }
                if (add2) { v0 += add2[idx]; v1 += add2[idx + 1]; }
                if (act == 1) {
                    v0 = 0.5f * v0 * (1.0f + erff(v0 * 0.70710678118654752f));
                    v1 = 0.5f * v1 * (1.0f + erff(v1 * 0.70710678118654752f));
                }
                out[idx] = v0; out[idx + 1] = v1;
            }
        }
    }
}

// ---------------- flash attention, tf32, Q-tile 128, 8 warps, pipelined ------
// grid (32 qblocks, 8 heads), 256 threads. Warp w owns 16 query rows.
#define SMEM_ATTN ((2 * 64 * 36 + 128 * 72) * 4)
__global__ __launch_bounds__(256)
void attn_k(const float* __restrict__ qkv, float* __restrict__ o) {
    extern __shared__ float smem[];
    float (*Ks)[36]  = reinterpret_cast<float(*)[36]>(smem);
    float (*Vs)[36]  = reinterpret_cast<float(*)[36]>(smem + 64 * 36);
    float (*Psm)[72] = reinterpret_cast<float(*)[72]>(smem + 2 * 64 * 36);  // also Q staging

    const int h = blockIdx.y, q0 = blockIdx.x * 128;
    const int tid = threadIdx.x;
    const int w = tid >> 5, l = tid & 31;
    const int r = l >> 2, tig = l & 3;
    const float scale = 0.17677669529663689f;  // 1/sqrt(32)
    const int lrow = tid >> 3, lc4 = (tid & 7) * 4;   // K/V loader: 2 chunks/thread

    // stage Q tile (128 x 32) into Psm, tf32-rounded
#pragma unroll
    for (int i = 0; i < 4; i++) {
        int s = tid + i * 256;
        int row = s >> 3, c4 = (s & 7) * 4;
        float4 v = *reinterpret_cast<const float4*>(qkv + (size_t)(q0 + row) * C3 + h * HD + c4);
        Psm[row][c4 + 0] = to_tf32(v.x); Psm[row][c4 + 1] = to_tf32(v.y);
        Psm[row][c4 + 2] = to_tf32(v.z); Psm[row][c4 + 3] = to_tf32(v.w);
    }
    __syncthreads();

    unsigned aq[4][4];
#pragma unroll
    for (int kk = 0; kk < 4; kk++) {
        int mr = w * 16 + r;
        aq[kk][0] = ldu(&Psm[mr][kk * 8 + tig]);
        aq[kk][1] = ldu(&Psm[mr + 8][kk * 8 + tig]);
        aq[kk][2] = ldu(&Psm[mr][kk * 8 + tig + 4]);
        aq[kk][3] = ldu(&Psm[mr + 8][kk * 8 + tig + 4]);
    }

    float oa[4][4];
#pragma unroll
    for (int jd = 0; jd < 4; jd++)
#pragma unroll
        for (int i = 0; i < 4; i++) oa[jd][i] = 0.f;
    float m0 = -1e30f, m1 = -1e30f, l0 = 0.f, l1 = 0.f;

    // prefetch K/V tile 0
    float4 kr[2], vr[2];
#pragma unroll
    for (int i = 0; i < 2; i++) {
        const float* kp = qkv + (size_t)(lrow + i * 32) * C3 + C_DIM + h * HD + lc4;
        kr[i] = *reinterpret_cast<const float4*>(kp);
        vr[i] = *reinterpret_cast<const float4*>(kp + C_DIM);
    }
#pragma unroll
    for (int i = 0; i < 2; i++) {
        int row = lrow + i * 32;
        Ks[row][lc4 + 0] = to_tf32(kr[i].x); Ks[row][lc4 + 1] = to_tf32(kr[i].y);
        Ks[row][lc4 + 2] = to_tf32(kr[i].z); Ks[row][lc4 + 3] = to_tf32(kr[i].w);
        Vs[row][lc4 + 0] = to_tf32(vr[i].x); Vs[row][lc4 + 1] = to_tf32(vr[i].y);
        Vs[row][lc4 + 2] = to_tf32(vr[i].z); Vs[row][lc4 + 3] = to_tf32(vr[i].w);
    }
    __syncthreads();

    for (int kb = 0; kb < 64; kb++) {
        if (kb + 1 < 64) {
#pragma unroll
            for (int i = 0; i < 2; i++) {
                const float* kp = qkv + (size_t)((kb + 1) * 64 + lrow + i * 32) * C3 + C_DIM + h * HD + lc4;
                kr[i] = *reinterpret_cast<const float4*>(kp);
                vr[i] = *reinterpret_cast<const float4*>(kp + C_DIM);
            }
        }

        // S = Q K^T  (warp: 16 x 64)
        float st[8][4];
#pragma unroll
        for (int j = 0; j < 8; j++) {
#pragma unroll
            for (int i = 0; i < 4; i++) st[j][i] = 0.f;
#pragma unroll
            for (int kk = 0; kk < 4; kk++) {
                unsigned bk[2];
                int nr = 8 * j + r;
                bk[0] = ldu(&Ks[nr][kk * 8 + tig]);
                bk[1] = ldu(&Ks[nr][kk * 8 + tig + 4]);
                mma_tf32(st[j], aq[kk], bk);
            }
        }
        // scale + online softmax
        float mxa = -1e30f, mxb = -1e30f;
#pragma unroll
        for (int j = 0; j < 8; j++) {
            st[j][0] *= scale; st[j][1] *= scale;
            st[j][2] *= scale; st[j][3] *= scale;
            mxa = fmaxf(mxa, fmaxf(st[j][0], st[j][1]));
            mxb = fmaxf(mxb, fmaxf(st[j][2], st[j][3]));
        }
        mxa = fmaxf(mxa, __shfl_xor_sync(0xffffffffu, mxa, 1));
        mxa = fmaxf(mxa, __shfl_xor_sync(0xffffffffu, mxa, 2));
        mxb = fmaxf(mxb, __shfl_xor_sync(0xffffffffu, mxb, 1));
        mxb = fmaxf(mxb, __shfl_xor_sync(0xffffffffu, mxb, 2));

        float m0n = fmaxf(m0, mxa), m1n = fmaxf(m1, mxb);
        float corr0 = __expf(m0 - m0n), corr1 = __expf(m1 - m1n);
        float s0 = 0.f, s1 = 0.f;
#pragma unroll
        for (int j = 0; j < 8; j++) {
            st[j][0] = __expf(st[j][0] - m0n);
            st[j][1] = __expf(st[j][1] - m0n);
            st[j][2] = __expf(st[j][2] - m1n);
            st[j][3] = __expf(st[j][3] - m1n);
            s0 += st[j][0] + st[j][1];
            s1 += st[j][2] + st[j][3];
        }
        s0 += __shfl_xor_sync(0xffffffffu, s0, 1);
        s0 += __shfl_xor_sync(0xffffffffu, s0, 2);
        s1 += __shfl_xor_sync(0xffffffffu, s1, 1);
        s1 += __shfl_xor_sync(0xffffffffu, s1, 2);
        l0 = l0 * corr0 + s0; m0 = m0n;
        l1 = l1 * corr1 + s1; m1 = m1n;
#pragma unroll
        for (int jd = 0; jd < 4; jd++) {
            oa[jd][0] *= corr0; oa[jd][1] *= corr0;
            oa[jd][2] *= corr1; oa[jd][3] *= corr1;
        }

        // stage P to own-warp rows of Psm (accum layout -> A-frag layout)
        {
            int pr = w * 16 + r;
#pragma unroll
            for (int j = 0; j < 8; j++) {
                int pc = 8 * j + 2 * tig;
                *reinterpret_cast<float2*>(&Psm[pr][pc]) =
                    make_float2(to_tf32(st[j][0]), to_tf32(st[j][1]));
                *reinterpret_cast<float2*>(&Psm[pr + 8][pc]) =
                    make_float2(to_tf32(st[j][2]), to_tf32(st[j][3]));
            }
        }
        __syncwarp();

        // O += P V  (warp: 16 x 32, K = 64 keys)
#pragma unroll
        for (int kk = 0; kk < 8; kk++) {
            unsigned ap[4];
            int pr = w * 16 + r;
            ap[0] = ldu(&Psm[pr][kk * 8 + tig]);
            ap[1] = ldu(&Psm[pr + 8][kk * 8 + tig]);
            ap[2] = ldu(&Psm[pr][kk * 8 + tig + 4]);
            ap[3] = ldu(&Psm[pr + 8][kk * 8 + tig + 4]);
#pragma unroll
            for (int jd = 0; jd < 4; jd++) {
                unsigned bv[2];
                bv[0] = ldu(&Vs[kk * 8 + tig][8 * jd + r]);
                bv[1] = ldu(&Vs[kk * 8 + tig + 4][8 * jd + r]);
                mma_tf32(oa[jd], ap, bv);
            }
        }
        __syncthreads();   // done reading Ks/Vs
        if (kb + 1 < 64) {
#pragma unroll
            for (int i = 0; i < 2; i++) {
                int row = lrow + i * 32;
                Ks[row][lc4 + 0] = to_tf32(kr[i].x); Ks[row][lc4 + 1] = to_tf32(kr[i].y);
                Ks[row][lc4 + 2] = to_tf32(kr[i].z); Ks[row][lc4 + 3] = to_tf32(kr[i].w);
                Vs[row][lc4 + 0] = to_tf32(vr[i].x); Vs[row][lc4 + 1] = to_tf32(vr[i].y);
                Vs[row][lc4 + 2] = to_tf32(vr[i].z); Vs[row][lc4 + 3] = to_tf32(vr[i].w);
            }
            __syncthreads();
        }
    }

    float inv0 = 1.f / l0, inv1 = 1.f / l1;
    int row0 = q0 + w * 16 + r;
#pragma unroll
    for (int jd = 0; jd < 4; jd++) {
        int col = h * HD + 8 * jd + tig * 2;
        *reinterpret_cast<float2*>(o + (size_t)row0 * C_DIM + col) =
            make_float2(oa[jd][0] * inv0, oa[jd][1] * inv0);
        *reinterpret_cast<float2*>(o + (size_t)(row0 + 8) * C_DIM + col) =
            make_float2(oa[jd][2] * inv1, oa[jd][3] * inv1);
    }
}

// ---------------- launch ----------------
template <typename Sym>
static float* dev_ptr(const Sym& sym) {
    void* p = nullptr;
    cudaGetSymbolAddress(&p, sym);
    return (float*)p;
}

extern "C" void kernel_launch(void* const* d_in, const int* in_sizes, int n_in,
                              void* d_out, int out_size) {
    (void)in_sizes; (void)n_in; (void)out_size;
    const float* x        = (const float*)d_in[0];
    const float* bn_gamma = (const float*)d_in[1];
    const float* bn_beta  = (const float*)d_in[2];
    const float* bn_mean  = (const float*)d_in[3];
    const float* bn_var   = (const float*)d_in[4];
    const float* w_in     = (const float*)d_in[5];
    const float* b_in     = (const float*)d_in[6];
    const float* ln1_g    = (const float*)d_in[7];
    const float* ln1_b    = (const float*)d_in[8];
    const float* w_qkv    = (const float*)d_in[9];
    const float* b_qkv    = (const float*)d_in[10];
    const float* w_ap     = (const float*)d_in[11];
    const float* b_ap     = (const float*)d_in[12];
    const float* ln2_g    = (const float*)d_in[13];
    const float* ln2_b    = (const float*)d_in[14];
    const float* w_ff1    = (const float*)d_in[15];
    const float* b_ff1    = (const float*)d_in[16];
    const float* w_ff2    = (const float*)d_in[17];
    const float* b_ff2    = (const float*)d_in[18];
    const float* w_out    = (const float*)d_in[19];
    const float* b_out    = (const float*)d_in[20];
    float* out = (float*)d_out;

    float* tok0 = dev_ptr(g_tok0);
    float* tok  = dev_ptr(g_tok);
    float* y    = dev_ptr(g_y);
    float* qkv  = dev_ptr(g_qkv);
    float* ov   = dev_ptr(g_ov);
    float* tok2 = dev_ptr(g_tok2);
    float* z    = dev_ptr(g_z);
    float* h1   = dev_ptr(g_h1);
    float* tok3 = dev_ptr(g_tok3);
    float* tmp  = dev_ptr(g_tmp);

    static bool attr_set = false;
    if (!attr_set) {
        cudaFuncSetAttribute(attn_k, cudaFuncAttributeMaxDynamicSharedMemorySize, SMEM_ATTN);
        attr_set = true;
    }

    // 1) BN + transpose
    bn_transpose_k<<<dim3(C_DIM / 32, T_TOK / 32), dim3(32, 32)>>>(
        x, bn_gamma, bn_beta, bn_mean, bn_var, tok0);
    // 2) proj_in
    gemm_k<<<dim3(C_DIM / 64, T_TOK / 128), 256>>>(
        tok0, w_in, b_in, nullptr, nullptr, tok, T_TOK, C_DIM, C_DIM, 0);
    // 3) LN1
    ln_k<<<T_TOK / 8, 256>>>(tok, ln1_g, ln1_b, y);
    // 4) QKV
    gemm_k<<<dim3(C3 / 64, T_TOK / 128), 256>>>(
        y, w_qkv, b_qkv, nullptr, nullptr, qkv, T_TOK, C3, C_DIM, 0);
    // 5) attention
    attn_k<<<dim3(T_TOK / 128, HEADS), 256, SMEM_ATTN>>>(qkv, ov);
    // 6) attn proj + y + tok residuals
    gemm_k<<<dim3(C_DIM / 64, T_TOK / 128), 256>>>(
        ov, w_ap, b_ap, y, tok, tok2, T_TOK, C_DIM, C_DIM, 0);
    // 7) LN2
    ln_k<<<T_TOK / 8, 256>>>(tok2, ln2_g, ln2_b, z);
    // 8) FF1 + gelu
    gemm_k<<<dim3(FF / 64, T_TOK / 128), 256>>>(
        z, w_ff1, b_ff1, nullptr, nullptr, h1, T_TOK, FF, C_DIM, 1);
    // 9) FF2 + tok2 residual
    gemm_k<<<dim3(C_DIM / 64, T_TOK / 128), 256>>>(
        h1, w_ff2, b_ff2, tok2, nullptr, tok3, T_TOK, C_DIM, FF, 0);
    // 10) proj_out
    gemm_k<<<dim3(C_DIM / 64, T_TOK / 128), 256>>>(
        tok3, w_out, b_out, nullptr, nullptr, tmp, T_TOK, C_DIM, C_DIM, 0);
    // 11) transpose back + image residual
    out_transpose_k<<<dim3(C_DIM / 32, T_TOK / 32), dim3(32, 32)>>>(tmp, x, out);
}

// round 5
// speedup vs baseline: 10.8582x; 1.3052x over previous
#include <cuda_runtime.h>
#include <cuda_bf16.h>
#include <math.h>

#define T_TOK 4096
#define C_DIM 256
#define C3    768
#define FF    1024
#define HEADS 8
#define HD    32
#define EPS   1e-5f
#define KVS   2

// ---------------- scratch (device globals; no allocation) ----------------
__device__ float g_tok0[T_TOK * C_DIM];
__device__ float g_tok [T_TOK * C_DIM];
__device__ float g_y   [T_TOK * C_DIM];
__device__ float g_qkv [T_TOK * C3];
__device__ float g_ov  [T_TOK * C_DIM];
__device__ float g_tok2[T_TOK * C_DIM];
__device__ float g_z   [T_TOK * C_DIM];
__device__ float g_h1  [T_TOK * FF];
__device__ float g_tok3[T_TOK * C_DIM];
__device__ float g_tmp [T_TOK * C_DIM];
__device__ float g_opart[KVS * T_TOK * C_DIM];          // unnormalized partial O
__device__ float g_ml   [KVS * T_TOK * HEADS * 2];      // (m, l) per split/row/head

// ---------------- helpers ----------------
__device__ __forceinline__ float to_tf32(float x) {
    unsigned u;
    asm("cvt.rna.tf32.f32 %0, %1;" : "=r"(u) : "f"(x));
    return __uint_as_float(u);
}
__device__ __forceinline__ unsigned ldu(const float* p) {
    return *reinterpret_cast<const unsigned*>(p);
}
__device__ __forceinline__ unsigned ldub(const __nv_bfloat16* p) {
    return *reinterpret_cast<const unsigned*>(p);
}
__device__ __forceinline__ unsigned pack_bf16(float lo, float hi) {
    __nv_bfloat162 t = __floats2bfloat162_rn(lo, hi);
    return *reinterpret_cast<unsigned*>(&t);
}
__device__ __forceinline__ void mma_tf32(float c[4], const unsigned a[4], const unsigned b[2]) {
    asm volatile(
        "mma.sync.aligned.m16n8k8.row.col.f32.tf32.tf32.f32 "
        "{%0,%1,%2,%3}, {%4,%5,%6,%7}, {%8,%9}, {%0,%1,%2,%3};"
        : "+f"(c[0]), "+f"(c[1]), "+f"(c[2]), "+f"(c[3])
        : "r"(a[0]), "r"(a[1]), "r"(a[2]), "r"(a[3]), "r"(b[0]), "r"(b[1]));
}
__device__ __forceinline__ void mma_bf16(float c[4], const unsigned a[4], const unsigned b[2]) {
    asm volatile(
        "mma.sync.aligned.m16n8k16.row.col.f32.bf16.bf16.f32 "
        "{%0,%1,%2,%3}, {%4,%5,%6,%7}, {%8,%9}, {%0,%1,%2,%3};"
        : "+f"(c[0]), "+f"(c[1]), "+f"(c[2]), "+f"(c[3])
        : "r"(a[0]), "r"(a[1]), "r"(a[2]), "r"(a[3]), "r"(b[0]), "r"(b[1]));
}

// ---------------- BN (folded) + transpose [C,T] -> [T,C] ----------------
__global__ void bn_transpose_k(const float* __restrict__ x,
                               const float* __restrict__ gamma,
                               const float* __restrict__ beta,
                               const float* __restrict__ mean,
                               const float* __restrict__ var,
                               float* __restrict__ tok0) {
    __shared__ float sm[32][33];
    int c0 = blockIdx.x * 32, t0 = blockIdx.y * 32;
    int tx = threadIdx.x, ty = threadIdx.y;
    int c = c0 + ty;
    float a  = gamma[c] * rsqrtf(var[c] + EPS);
    float bb = beta[c] - mean[c] * a;
    sm[ty][tx] = x[c * T_TOK + t0 + tx] * a + bb;
    __syncthreads();
    tok0[(t0 + ty) * C_DIM + c0 + tx] = sm[tx][ty];
}

// ---------------- transpose back + image residual ----------------
__global__ void out_transpose_k(const float* __restrict__ tmp,
                                const float* __restrict__ xin,
                                float* __restrict__ out) {
    __shared__ float sm[32][33];
    int c0 = blockIdx.x * 32, t0 = blockIdx.y * 32;
    int tx = threadIdx.x, ty = threadIdx.y;
    sm[ty][tx] = tmp[(t0 + ty) * C_DIM + c0 + tx];
    __syncthreads();
    int c = c0 + ty, t = t0 + tx;
    out[c * T_TOK + t] = sm[tx][ty] + xin[c * T_TOK + t];
}

// ---------------- LayerNorm over last dim (256), warp per row ----------------
__global__ void ln_k(const float* __restrict__ x,
                     const float* __restrict__ g,
                     const float* __restrict__ b,
                     float* __restrict__ y) {
    int row  = blockIdx.x * 8 + (threadIdx.x >> 5);
    int lane = threadIdx.x & 31;
    const float* xr = x + row * C_DIM;
    float v[8], s = 0.f, s2 = 0.f;
#pragma unroll
    for (int i = 0; i < 8; i++) {
        v[i] = xr[lane + 32 * i];
        s += v[i]; s2 += v[i] * v[i];
    }
#pragma unroll
    for (int off = 16; off > 0; off >>= 1) {
        s  += __shfl_xor_sync(0xffffffffu, s,  off);
        s2 += __shfl_xor_sync(0xffffffffu, s2, off);
    }
    float mu = s * (1.f / C_DIM);
    float va = s2 * (1.f / C_DIM) - mu * mu;
    float r = rsqrtf(va + EPS);
#pragma unroll
    for (int i = 0; i < 8; i++) {
        int c = lane + 32 * i;
        y[row * C_DIM + c] = (v[i] - mu) * r * g[c] + b[c];
    }
}

// ---------------- tf32 tensor-core GEMM (unchanged from R4) -----------------
__global__ __launch_bounds__(256)
void gemm_k(const float* __restrict__ A, const float* __restrict__ W,
            const float* __restrict__ bias,
            const float* __restrict__ add1, const float* __restrict__ add2,
            float* __restrict__ out, int M, int N, int K, int act) {
    __shared__ float As[128][36];
    __shared__ float Ws[64][36];
    const int tid = threadIdx.x;
    const int warp = tid >> 5, l = tid & 31;
    const int wm = warp >> 1, wn = warp & 1;
    const int r = l >> 2, tig = l & 3;
    const int m0 = blockIdx.y * 128, n0 = blockIdx.x * 64;
    const int arow = tid >> 3, ac4 = (tid & 7) * 4;
    const int wrow = tid >> 3, wc4 = (tid & 7) * 4;

    float acc[2][4][4];
#pragma unroll
    for (int tm = 0; tm < 2; tm++)
#pragma unroll
        for (int j = 0; j < 4; j++)
#pragma unroll
            for (int i = 0; i < 4; i++) acc[tm][j][i] = 0.f;

    float4 pa[4], pw[2];
#pragma unroll
    for (int i = 0; i < 4; i++)
        pa[i] = *reinterpret_cast<const float4*>(A + (size_t)(m0 + arow + i * 32) * K + ac4);
#pragma unroll
    for (int i = 0; i < 2; i++)
        pw[i] = *reinterpret_cast<const float4*>(W + (size_t)(n0 + wrow + i * 32) * K + wc4);
#pragma unroll
    for (int i = 0; i < 4; i++) {
        As[arow + i * 32][ac4 + 0] = to_tf32(pa[i].x); As[arow + i * 32][ac4 + 1] = to_tf32(pa[i].y);
        As[arow + i * 32][ac4 + 2] = to_tf32(pa[i].z); As[arow + i * 32][ac4 + 3] = to_tf32(pa[i].w);
    }
#pragma unroll
    for (int i = 0; i < 2; i++) {
        Ws[wrow + i * 32][wc4 + 0] = to_tf32(pw[i].x); Ws[wrow + i * 32][wc4 + 1] = to_tf32(pw[i].y);
        Ws[wrow + i * 32][wc4 + 2] = to_tf32(pw[i].z); Ws[wrow + i * 32][wc4 + 3] = to_tf32(pw[i].w);
    }
    __syncthreads();

    const int nt = K >> 5;
    for (int t = 0; t < nt; t++) {
        if (t + 1 < nt) {
            int k0 = (t + 1) * 32;
#pragma unroll
            for (int i = 0; i < 4; i++)
                pa[i] = *reinterpret_cast<const float4*>(A + (size_t)(m0 + arow + i * 32) * K + k0 + ac4);
#pragma unroll
            for (int i = 0; i < 2; i++)
                pw[i] = *reinterpret_cast<const float4*>(W + (size_t)(n0 + wrow + i * 32) * K + k0 + wc4);
        }
#pragma unroll
        for (int kk = 0; kk < 4; kk++) {
            unsigned au[2][4], bu[4][2];
#pragma unroll
            for (int tm = 0; tm < 2; tm++) {
                int mr = wm * 32 + tm * 16 + r;
                au[tm][0] = ldu(&As[mr][kk * 8 + tig]);
                au[tm][1] = ldu(&As[mr + 8][kk * 8 + tig]);
                au[tm][2] = ldu(&As[mr][kk * 8 + tig + 4]);
                au[tm][3] = ldu(&As[mr + 8][kk * 8 + tig + 4]);
            }
#pragma unroll
            for (int j = 0; j < 4; j++) {
                int nr = wn * 32 + 8 * j + r;
                bu[j][0] = ldu(&Ws[nr][kk * 8 + tig]);
                bu[j][1] = ldu(&Ws[nr][kk * 8 + tig + 4]);
            }
#pragma unroll
            for (int tm = 0; tm < 2; tm++)
#pragma unroll
                for (int j = 0; j < 4; j++)
                    mma_tf32(acc[tm][j], au[tm], bu[j]);
        }
        __syncthreads();
        if (t + 1 < nt) {
#pragma unroll
            for (int i = 0; i < 4; i++) {
                As[arow + i * 32][ac4 + 0] = to_tf32(pa[i].x); As[arow + i * 32][ac4 + 1] = to_tf32(pa[i].y);
                As[arow + i * 32][ac4 + 2] = to_tf32(pa[i].z); As[arow + i * 32][ac4 + 3] = to_tf32(pa[i].w);
            }
#pragma unroll
            for (int i = 0; i < 2; i++) {
                Ws[wrow + i * 32][wc4 + 0] = to_tf32(pw[i].x); Ws[wrow + i * 32][wc4 + 1] = to_tf32(pw[i].y);
                Ws[wrow + i * 32][wc4 + 2] = to_tf32(pw[i].z); Ws[wrow + i * 32][wc4 + 3] = to_tf32(pw[i].w);
            }
            __syncthreads();
        }
    }

#pragma unroll
    for (int tm = 0; tm < 2; tm++) {
#pragma unroll
        for (int j = 0; j < 4; j++) {
            int rr0 = m0 + wm * 32 + tm * 16 + r;
            int cc = n0 + wn * 32 + 8 * j + tig * 2;
#pragma unroll
            for (int half = 0; half < 2; half++) {
                int rr = rr0 + half * 8;
                float v0 = acc[tm][j][half * 2 + 0] + bias[cc];
                float v1 = acc[tm][j][half * 2 + 1] + bias[cc + 1];
                size_t idx = (size_t)rr * N + cc;
                if (add1) { v0 += add1[idx]; v1 += add1[idx + 1]; }
                if (add2) { v0 += add2[idx]; v1 += add2[idx + 1]; }
                if (act == 1) {
                    v0 = 0.5f * v0 * (1.0f + erff(v0 * 0.70710678118654752f));
                    v1 = 0.5f * v1 * (1.0f + erff(v1 * 0.70710678118654752f));
                }
                out[idx] = v0; out[idx + 1] = v1;
            }
        }
    }
}

// ---------------- flash attention: tf32 QK^T, bf16 PV, KV-split=2 ------------
// grid (32 qblocks, 8 heads, KVS splits), 256 threads (8 warps, 16 q-rows each).
// Emits unnormalized partial O plus (m, l); combined by attn_combine_k.
__global__ __launch_bounds__(256)
void attn_k(const float* __restrict__ qkv,
            float* __restrict__ opart, float* __restrict__ ml) {
    __shared__ float buf[128 * 36];                       // 18.4 KB
    float (*Qst)[36] = reinterpret_cast<float(*)[36]>(buf);
    float (*Ks)[36]  = reinterpret_cast<float(*)[36]>(buf);
    __nv_bfloat16* Vt = reinterpret_cast<__nv_bfloat16*>(buf + 64 * 36);  // [32][72]

    const int h = blockIdx.y, q0 = blockIdx.x * 128, split = blockIdx.z;
    const int tid = threadIdx.x;
    const int w = tid >> 5, l = tid & 31;
    const int r = l >> 2, tig = l & 3;
    const float scale = 0.17677669529663689f;  // 1/sqrt(32)
    const int lrow = tid >> 3, lc4 = (tid & 7) * 4;

    // stage Q tile (128 x 32) tf32
#pragma unroll
    for (int i = 0; i < 4; i++) {
        int s = tid + i * 256;
        int row = s >> 3, c4 = (s & 7) * 4;
        float4 v = *reinterpret_cast<const float4*>(qkv + (size_t)(q0 + row) * C3 + h * HD + c4);
        Qst[row][c4 + 0] = to_tf32(v.x); Qst[row][c4 + 1] = to_tf32(v.y);
        Qst[row][c4 + 2] = to_tf32(v.z); Qst[row][c4 + 3] = to_tf32(v.w);
    }
    __syncthreads();
    unsigned aq[4][4];
#pragma unroll
    for (int kk = 0; kk < 4; kk++) {
        int mr = w * 16 + r;
        aq[kk][0] = ldu(&Qst[mr][kk * 8 + tig]);
        aq[kk][1] = ldu(&Qst[mr + 8][kk * 8 + tig]);
        aq[kk][2] = ldu(&Qst[mr][kk * 8 + tig + 4]);
        aq[kk][3] = ldu(&Qst[mr + 8][kk * 8 + tig + 4]);
    }
    __syncthreads();   // done with Q staging; smem reused for K/V

    float oa[4][4];
#pragma unroll
    for (int jd = 0; jd < 4; jd++)
#pragma unroll
        for (int i = 0; i < 4; i++) oa[jd][i] = 0.f;
    float m0 = -1e30f, m1 = -1e30f, l0 = 0.f, l1 = 0.f;

    const int kb0 = split * 32;
    // prefetch tile 0
    float4 kr[2], vr[2];
#pragma unroll
    for (int i = 0; i < 2; i++) {
        const float* kp = qkv + (size_t)(kb0 * 64 + lrow + i * 32) * C3 + C_DIM + h * HD + lc4;
        kr[i] = *reinterpret_cast<const float4*>(kp);
        vr[i] = *reinterpret_cast<const float4*>(kp + C_DIM);
    }
#pragma unroll
    for (int i = 0; i < 2; i++) {
        int row = lrow + i * 32;
        Ks[row][lc4 + 0] = to_tf32(kr[i].x); Ks[row][lc4 + 1] = to_tf32(kr[i].y);
        Ks[row][lc4 + 2] = to_tf32(kr[i].z); Ks[row][lc4 + 3] = to_tf32(kr[i].w);
        Vt[(lc4 + 0) * 72 + row] = __float2bfloat16(vr[i].x);
        Vt[(lc4 + 1) * 72 + row] = __float2bfloat16(vr[i].y);
        Vt[(lc4 + 2) * 72 + row] = __float2bfloat16(vr[i].z);
        Vt[(lc4 + 3) * 72 + row] = __float2bfloat16(vr[i].w);
    }
    __syncthreads();

    for (int t = 0; t < 32; t++) {
        if (t + 1 < 32) {
#pragma unroll
            for (int i = 0; i < 2; i++) {
                const float* kp = qkv + (size_t)((kb0 + t + 1) * 64 + lrow + i * 32) * C3 + C_DIM + h * HD + lc4;
                kr[i] = *reinterpret_cast<const float4*>(kp);
                vr[i] = *reinterpret_cast<const float4*>(kp + C_DIM);
            }
        }

        // S = Q K^T (tf32; warp: 16 x 64)
        float st[8][4];
#pragma unroll
        for (int j = 0; j < 8; j++) {
#pragma unroll
            for (int i = 0; i < 4; i++) st[j][i] = 0.f;
#pragma unroll
            for (int kk = 0; kk < 4; kk++) {
                unsigned bk[2];
                int nr = 8 * j + r;
                bk[0] = ldu(&Ks[nr][kk * 8 + tig]);
                bk[1] = ldu(&Ks[nr][kk * 8 + tig + 4]);
                mma_tf32(st[j], aq[kk], bk);
            }
        }
        // online softmax (fp32)
        float mxa = -1e30f, mxb = -1e30f;
#pragma unroll
        for (int j = 0; j < 8; j++) {
            st[j][0] *= scale; st[j][1] *= scale;
            st[j][2] *= scale; st[j][3] *= scale;
            mxa = fmaxf(mxa, fmaxf(st[j][0], st[j][1]));
            mxb = fmaxf(mxb, fmaxf(st[j][2], st[j][3]));
        }
        mxa = fmaxf(mxa, __shfl_xor_sync(0xffffffffu, mxa, 1));
        mxa = fmaxf(mxa, __shfl_xor_sync(0xffffffffu, mxa, 2));
        mxb = fmaxf(mxb, __shfl_xor_sync(0xffffffffu, mxb, 1));
        mxb = fmaxf(mxb, __shfl_xor_sync(0xffffffffu, mxb, 2));

        float m0n = fmaxf(m0, mxa), m1n = fmaxf(m1, mxb);
        float corr0 = __expf(m0 - m0n), corr1 = __expf(m1 - m1n);
        float s0 = 0.f, s1 = 0.f;
#pragma unroll
        for (int j = 0; j < 8; j++) {
            st[j][0] = __expf(st[j][0] - m0n);
            st[j][1] = __expf(st[j][1] - m0n);
            st[j][2] = __expf(st[j][2] - m1n);
            st[j][3] = __expf(st[j][3] - m1n);
            s0 += st[j][0] + st[j][1];
            s1 += st[j][2] + st[j][3];
        }
        s0 += __shfl_xor_sync(0xffffffffu, s0, 1);
        s0 += __shfl_xor_sync(0xffffffffu, s0, 2);
        s1 += __shfl_xor_sync(0xffffffffu, s1, 1);
        s1 += __shfl_xor_sync(0xffffffffu, s1, 2);
        l0 = l0 * corr0 + s0; m0 = m0n;
        l1 = l1 * corr1 + s1; m1 = m1n;
#pragma unroll
        for (int jd = 0; jd < 4; jd++) {
            oa[jd][0] *= corr0; oa[jd][1] *= corr0;
            oa[jd][2] *= corr1; oa[jd][3] *= corr1;
        }

        // P fragments directly from S accumulators (bf16, k16 x 4 steps)
        unsigned ap[4][4];
#pragma unroll
        for (int kk = 0; kk < 4; kk++) {
            ap[kk][0] = pack_bf16(st[2 * kk][0],     st[2 * kk][1]);
            ap[kk][1] = pack_bf16(st[2 * kk][2],     st[2 * kk][3]);
            ap[kk][2] = pack_bf16(st[2 * kk + 1][0], st[2 * kk + 1][1]);
            ap[kk][3] = pack_bf16(st[2 * kk + 1][2], st[2 * kk + 1][3]);
        }
        // O += P V  (bf16; warp 16 x 32, 64 keys)
#pragma unroll
        for (int jd = 0; jd < 4; jd++) {
            int nr = 8 * jd + r;
#pragma unroll
            for (int kk = 0; kk < 4; kk++) {
                unsigned bv[2];
                bv[0] = ldub(&Vt[nr * 72 + kk * 16 + 2 * tig]);
                bv[1] = ldub(&Vt[nr * 72 + kk * 16 + 8 + 2 * tig]);
                mma_bf16(oa[jd], ap[kk], bv);
            }
        }
        __syncthreads();
        if (t + 1 < 32) {
#pragma unroll
            for (int i = 0; i < 2; i++) {
                int row = lrow + i * 32;
                Ks[row][lc4 + 0] = to_tf32(kr[i].x); Ks[row][lc4 + 1] = to_tf32(kr[i].y);
                Ks[row][lc4 + 2] = to_tf32(kr[i].z); Ks[row][lc4 + 3] = to_tf32(kr[i].w);
                Vt[(lc4 + 0) * 72 + row] = __float2bfloat16(vr[i].x);
                Vt[(lc4 + 1) * 72 + row] = __float2bfloat16(vr[i].y);
                Vt[(lc4 + 2) * 72 + row] = __float2bfloat16(vr[i].z);
                Vt[(lc4 + 3) * 72 + row] = __float2bfloat16(vr[i].w);
            }
            __syncthreads();
        }
    }

    // store unnormalized partials + (m, l)
    int row0 = q0 + w * 16 + r;
    float* ob = opart + ((size_t)split * T_TOK) * C_DIM;
#pragma unroll
    for (int jd = 0; jd < 4; jd++) {
        int col = h * HD + 8 * jd + tig * 2;
        *reinterpret_cast<float2*>(ob + (size_t)row0 * C_DIM + col) =
            make_float2(oa[jd][0], oa[jd][1]);
        *reinterpret_cast<float2*>(ob + (size_t)(row0 + 8) * C_DIM + col) =
            make_float2(oa[jd][2], oa[jd][3]);
    }
    if (tig == 0) {
        size_t b0 = (((size_t)split * T_TOK + row0) * HEADS + h) * 2;
        size_t b1 = (((size_t)split * T_TOK + row0 + 8) * HEADS + h) * 2;
        ml[b0] = m0; ml[b0 + 1] = l0;
        ml[b1] = m1; ml[b1 + 1] = l1;
    }
}

// ---------------- combine KV splits ----------------
__global__ void attn_combine_k(const float* __restrict__ opart,
                               const float* __restrict__ ml,
                               float* __restrict__ ov) {
    int row  = blockIdx.x * 8 + (threadIdx.x >> 5);
    int lane = threadIdx.x & 31;
#pragma unroll
    for (int k = 0; k < 8; k++) {
        int c = lane + 32 * k;           // head = k
        size_t ba = ((size_t)row * HEADS + k) * 2;
        size_t bb = (((size_t)T_TOK + row) * HEADS + k) * 2;
        float ma = ml[ba], la = ml[ba + 1];
        float mb = ml[bb], lb = ml[bb + 1];
        float m = fmaxf(ma, mb);
        float wa = __expf(ma - m), wb = __expf(mb - m);
        float inv = 1.f / (wa * la + wb * lb);
        float oa = opart[(size_t)row * C_DIM + c];
        float obv = opart[((size_t)T_TOK + row) * C_DIM + c];
        ov[(size_t)row * C_DIM + c] = (wa * oa + wb * obv) * inv;
    }
}

// ---------------- launch ----------------
template <typename Sym>
static float* dev_ptr(const Sym& sym) {
    void* p = nullptr;
    cudaGetSymbolAddress(&p, sym);
    return (float*)p;
}

extern "C" void kernel_launch(void* const* d_in, const int* in_sizes, int n_in,
                              void* d_out, int out_size) {
    (void)in_sizes; (void)n_in; (void)out_size;
    const float* x        = (const float*)d_in[0];
    const float* bn_gamma = (const float*)d_in[1];
    const float* bn_beta  = (const float*)d_in[2];
    const float* bn_mean  = (const float*)d_in[3];
    const float* bn_var   = (const float*)d_in[4];
    const float* w_in     = (const float*)d_in[5];
    const float* b_in     = (const float*)d_in[6];
    const float* ln1_g    = (const float*)d_in[7];
    const float* ln1_b    = (const float*)d_in[8];
    const float* w_qkv    = (const float*)d_in[9];
    const float* b_qkv    = (const float*)d_in[10];
    const float* w_ap     = (const float*)d_in[11];
    const float* b_ap     = (const float*)d_in[12];
    const float* ln2_g    = (const float*)d_in[13];
    const float* ln2_b    = (const float*)d_in[14];
    const float* w_ff1    = (const float*)d_in[15];
    const float* b_ff1    = (const float*)d_in[16];
    const float* w_ff2    = (const float*)d_in[17];
    const float* b_ff2    = (const float*)d_in[18];
    const float* w_out    = (const float*)d_in[19];
    const float* b_out    = (const float*)d_in[20];
    float* out = (float*)d_out;

    float* tok0  = dev_ptr(g_tok0);
    float* tok   = dev_ptr(g_tok);
    float* y     = dev_ptr(g_y);
    float* qkv   = dev_ptr(g_qkv);
    float* ov    = dev_ptr(g_ov);
    float* tok2  = dev_ptr(g_tok2);
    float* z     = dev_ptr(g_z);
    float* h1    = dev_ptr(g_h1);
    float* tok3  = dev_ptr(g_tok3);
    float* tmp   = dev_ptr(g_tmp);
    float* opart = dev_ptr(g_opart);
    float* ml    = dev_ptr(g_ml);

    // 1) BN + transpose
    bn_transpose_k<<<dim3(C_DIM / 32, T_TOK / 32), dim3(32, 32)>>>(
        x, bn_gamma, bn_beta, bn_mean, bn_var, tok0);
    // 2) proj_in
    gemm_k<<<dim3(C_DIM / 64, T_TOK / 128), 256>>>(
        tok0, w_in, b_in, nullptr, nullptr, tok, T_TOK, C_DIM, C_DIM, 0);
    // 3) LN1
    ln_k<<<T_TOK / 8, 256>>>(tok, ln1_g, ln1_b, y);
    // 4) QKV
    gemm_k<<<dim3(C3 / 64, T_TOK / 128), 256>>>(
        y, w_qkv, b_qkv, nullptr, nullptr, qkv, T_TOK, C3, C_DIM, 0);
    // 5) attention (split-KV) + combine
    attn_k<<<dim3(T_TOK / 128, HEADS, KVS), 256>>>(qkv, opart, ml);
    attn_combine_k<<<T_TOK / 8, 256>>>(opart, ml, ov);
    // 6) attn proj + y + tok residuals
    gemm_k<<<dim3(C_DIM / 64, T_TOK / 128), 256>>>(
        ov, w_ap, b_ap, y, tok, tok2, T_TOK, C_DIM, C_DIM, 0);
    // 7) LN2
    ln_k<<<T_TOK / 8, 256>>>(tok2, ln2_g, ln2_b, z);
    // 8) FF1 + gelu
    gemm_k<<<dim3(FF / 64, T_TOK / 128), 256>>>(
        z, w_ff1, b_ff1, nullptr, nullptr, h1, T_TOK, FF, C_DIM, 1);
    // 9) FF2 + tok2 residual
    gemm_k<<<dim3(C_DIM / 64, T_TOK / 128), 256>>>(
        h1, w_ff2, b_ff2, tok2, nullptr, tok3, T_TOK, C_DIM, FF, 0);
    // 10) proj_out
    gemm_k<<<dim3(C_DIM / 64, T_TOK / 128), 256>>>(
        tok3, w_out, b_out, nullptr, nullptr, tmp, T_TOK, C_DIM, C_DIM, 0);
    // 11) transpose back + image residual
    out_transpose_k<<<dim3(C_DIM / 32, T_TOK / 32), dim3(32, 32)>>>(tmp, x, out);
}

// round 6
// speedup vs baseline: 11.9994x; 1.1051x over previous
#include <cuda_runtime.h>
#include <cuda_bf16.h>
#include <math.h>

#define T_TOK 4096
#define C_DIM 256
#define C3    768
#define FF    1024
#define HEADS 8
#define HD    32
#define EPS   1e-5f
#define KVS   4

// ---------------- scratch (device globals; no allocation) ----------------
__device__ float g_tok0[T_TOK * C_DIM];
__device__ float g_tok [T_TOK * C_DIM];
__device__ float g_yt  [T_TOK * C_DIM];   // LN1 out, tf32-rounded
__device__ float g_y32 [T_TOK * C_DIM];   // LN1 out, fp32
__device__ float g_qkv [T_TOK * C3];      // tf32-rounded
__device__ float g_ov  [T_TOK * C_DIM];   // tf32-rounded
__device__ float g_tok2[T_TOK * C_DIM];
__device__ float g_z   [T_TOK * C_DIM];   // tf32-rounded
__device__ float g_h1  [T_TOK * FF];      // tf32-rounded
__device__ float g_tok3[T_TOK * C_DIM];   // tf32-rounded
__device__ float g_tmp [T_TOK * C_DIM];
__device__ float g_opart[KVS * T_TOK * C_DIM];
__device__ float g_l    [KVS * T_TOK * HEADS];
// tf32-rounded weights
__device__ float g_w_in_r [C_DIM * C_DIM];
__device__ float g_w_qkv_r[C3 * C_DIM];
__device__ float g_w_ap_r [C_DIM * C_DIM];
__device__ float g_w_ff1_r[FF * C_DIM];
__device__ float g_w_ff2_r[C_DIM * FF];
__device__ float g_w_out_r[C_DIM * C_DIM];

// ---------------- helpers ----------------
__device__ __forceinline__ float to_tf32(float x) {
    unsigned u;
    asm("cvt.rna.tf32.f32 %0, %1;" : "=r"(u) : "f"(x));
    return __uint_as_float(u);
}
__device__ __forceinline__ float ex2f(float x) {
    float y;
    asm("ex2.approx.f32 %0, %1;" : "=f"(y) : "f"(x));
    return y;
}
__device__ __forceinline__ unsigned ldu(const float* p) {
    return *reinterpret_cast<const unsigned*>(p);
}
__device__ __forceinline__ unsigned ldub(const __nv_bfloat16* p) {
    return *reinterpret_cast<const unsigned*>(p);
}
__device__ __forceinline__ unsigned pack_bf16(float lo, float hi) {
    __nv_bfloat162 t = __floats2bfloat162_rn(lo, hi);
    return *reinterpret_cast<unsigned*>(&t);
}
__device__ __forceinline__ void mma_tf32(float c[4], const unsigned a[4], const unsigned b[2]) {
    asm volatile(
        "mma.sync.aligned.m16n8k8.row.col.f32.tf32.tf32.f32 "
        "{%0,%1,%2,%3}, {%4,%5,%6,%7}, {%8,%9}, {%0,%1,%2,%3};"
        : "+f"(c[0]), "+f"(c[1]), "+f"(c[2]), "+f"(c[3])
        : "r"(a[0]), "r"(a[1]), "r"(a[2]), "r"(a[3]), "r"(b[0]), "r"(b[1]));
}
__device__ __forceinline__ void mma_bf16(float c[4], const unsigned a[4], const unsigned b[2]) {
    asm volatile(
        "mma.sync.aligned.m16n8k16.row.col.f32.bf16.bf16.f32 "
        "{%0,%1,%2,%3}, {%4,%5,%6,%7}, {%8,%9}, {%0,%1,%2,%3};"
        : "+f"(c[0]), "+f"(c[1]), "+f"(c[2]), "+f"(c[3])
        : "r"(a[0]), "r"(a[1]), "r"(a[2]), "r"(a[3]), "r"(b[0]), "r"(b[1]));
}
__device__ __forceinline__ void cp16(float* s, const float* g) {
    unsigned sa = (unsigned)__cvta_generic_to_shared(s);
    asm volatile("cp.async.cg.shared.global [%0], [%1], 16;\n" :: "r"(sa), "l"(g));
}
#define CP_COMMIT() asm volatile("cp.async.commit_group;\n" ::: "memory")
#define CP_WAIT1()  asm volatile("cp.async.wait_group 1;\n" ::: "memory")
#define CP_WAIT0()  asm volatile("cp.async.wait_group 0;\n" ::: "memory")

// ---------------- weight fp32 -> tf32-rounded ----------------
__global__ void round_k(const float* __restrict__ src, float* __restrict__ dst, int n) {
    for (int i = blockIdx.x * blockDim.x + threadIdx.x; i < n; i += gridDim.x * blockDim.x)
        dst[i] = to_tf32(src[i]);
}

// ---------------- BN (folded) + transpose -> tf32-rounded tokens ------------
__global__ void bn_transpose_k(const float* __restrict__ x,
                               const float* __restrict__ gamma,
                               const float* __restrict__ beta,
                               const float* __restrict__ mean,
                               const float* __restrict__ var,
                               float* __restrict__ tok0) {
    __shared__ float sm[32][33];
    int c0 = blockIdx.x * 32, t0 = blockIdx.y * 32;
    int tx = threadIdx.x, ty = threadIdx.y;
    int c = c0 + ty;
    float a  = gamma[c] * rsqrtf(var[c] + EPS);
    float bb = beta[c] - mean[c] * a;
    sm[ty][tx] = x[c * T_TOK + t0 + tx] * a + bb;
    __syncthreads();
    tok0[(t0 + ty) * C_DIM + c0 + tx] = to_tf32(sm[tx][ty]);
}

// ---------------- transpose back + image residual ----------------
__global__ void out_transpose_k(const float* __restrict__ tmp,
                                const float* __restrict__ xin,
                                float* __restrict__ out) {
    __shared__ float sm[32][33];
    int c0 = blockIdx.x * 32, t0 = blockIdx.y * 32;
    int tx = threadIdx.x, ty = threadIdx.y;
    sm[ty][tx] = tmp[(t0 + ty) * C_DIM + c0 + tx];
    __syncthreads();
    int c = c0 + ty, t = t0 + tx;
    out[c * T_TOK + t] = sm[tx][ty] + xin[c * T_TOK + t];
}

// ---------------- LayerNorm: yt (tf32-rounded) + optional fp32 copy ---------
__global__ void ln_k(const float* __restrict__ x,
                     const float* __restrict__ g,
                     const float* __restrict__ b,
                     float* __restrict__ yt, float* __restrict__ y32) {
    int row  = blockIdx.x * 8 + (threadIdx.x >> 5);
    int lane = threadIdx.x & 31;
    const float* xr = x + row * C_DIM;
    float v[8], s = 0.f, s2 = 0.f;
#pragma unroll
    for (int i = 0; i < 8; i++) {
        v[i] = xr[lane + 32 * i];
        s += v[i]; s2 += v[i] * v[i];
    }
#pragma unroll
    for (int off = 16; off > 0; off >>= 1) {
        s  += __shfl_xor_sync(0xffffffffu, s,  off);
        s2 += __shfl_xor_sync(0xffffffffu, s2, off);
    }
    float mu = s * (1.f / C_DIM);
    float va = s2 * (1.f / C_DIM) - mu * mu;
    float r = rsqrtf(va + EPS);
#pragma unroll
    for (int i = 0; i < 8; i++) {
        int c = lane + 32 * i;
        float o = (v[i] - mu) * r * g[c] + b[c];
        yt[row * C_DIM + c] = to_tf32(o);
        if (y32) y32[row * C_DIM + c] = o;
    }
}

// ---------------- tf32 GEMM, cp.async 2-stage, pre-rounded inputs -----------
// BM=128 BN=64 BK=32, 256 threads. Inputs A/W must be tf32-rounded fp32.
#define GSTAGE (192 * 36)   // floats per stage (A 128x36 + W 64x36)
#define SMEM_GEMM (2 * GSTAGE * 4)
__global__ __launch_bounds__(256)
void gemm_k(const float* __restrict__ A, const float* __restrict__ W,
            const float* __restrict__ bias,
            const float* __restrict__ add1, const float* __restrict__ add2,
            float* __restrict__ out, int M, int N, int K, int act, int round_out) {
    extern __shared__ float smg[];
    const int tid = threadIdx.x;
    const int warp = tid >> 5, l = tid & 31;
    const int wm = warp >> 1, wn = warp & 1;
    const int r = l >> 2, tig = l & 3;
    const int m0 = blockIdx.y * 128, n0 = blockIdx.x * 64;
    const int lrow = tid >> 3, lc4 = (tid & 7) * 4;

    float acc[2][4][4];
#pragma unroll
    for (int tm = 0; tm < 2; tm++)
#pragma unroll
        for (int j = 0; j < 4; j++)
#pragma unroll
            for (int i = 0; i < 4; i++) acc[tm][j][i] = 0.f;

    const int nt = K >> 5;
    // prologue: issue tiles 0,1
#pragma unroll
    for (int t0 = 0; t0 < 2; t0++) {
        if (t0 < nt) {
            float* As = smg + t0 * GSTAGE;
            float* Ws = As + 128 * 36;
#pragma unroll
            for (int i = 0; i < 4; i++)
                cp16(&As[(lrow + i * 32) * 36 + lc4],
                     A + (size_t)(m0 + lrow + i * 32) * K + t0 * 32 + lc4);
#pragma unroll
            for (int i = 0; i < 2; i++)
                cp16(&Ws[(lrow + i * 32) * 36 + lc4],
                     W + (size_t)(n0 + lrow + i * 32) * K + t0 * 32 + lc4);
            CP_COMMIT();
        }
    }

    for (int t = 0; t < nt; t++) {
        if (t + 1 < nt) CP_WAIT1(); else CP_WAIT0();
        __syncthreads();
        float* As = smg + (t & 1) * GSTAGE;
        float* Ws = As + 128 * 36;
#pragma unroll
        for (int kk = 0; kk < 4; kk++) {
            unsigned au[2][4], bu[4][2];
#pragma unroll
            for (int tm = 0; tm < 2; tm++) {
                int mr = wm * 32 + tm * 16 + r;
                au[tm][0] = ldu(&As[mr * 36 + kk * 8 + tig]);
                au[tm][1] = ldu(&As[(mr + 8) * 36 + kk * 8 + tig]);
                au[tm][2] = ldu(&As[mr * 36 + kk * 8 + tig + 4]);
                au[tm][3] = ldu(&As[(mr + 8) * 36 + kk * 8 + tig + 4]);
            }
#pragma unroll
            for (int j = 0; j < 4; j++) {
                int nr = wn * 32 + 8 * j + r;
                bu[j][0] = ldu(&Ws[nr * 36 + kk * 8 + tig]);
                bu[j][1] = ldu(&Ws[nr * 36 + kk * 8 + tig + 4]);
            }
#pragma unroll
            for (int tm = 0; tm < 2; tm++)
#pragma unroll
                for (int j = 0; j < 4; j++)
                    mma_tf32(acc[tm][j], au[tm], bu[j]);
        }
        __syncthreads();
        if (t + 2 < nt) {
            float* Asn = smg + (t & 1) * GSTAGE;
            float* Wsn = Asn + 128 * 36;
            int k0 = (t + 2) * 32;
#pragma unroll
            for (int i = 0; i < 4; i++)
                cp16(&Asn[(lrow + i * 32) * 36 + lc4],
                     A + (size_t)(m0 + lrow + i * 32) * K + k0 + lc4);
#pragma unroll
            for (int i = 0; i < 2; i++)
                cp16(&Wsn[(lrow + i * 32) * 36 + lc4],
                     W + (size_t)(n0 + lrow + i * 32) * K + k0 + lc4);
            CP_COMMIT();
        }
    }

    // epilogue
#pragma unroll
    for (int tm = 0; tm < 2; tm++) {
#pragma unroll
        for (int j = 0; j < 4; j++) {
            int rr0 = m0 + wm * 32 + tm * 16 + r;
            int cc = n0 + wn * 32 + 8 * j + tig * 2;
#pragma unroll
            for (int half = 0; half < 2; half++) {
                int rr = rr0 + half * 8;
                float v0 = acc[tm][j][half * 2 + 0] + bias[cc];
                float v1 = acc[tm][j][half * 2 + 1] + bias[cc + 1];
                size_t idx = (size_t)rr * N + cc;
                if (add1) { v0 += add1[idx]; v1 += add1[idx + 1]; }
                if (add2) { v0 += add2[idx]; v1 += add2[idx + 1]; }
                if (act == 1) {
                    v0 = 0.5f * v0 * (1.0f + erff(v0 * 0.70710678118654752f));
                    v1 = 0.5f * v1 * (1.0f + erff(v1 * 0.70710678118654752f));
                }
                if (round_out) { v0 = to_tf32(v0); v1 = to_tf32(v1); }
                out[idx] = v0; out[idx + 1] = v1;
            }
        }
    }
}

// ---------------- flash attention: max-free softmax, KV-split=4 -------------
// qkv is tf32-pre-rounded. grid (32 qblocks, 8 heads, KVS), 256 threads.
__global__ __launch_bounds__(256)
void attn_k(const float* __restrict__ qkv,
            float* __restrict__ opart, float* __restrict__ lpart) {
    __shared__ float buf[128 * 36];
    float (*Qst)[36] = reinterpret_cast<float(*)[36]>(buf);
    float (*Ks)[36]  = reinterpret_cast<float(*)[36]>(buf);
    __nv_bfloat16* Vt = reinterpret_cast<__nv_bfloat16*>(buf + 64 * 36);  // [32][72]

    const int h = blockIdx.y, q0 = blockIdx.x * 128, split = blockIdx.z;
    const int tid = threadIdx.x;
    const int w = tid >> 5, l = tid & 31;
    const int r = l >> 2, tig = l & 3;
    // exp(s * scale) = exp2(s * log2e * scale)
    const float K2 = 1.4426950408889634f * 0.17677669529663689f;
    const int lrow = tid >> 3, lc4 = (tid & 7) * 4;

    // stage Q (pre-rounded; plain copy)
#pragma unroll
    for (int i = 0; i < 4; i++) {
        int s = tid + i * 256;
        int row = s >> 3, c4 = (s & 7) * 4;
        *reinterpret_cast<float4*>(&Qst[row][c4]) =
            *reinterpret_cast<const float4*>(qkv + (size_t)(q0 + row) * C3 + h * HD + c4);
    }
    __syncthreads();
    unsigned aq[4][4];
#pragma unroll
    for (int kk = 0; kk < 4; kk++) {
        int mr = w * 16 + r;
        aq[kk][0] = ldu(&Qst[mr][kk * 8 + tig]);
        aq[kk][1] = ldu(&Qst[mr + 8][kk * 8 + tig]);
        aq[kk][2] = ldu(&Qst[mr][kk * 8 + tig + 4]);
        aq[kk][3] = ldu(&Qst[mr + 8][kk * 8 + tig + 4]);
    }
    __syncthreads();

    float oa[4][4];
#pragma unroll
    for (int jd = 0; jd < 4; jd++)
#pragma unroll
        for (int i = 0; i < 4; i++) oa[jd][i] = 0.f;
    float l0 = 0.f, l1 = 0.f;

    const int NT = (T_TOK / KVS) / 64;       // 16 key tiles per split
    const int kb0 = split * NT;
    float4 kr[2], vr[2];
#pragma unroll
    for (int i = 0; i < 2; i++) {
        const float* kp = qkv + (size_t)(kb0 * 64 + lrow + i * 32) * C3 + C_DIM + h * HD + lc4;
        kr[i] = *reinterpret_cast<const float4*>(kp);
        vr[i] = *reinterpret_cast<const float4*>(kp + C_DIM);
    }
#pragma unroll
    for (int i = 0; i < 2; i++) {
        int row = lrow + i * 32;
        *reinterpret_cast<float4*>(&Ks[row][lc4]) = kr[i];
        Vt[(lc4 + 0) * 72 + row] = __float2bfloat16(vr[i].x);
        Vt[(lc4 + 1) * 72 + row] = __float2bfloat16(vr[i].y);
        Vt[(lc4 + 2) * 72 + row] = __float2bfloat16(vr[i].z);
        Vt[(lc4 + 3) * 72 + row] = __float2bfloat16(vr[i].w);
    }
    __syncthreads();

    for (int t = 0; t < NT; t++) {
        if (t + 1 < NT) {
#pragma unroll
            for (int i = 0; i < 2; i++) {
                const float* kp = qkv + (size_t)((kb0 + t + 1) * 64 + lrow + i * 32) * C3 + C_DIM + h * HD + lc4;
                kr[i] = *reinterpret_cast<const float4*>(kp);
                vr[i] = *reinterpret_cast<const float4*>(kp + C_DIM);
            }
        }

        // S = Q K^T (tf32)
        float st[8][4];
#pragma unroll
        for (int j = 0; j < 8; j++) {
#pragma unroll
            for (int i = 0; i < 4; i++) st[j][i] = 0.f;
#pragma unroll
            for (int kk = 0; kk < 4; kk++) {
                unsigned bk[2];
                int nr = 8 * j + r;
                bk[0] = ldu(&Ks[nr][kk * 8 + tig]);
                bk[1] = ldu(&Ks[nr][kk * 8 + tig + 4]);
                mma_tf32(st[j], aq[kk], bk);
            }
        }
        // max-free softmax: p = exp2(s * K2); accumulate l
#pragma unroll
        for (int j = 0; j < 8; j++) {
            st[j][0] = ex2f(st[j][0] * K2);
            st[j][1] = ex2f(st[j][1] * K2);
            st[j][2] = ex2f(st[j][2] * K2);
            st[j][3] = ex2f(st[j][3] * K2);
            l0 += st[j][0] + st[j][1];
            l1 += st[j][2] + st[j][3];
        }
        // P fragments (bf16) directly from S accumulators
        unsigned ap[4][4];
#pragma unroll
        for (int kk = 0; kk < 4; kk++) {
            ap[kk][0] = pack_bf16(st[2 * kk][0],     st[2 * kk][1]);
            ap[kk][1] = pack_bf16(st[2 * kk][2],     st[2 * kk][3]);
            ap[kk][2] = pack_bf16(st[2 * kk + 1][0], st[2 * kk + 1][1]);
            ap[kk][3] = pack_bf16(st[2 * kk + 1][2], st[2 * kk + 1][3]);
        }
        // O += P V (bf16)
#pragma unroll
        for (int jd = 0; jd < 4; jd++) {
            int nr = 8 * jd + r;
#pragma unroll
            for (int kk = 0; kk < 4; kk++) {
                unsigned bv[2];
                bv[0] = ldub(&Vt[nr * 72 + kk * 16 + 2 * tig]);
                bv[1] = ldub(&Vt[nr * 72 + kk * 16 + 8 + 2 * tig]);
                mma_bf16(oa[jd], ap[kk], bv);
            }
        }
        __syncthreads();
        if (t + 1 < NT) {
#pragma unroll
            for (int i = 0; i < 2; i++) {
                int row = lrow + i * 32;
                *reinterpret_cast<float4*>(&Ks[row][lc4]) = kr[i];
                Vt[(lc4 + 0) * 72 + row] = __float2bfloat16(vr[i].x);
                Vt[(lc4 + 1) * 72 + row] = __float2bfloat16(vr[i].y);
                Vt[(lc4 + 2) * 72 + row] = __float2bfloat16(vr[i].z);
                Vt[(lc4 + 3) * 72 + row] = __float2bfloat16(vr[i].w);
            }
            __syncthreads();
        }
    }

    // end-of-kernel l reduction (deferred from the loop)
    l0 += __shfl_xor_sync(0xffffffffu, l0, 1);
    l0 += __shfl_xor_sync(0xffffffffu, l0, 2);
    l1 += __shfl_xor_sync(0xffffffffu, l1, 1);
    l1 += __shfl_xor_sync(0xffffffffu, l1, 2);

    int row0 = q0 + w * 16 + r;
    float* ob = opart + ((size_t)split * T_TOK) * C_DIM;
#pragma unroll
    for (int jd = 0; jd < 4; jd++) {
        int col = h * HD + 8 * jd + tig * 2;
        *reinterpret_cast<float2*>(ob + (size_t)row0 * C_DIM + col) =
            make_float2(oa[jd][0], oa[jd][1]);
        *reinterpret_cast<float2*>(ob + (size_t)(row0 + 8) * C_DIM + col) =
            make_float2(oa[jd][2], oa[jd][3]);
    }
    if (tig == 0) {
        lpart[((size_t)split * T_TOK + row0) * HEADS + h] = l0;
        lpart[((size_t)split * T_TOK + row0 + 8) * HEADS + h] = l1;
    }
}

// ---------------- combine KV splits (tf32-rounded output) ----------------
__global__ void attn_combine_k(const float* __restrict__ opart,
                               const float* __restrict__ lpart,
                               float* __restrict__ ov) {
    int row  = blockIdx.x * 8 + (threadIdx.x >> 5);
    int lane = threadIdx.x & 31;
#pragma unroll
    for (int k = 0; k < 8; k++) {
        int c = lane + 32 * k;    // head = k
        float lsum = 0.f, osum = 0.f;
#pragma unroll
        for (int s = 0; s < KVS; s++) {
            lsum += lpart[((size_t)s * T_TOK + row) * HEADS + k];
            osum += opart[((size_t)s * T_TOK + row) * C_DIM + c];
        }
        ov[(size_t)row * C_DIM + c] = to_tf32(osum / lsum);
    }
}

// ---------------- launch ----------------
template <typename Sym>
static float* dev_ptr(const Sym& sym) {
    void* p = nullptr;
    cudaGetSymbolAddress(&p, sym);
    return (float*)p;
}

extern "C" void kernel_launch(void* const* d_in, const int* in_sizes, int n_in,
                              void* d_out, int out_size) {
    (void)in_sizes; (void)n_in; (void)out_size;
    const float* x        = (const float*)d_in[0];
    const float* bn_gamma = (const float*)d_in[1];
    const float* bn_beta  = (const float*)d_in[2];
    const float* bn_mean  = (const float*)d_in[3];
    const float* bn_var   = (const float*)d_in[4];
    const float* w_in     = (const float*)d_in[5];
    const float* b_in     = (const float*)d_in[6];
    const float* ln1_g    = (const float*)d_in[7];
    const float* ln1_b    = (const float*)d_in[8];
    const float* w_qkv    = (const float*)d_in[9];
    const float* b_qkv    = (const float*)d_in[10];
    const float* w_ap     = (const float*)d_in[11];
    const float* b_ap     = (const float*)d_in[12];
    const float* ln2_g    = (const float*)d_in[13];
    const float* ln2_b    = (const float*)d_in[14];
    const float* w_ff1    = (const float*)d_in[15];
    const float* b_ff1    = (const float*)d_in[16];
    const float* w_ff2    = (const float*)d_in[17];
    const float* b_ff2    = (const float*)d_in[18];
    const float* w_out    = (const float*)d_in[19];
    const float* b_out    = (const float*)d_in[20];
    float* out = (float*)d_out;

    float* tok0  = dev_ptr(g_tok0);
    float* tok   = dev_ptr(g_tok);
    float* yt    = dev_ptr(g_yt);
    float* y32   = dev_ptr(g_y32);
    float* qkv   = dev_ptr(g_qkv);
    float* ov    = dev_ptr(g_ov);
    float* tok2  = dev_ptr(g_tok2);
    float* z     = dev_ptr(g_z);
    float* h1    = dev_ptr(g_h1);
    float* tok3  = dev_ptr(g_tok3);
    float* tmp   = dev_ptr(g_tmp);
    float* opart = dev_ptr(g_opart);
    float* lpart = dev_ptr(g_l);
    float* w_in_r  = dev_ptr(g_w_in_r);
    float* w_qkv_r = dev_ptr(g_w_qkv_r);
    float* w_ap_r  = dev_ptr(g_w_ap_r);
    float* w_ff1_r = dev_ptr(g_w_ff1_r);
    float* w_ff2_r = dev_ptr(g_w_ff2_r);
    float* w_out_r = dev_ptr(g_w_out_r);

    static bool attr_set = false;
    if (!attr_set) {
        cudaFuncSetAttribute(gemm_k, cudaFuncAttributeMaxDynamicSharedMemorySize, SMEM_GEMM);
        attr_set = true;
    }

    // round weights to tf32
    round_k<<<128, 256>>>(w_in,  w_in_r,  C_DIM * C_DIM);
    round_k<<<128, 256>>>(w_qkv, w_qkv_r, C3 * C_DIM);
    round_k<<<128, 256>>>(w_ap,  w_ap_r,  C_DIM * C_DIM);
    round_k<<<128, 256>>>(w_ff1, w_ff1_r, FF * C_DIM);
    round_k<<<128, 256>>>(w_ff2, w_ff2_r, C_DIM * FF);
    round_k<<<128, 256>>>(w_out, w_out_r, C_DIM * C_DIM);

    // 1) BN + transpose (tf32-rounded)
    bn_transpose_k<<<dim3(C_DIM / 32, T_TOK / 32), dim3(32, 32)>>>(
        x, bn_gamma, bn_beta, bn_mean, bn_var, tok0);
    // 2) proj_in -> tok (fp32)
    gemm_k<<<dim3(C_DIM / 64, T_TOK / 128), 256, SMEM_GEMM>>>(
        tok0, w_in_r, b_in, nullptr, nullptr, tok, T_TOK, C_DIM, C_DIM, 0, 0);
    // 3) LN1 -> yt (rounded) + y32
    ln_k<<<T_TOK / 8, 256>>>(tok, ln1_g, ln1_b, yt, y32);
    // 4) QKV -> qkv (rounded)
    gemm_k<<<dim3(C3 / 64, T_TOK / 128), 256, SMEM_GEMM>>>(
        yt, w_qkv_r, b_qkv, nullptr, nullptr, qkv, T_TOK, C3, C_DIM, 0, 1);
    // 5) attention (split-KV, max-free) + combine (rounded)
    attn_k<<<dim3(T_TOK / 128, HEADS, KVS), 256>>>(qkv, opart, lpart);
    attn_combine_k<<<T_TOK / 8, 256>>>(opart, lpart, ov);
    // 6) attn proj + y + tok -> tok2 (fp32)
    gemm_k<<<dim3(C_DIM / 64, T_TOK / 128), 256, SMEM_GEMM>>>(
        ov, w_ap_r, b_ap, y32, tok, tok2, T_TOK, C_DIM, C_DIM, 0, 0);
    // 7) LN2 -> z (rounded)
    ln_k<<<T_TOK / 8, 256>>>(tok2, ln2_g, ln2_b, z, nullptr);
    // 8) FF1 + gelu -> h1 (rounded)
    gemm_k<<<dim3(FF / 64, T_TOK / 128), 256, SMEM_GEMM>>>(
        z, w_ff1_r, b_ff1, nullptr, nullptr, h1, T_TOK, FF, C_DIM, 1, 1);
    // 9) FF2 + tok2 -> tok3 (rounded)
    gemm_k<<<dim3(C_DIM / 64, T_TOK / 128), 256, SMEM_GEMM>>>(
        h1, w_ff2_r, b_ff2, tok2, nullptr, tok3, T_TOK, C_DIM, FF, 0, 1);
    // 10) proj_out -> tmp (fp32)
    gemm_k<<<dim3(C_DIM / 64, T_TOK / 128), 256, SMEM_GEMM>>>(
        tok3, w_out_r, b_out, nullptr, nullptr, tmp, T_TOK, C_DIM, C_DIM, 0, 0);
    // 11) transpose back + image residual
    out_transpose_k<<<dim3(C_DIM / 32, T_TOK / 32), dim3(32, 32)>>>(tmp, x, out);
}

// round 7
// speedup vs baseline: 14.1147x; 1.1763x over previous
#include <cuda_runtime.h>
#include <cuda_bf16.h>
#include <math.h>

#define T_TOK 4096
#define C_DIM 256
#define C3    768
#define FF    1024
#define HEADS 8
#define HD    32
#define EPS   1e-5f
#define KVS   4

// ---------------- scratch (device globals; no allocation) ----------------
__device__ float g_tok0[T_TOK * C_DIM];
__device__ float g_tok [T_TOK * C_DIM];
__device__ float g_yt  [T_TOK * C_DIM];
__device__ float g_y32 [T_TOK * C_DIM];
__device__ float g_qkv [T_TOK * C3];
__device__ float g_ov  [T_TOK * C_DIM];
__device__ float g_tok2[T_TOK * C_DIM];
__device__ float g_z   [T_TOK * C_DIM];
__device__ float g_h1  [T_TOK * FF];
__device__ float g_tok3[T_TOK * C_DIM];
__device__ float g_tmp [T_TOK * C_DIM];
__device__ float g_opart[KVS * T_TOK * C_DIM];
__device__ float g_l    [KVS * T_TOK * HEADS];
__device__ float g_w_in_r [C_DIM * C_DIM];
__device__ float g_w_qkv_r[C3 * C_DIM];
__device__ float g_w_ap_r [C_DIM * C_DIM];
__device__ float g_w_ff1_r[FF * C_DIM];
__device__ float g_w_ff2_r[C_DIM * FF];
__device__ float g_w_out_r[C_DIM * C_DIM];

// ---------------- helpers ----------------
__device__ __forceinline__ float to_tf32(float x) {
    unsigned u;
    asm("cvt.rna.tf32.f32 %0, %1;" : "=r"(u) : "f"(x));
    return __uint_as_float(u);
}
__device__ __forceinline__ float ex2f(float x) {
    float y;
    asm("ex2.approx.f32 %0, %1;" : "=f"(y) : "f"(x));
    return y;
}
__device__ __forceinline__ unsigned ldu(const float* p) {
    return *reinterpret_cast<const unsigned*>(p);
}
__device__ __forceinline__ unsigned ldub(const __nv_bfloat16* p) {
    return *reinterpret_cast<const unsigned*>(p);
}
__device__ __forceinline__ unsigned pack_bf16(float lo, float hi) {
    __nv_bfloat162 t = __floats2bfloat162_rn(lo, hi);
    return *reinterpret_cast<unsigned*>(&t);
}
__device__ __forceinline__ void mma_tf32(float c[4], const unsigned a[4], const unsigned b[2]) {
    asm volatile(
        "mma.sync.aligned.m16n8k8.row.col.f32.tf32.tf32.f32 "
        "{%0,%1,%2,%3}, {%4,%5,%6,%7}, {%8,%9}, {%0,%1,%2,%3};"
        : "+f"(c[0]), "+f"(c[1]), "+f"(c[2]), "+f"(c[3])
        : "r"(a[0]), "r"(a[1]), "r"(a[2]), "r"(a[3]), "r"(b[0]), "r"(b[1]));
}
__device__ __forceinline__ void mma_bf16(float c[4], const unsigned a[4], const unsigned b[2]) {
    asm volatile(
        "mma.sync.aligned.m16n8k16.row.col.f32.bf16.bf16.f32 "
        "{%0,%1,%2,%3}, {%4,%5,%6,%7}, {%8,%9}, {%0,%1,%2,%3};"
        : "+f"(c[0]), "+f"(c[1]), "+f"(c[2]), "+f"(c[3])
        : "r"(a[0]), "r"(a[1]), "r"(a[2]), "r"(a[3]), "r"(b[0]), "r"(b[1]));
}
__device__ __forceinline__ void cp16(float* s, const float* g) {
    unsigned sa = (unsigned)__cvta_generic_to_shared(s);
    asm volatile("cp.async.cg.shared.global [%0], [%1], 16;\n" :: "r"(sa), "l"(g));
}
#define CP_COMMIT() asm volatile("cp.async.commit_group;\n" ::: "memory")
#define CP_WAIT1()  asm volatile("cp.async.wait_group 1;\n" ::: "memory")
#define CP_WAIT0()  asm volatile("cp.async.wait_group 0;\n" ::: "memory")

// ---------------- fused weight rounding (all 6 weights, one launch) ----------
struct RoundArgs {
    const float* src[6];
    float* dst[6];
    int n4[6];   // number of float4 elements
};
__global__ void round_all_k(RoundArgs a) {
#pragma unroll
    for (int s = 0; s < 6; s++) {
        const float4* sp = reinterpret_cast<const float4*>(a.src[s]);
        float4* dp = reinterpret_cast<float4*>(a.dst[s]);
        int n = a.n4[s];
        for (int i = blockIdx.x * blockDim.x + threadIdx.x; i < n; i += gridDim.x * blockDim.x) {
            float4 v = sp[i];
            v.x = to_tf32(v.x); v.y = to_tf32(v.y);
            v.z = to_tf32(v.z); v.w = to_tf32(v.w);
            dp[i] = v;
        }
    }
}

// ---------------- BN (folded) + transpose -> tf32-rounded tokens ------------
__global__ void bn_transpose_k(const float* __restrict__ x,
                               const float* __restrict__ gamma,
                               const float* __restrict__ beta,
                               const float* __restrict__ mean,
                               const float* __restrict__ var,
                               float* __restrict__ tok0) {
    __shared__ float sm[32][33];
    int c0 = blockIdx.x * 32, t0 = blockIdx.y * 32;
    int tx = threadIdx.x, ty = threadIdx.y;
    int c = c0 + ty;
    float a  = gamma[c] * rsqrtf(var[c] + EPS);
    float bb = beta[c] - mean[c] * a;
    sm[ty][tx] = x[c * T_TOK + t0 + tx] * a + bb;
    __syncthreads();
    tok0[(t0 + ty) * C_DIM + c0 + tx] = to_tf32(sm[tx][ty]);
}

// ---------------- transpose back + image residual ----------------
__global__ void out_transpose_k(const float* __restrict__ tmp,
                                const float* __restrict__ xin,
                                float* __restrict__ out) {
    __shared__ float sm[32][33];
    int c0 = blockIdx.x * 32, t0 = blockIdx.y * 32;
    int tx = threadIdx.x, ty = threadIdx.y;
    sm[ty][tx] = tmp[(t0 + ty) * C_DIM + c0 + tx];
    __syncthreads();
    int c = c0 + ty, t = t0 + tx;
    out[c * T_TOK + t] = sm[tx][ty] + xin[c * T_TOK + t];
}

// ---------------- LayerNorm ----------------
__global__ void ln_k(const float* __restrict__ x,
                     const float* __restrict__ g,
                     const float* __restrict__ b,
                     float* __restrict__ yt, float* __restrict__ y32) {
    int row  = blockIdx.x * 8 + (threadIdx.x >> 5);
    int lane = threadIdx.x & 31;
    const float* xr = x + row * C_DIM;
    float v[8], s = 0.f, s2 = 0.f;
#pragma unroll
    for (int i = 0; i < 8; i++) {
        v[i] = xr[lane + 32 * i];
        s += v[i]; s2 += v[i] * v[i];
    }
#pragma unroll
    for (int off = 16; off > 0; off >>= 1) {
        s  += __shfl_xor_sync(0xffffffffu, s,  off);
        s2 += __shfl_xor_sync(0xffffffffu, s2, off);
    }
    float mu = s * (1.f / C_DIM);
    float va = s2 * (1.f / C_DIM) - mu * mu;
    float r = rsqrtf(va + EPS);
#pragma unroll
    for (int i = 0; i < 8; i++) {
        int c = lane + 32 * i;
        float o = (v[i] - mu) * r * g[c] + b[c];
        yt[row * C_DIM + c] = to_tf32(o);
        if (y32) y32[row * C_DIM + c] = o;
    }
}

// ---------------- tf32 GEMM, cp.async 2-stage (unchanged from R6) -----------
#define GSTAGE (192 * 36)
#define SMEM_GEMM (2 * GSTAGE * 4)
__global__ __launch_bounds__(256)
void gemm_k(const float* __restrict__ A, const float* __restrict__ W,
            const float* __restrict__ bias,
            const float* __restrict__ add1, const float* __restrict__ add2,
            float* __restrict__ out, int M, int N, int K, int act, int round_out) {
    extern __shared__ float smg[];
    const int tid = threadIdx.x;
    const int warp = tid >> 5, l = tid & 31;
    const int wm = warp >> 1, wn = warp & 1;
    const int r = l >> 2, tig = l & 3;
    const int m0 = blockIdx.y * 128, n0 = blockIdx.x * 64;
    const int lrow = tid >> 3, lc4 = (tid & 7) * 4;

    float acc[2][4][4];
#pragma unroll
    for (int tm = 0; tm < 2; tm++)
#pragma unroll
        for (int j = 0; j < 4; j++)
#pragma unroll
            for (int i = 0; i < 4; i++) acc[tm][j][i] = 0.f;

    const int nt = K >> 5;
#pragma unroll
    for (int t0 = 0; t0 < 2; t0++) {
        if (t0 < nt) {
            float* As = smg + t0 * GSTAGE;
            float* Ws = As + 128 * 36;
#pragma unroll
            for (int i = 0; i < 4; i++)
                cp16(&As[(lrow + i * 32) * 36 + lc4],
                     A + (size_t)(m0 + lrow + i * 32) * K + t0 * 32 + lc4);
#pragma unroll
            for (int i = 0; i < 2; i++)
                cp16(&Ws[(lrow + i * 32) * 36 + lc4],
                     W + (size_t)(n0 + lrow + i * 32) * K + t0 * 32 + lc4);
            CP_COMMIT();
        }
    }

    for (int t = 0; t < nt; t++) {
        if (t + 1 < nt) CP_WAIT1(); else CP_WAIT0();
        __syncthreads();
        float* As = smg + (t & 1) * GSTAGE;
        float* Ws = As + 128 * 36;
#pragma unroll
        for (int kk = 0; kk < 4; kk++) {
            unsigned au[2][4], bu[4][2];
#pragma unroll
            for (int tm = 0; tm < 2; tm++) {
                int mr = wm * 32 + tm * 16 + r;
                au[tm][0] = ldu(&As[mr * 36 + kk * 8 + tig]);
                au[tm][1] = ldu(&As[(mr + 8) * 36 + kk * 8 + tig]);
                au[tm][2] = ldu(&As[mr * 36 + kk * 8 + tig + 4]);
                au[tm][3] = ldu(&As[(mr + 8) * 36 + kk * 8 + tig + 4]);
            }
#pragma unroll
            for (int j = 0; j < 4; j++) {
                int nr = wn * 32 + 8 * j + r;
                bu[j][0] = ldu(&Ws[nr * 36 + kk * 8 + tig]);
                bu[j][1] = ldu(&Ws[nr * 36 + kk * 8 + tig + 4]);
            }
#pragma unroll
            for (int tm = 0; tm < 2; tm++)
#pragma unroll
                for (int j = 0; j < 4; j++)
                    mma_tf32(acc[tm][j], au[tm], bu[j]);
        }
        __syncthreads();
        if (t + 2 < nt) {
            float* Asn = smg + (t & 1) * GSTAGE;
            float* Wsn = Asn + 128 * 36;
            int k0 = (t + 2) * 32;
#pragma unroll
            for (int i = 0; i < 4; i++)
                cp16(&Asn[(lrow + i * 32) * 36 + lc4],
                     A + (size_t)(m0 + lrow + i * 32) * K + k0 + lc4);
#pragma unroll
            for (int i = 0; i < 2; i++)
                cp16(&Wsn[(lrow + i * 32) * 36 + lc4],
                     W + (size_t)(n0 + lrow + i * 32) * K + k0 + lc4);
            CP_COMMIT();
        }
    }

#pragma unroll
    for (int tm = 0; tm < 2; tm++) {
#pragma unroll
        for (int j = 0; j < 4; j++) {
            int rr0 = m0 + wm * 32 + tm * 16 + r;
            int cc = n0 + wn * 32 + 8 * j + tig * 2;
#pragma unroll
            for (int half = 0; half < 2; half++) {
                int rr = rr0 + half * 8;
                float v0 = acc[tm][j][half * 2 + 0] + bias[cc];
                float v1 = acc[tm][j][half * 2 + 1] + bias[cc + 1];
                size_t idx = (size_t)rr * N + cc;
                if (add1) { v0 += add1[idx]; v1 += add1[idx + 1]; }
                if (add2) { v0 += add2[idx]; v1 += add2[idx + 1]; }
                if (act == 1) {
                    v0 = 0.5f * v0 * (1.0f + erff(v0 * 0.70710678118654752f));
                    v1 = 0.5f * v1 * (1.0f + erff(v1 * 0.70710678118654752f));
                }
                if (round_out) { v0 = to_tf32(v0); v1 = to_tf32(v1); }
                out[idx] = v0; out[idx + 1] = v1;
            }
        }
    }
}

// ---------------- flash attention: bf16 QK^T + bf16 PV, max-free, KVS=4 -----
// grid (32 qblocks, 8 heads, KVS), 256 threads (8 warps x 16 q-rows).
__global__ __launch_bounds__(256)
void attn_k(const float* __restrict__ qkv,
            float* __restrict__ opart, float* __restrict__ lpart) {
    __shared__ __nv_bfloat16 Qb[128][40];     // Q staging (bf16), reused as nothing after
    __shared__ __nv_bfloat16 Kb[64][40];      // K tile bf16, [key][d]
    __shared__ __nv_bfloat16 Vt[32][72];      // V tile bf16, [d][key]

    const int h = blockIdx.y, q0 = blockIdx.x * 128, split = blockIdx.z;
    const int tid = threadIdx.x;
    const int w = tid >> 5, l = tid & 31;
    const int r = l >> 2, tig = l & 3;
    const int c2 = tig * 2;
    const float K2 = 1.4426950408889634f * 0.17677669529663689f;  // log2e/sqrt(hd)
    const int lrow = tid >> 3, lc4 = (tid & 7) * 4;

    // stage Q (bf16)
#pragma unroll
    for (int i = 0; i < 4; i++) {
        int s = tid + i * 256;
        int row = s >> 3, c4 = (s & 7) * 4;
        float4 v = *reinterpret_cast<const float4*>(qkv + (size_t)(q0 + row) * C3 + h * HD + c4);
        *reinterpret_cast<unsigned*>(&Qb[row][c4])     = pack_bf16(v.x, v.y);
        *reinterpret_cast<unsigned*>(&Qb[row][c4 + 2]) = pack_bf16(v.z, v.w);
    }
    __syncthreads();
    unsigned aq[2][4];
#pragma unroll
    for (int kk = 0; kk < 2; kk++) {
        int mr = w * 16 + r;
        aq[kk][0] = ldub(&Qb[mr][kk * 16 + c2]);
        aq[kk][1] = ldub(&Qb[mr + 8][kk * 16 + c2]);
        aq[kk][2] = ldub(&Qb[mr][kk * 16 + 8 + c2]);
        aq[kk][3] = ldub(&Qb[mr + 8][kk * 16 + 8 + c2]);
    }
    __syncthreads();

    float oa[4][4];
#pragma unroll
    for (int jd = 0; jd < 4; jd++)
#pragma unroll
        for (int i = 0; i < 4; i++) oa[jd][i] = 0.f;
    float l0 = 0.f, l1 = 0.f;

    const int NT = (T_TOK / KVS) / 64;
    const int kb0 = split * NT;
    float4 kr[2], vr[2];
#pragma unroll
    for (int i = 0; i < 2; i++) {
        const float* kp = qkv + (size_t)(kb0 * 64 + lrow + i * 32) * C3 + C_DIM + h * HD + lc4;
        kr[i] = *reinterpret_cast<const float4*>(kp);
        vr[i] = *reinterpret_cast<const float4*>(kp + C_DIM);
    }
#pragma unroll
    for (int i = 0; i < 2; i++) {
        int row = lrow + i * 32;
        *reinterpret_cast<unsigned*>(&Kb[row][lc4])     = pack_bf16(kr[i].x, kr[i].y);
        *reinterpret_cast<unsigned*>(&Kb[row][lc4 + 2]) = pack_bf16(kr[i].z, kr[i].w);
        Vt[lc4 + 0][row] = __float2bfloat16(vr[i].x);
        Vt[lc4 + 1][row] = __float2bfloat16(vr[i].y);
        Vt[lc4 + 2][row] = __float2bfloat16(vr[i].z);
        Vt[lc4 + 3][row] = __float2bfloat16(vr[i].w);
    }
    __syncthreads();

    for (int t = 0; t < NT; t++) {
        if (t + 1 < NT) {
#pragma unroll
            for (int i = 0; i < 2; i++) {
                const float* kp = qkv + (size_t)((kb0 + t + 1) * 64 + lrow + i * 32) * C3 + C_DIM + h * HD + lc4;
                kr[i] = *reinterpret_cast<const float4*>(kp);
                vr[i] = *reinterpret_cast<const float4*>(kp + C_DIM);
            }
        }

        // S = Q K^T (bf16, 2 k16 steps; warp: 16 x 64)
        float st[8][4];
#pragma unroll
        for (int j = 0; j < 8; j++) {
#pragma unroll
            for (int i = 0; i < 4; i++) st[j][i] = 0.f;
#pragma unroll
            for (int kk = 0; kk < 2; kk++) {
                unsigned bk[2];
                int nr = 8 * j + r;
                bk[0] = ldub(&Kb[nr][kk * 16 + c2]);
                bk[1] = ldub(&Kb[nr][kk * 16 + 8 + c2]);
                mma_bf16(st[j], aq[kk], bk);
            }
        }
        // max-free softmax
#pragma unroll
        for (int j = 0; j < 8; j++) {
            st[j][0] = ex2f(st[j][0] * K2);
            st[j][1] = ex2f(st[j][1] * K2);
            st[j][2] = ex2f(st[j][2] * K2);
            st[j][3] = ex2f(st[j][3] * K2);
            l0 += st[j][0] + st[j][1];
            l1 += st[j][2] + st[j][3];
        }
        // P fragments (bf16) directly from S accumulators
        unsigned ap[4][4];
#pragma unroll
        for (int kk = 0; kk < 4; kk++) {
            ap[kk][0] = pack_bf16(st[2 * kk][0],     st[2 * kk][1]);
            ap[kk][1] = pack_bf16(st[2 * kk][2],     st[2 * kk][3]);
            ap[kk][2] = pack_bf16(st[2 * kk + 1][0], st[2 * kk + 1][1]);
            ap[kk][3] = pack_bf16(st[2 * kk + 1][2], st[2 * kk + 1][3]);
        }
        // O += P V (bf16)
#pragma unroll
        for (int jd = 0; jd < 4; jd++) {
            int nr = 8 * jd + r;
#pragma unroll
            for (int kk = 0; kk < 4; kk++) {
                unsigned bv[2];
                bv[0] = ldub(&Vt[nr][kk * 16 + c2]);
                bv[1] = ldub(&Vt[nr][kk * 16 + 8 + c2]);
                mma_bf16(oa[jd], ap[kk], bv);
            }
        }
        __syncthreads();
        if (t + 1 < NT) {
#pragma unroll
            for (int i = 0; i < 2; i++) {
                int row = lrow + i * 32;
                *reinterpret_cast<unsigned*>(&Kb[row][lc4])     = pack_bf16(kr[i].x, kr[i].y);
                *reinterpret_cast<unsigned*>(&Kb[row][lc4 + 2]) = pack_bf16(kr[i].z, kr[i].w);
                Vt[lc4 + 0][row] = __float2bfloat16(vr[i].x);
                Vt[lc4 + 1][row] = __float2bfloat16(vr[i].y);
                Vt[lc4 + 2][row] = __float2bfloat16(vr[i].z);
                Vt[lc4 + 3][row] = __float2bfloat16(vr[i].w);
            }
            __syncthreads();
        }
    }

    l0 += __shfl_xor_sync(0xffffffffu, l0, 1);
    l0 += __shfl_xor_sync(0xffffffffu, l0, 2);
    l1 += __shfl_xor_sync(0xffffffffu, l1, 1);
    l1 += __shfl_xor_sync(0xffffffffu, l1, 2);

    int row0 = q0 + w * 16 + r;
    float* ob = opart + ((size_t)split * T_TOK) * C_DIM;
#pragma unroll
    for (int jd = 0; jd < 4; jd++) {
        int col = h * HD + 8 * jd + c2;
        *reinterpret_cast<float2*>(ob + (size_t)row0 * C_DIM + col) =
            make_float2(oa[jd][0], oa[jd][1]);
        *reinterpret_cast<float2*>(ob + (size_t)(row0 + 8) * C_DIM + col) =
            make_float2(oa[jd][2], oa[jd][3]);
    }
    if (tig == 0) {
        lpart[((size_t)split * T_TOK + row0) * HEADS + h] = l0;
        lpart[((size_t)split * T_TOK + row0 + 8) * HEADS + h] = l1;
    }
}

// ---------------- combine KV splits ----------------
__global__ void attn_combine_k(const float* __restrict__ opart,
                               const float* __restrict__ lpart,
                               float* __restrict__ ov) {
    int row  = blockIdx.x * 8 + (threadIdx.x >> 5);
    int lane = threadIdx.x & 31;
#pragma unroll
    for (int k = 0; k < 8; k++) {
        int c = lane + 32 * k;
        float lsum = 0.f, osum = 0.f;
#pragma unroll
        for (int s = 0; s < KVS; s++) {
            lsum += lpart[((size_t)s * T_TOK + row) * HEADS + k];
            osum += opart[((size_t)s * T_TOK + row) * C_DIM + c];
        }
        ov[(size_t)row * C_DIM + c] = to_tf32(osum / lsum);
    }
}

// ---------------- launch ----------------
template <typename Sym>
static float* dev_ptr(const Sym& sym) {
    void* p = nullptr;
    cudaGetSymbolAddress(&p, sym);
    return (float*)p;
}

extern "C" void kernel_launch(void* const* d_in, const int* in_sizes, int n_in,
                              void* d_out, int out_size) {
    (void)in_sizes; (void)n_in; (void)out_size;
    const float* x        = (const float*)d_in[0];
    const float* bn_gamma = (const float*)d_in[1];
    const float* bn_beta  = (const float*)d_in[2];
    const float* bn_mean  = (const float*)d_in[3];
    const float* bn_var   = (const float*)d_in[4];
    const float* w_in     = (const float*)d_in[5];
    const float* b_in     = (const float*)d_in[6];
    const float* ln1_g    = (const float*)d_in[7];
    const float* ln1_b    = (const float*)d_in[8];
    const float* w_qkv    = (const float*)d_in[9];
    const float* b_qkv    = (const float*)d_in[10];
    const float* w_ap     = (const float*)d_in[11];
    const float* b_ap     = (const float*)d_in[12];
    const float* ln2_g    = (const float*)d_in[13];
    const float* ln2_b    = (const float*)d_in[14];
    const float* w_ff1    = (const float*)d_in[15];
    const float* b_ff1    = (const float*)d_in[16];
    const float* w_ff2    = (const float*)d_in[17];
    const float* b_ff2    = (const float*)d_in[18];
    const float* w_out    = (const float*)d_in[19];
    const float* b_out    = (const float*)d_in[20];
    float* out = (float*)d_out;

    float* tok0  = dev_ptr(g_tok0);
    float* tok   = dev_ptr(g_tok);
    float* yt    = dev_ptr(g_yt);
    float* y32   = dev_ptr(g_y32);
    float* qkv   = dev_ptr(g_qkv);
    float* ov    = dev_ptr(g_ov);
    float* tok2  = dev_ptr(g_tok2);
    float* z     = dev_ptr(g_z);
    float* h1    = dev_ptr(g_h1);
    float* tok3  = dev_ptr(g_tok3);
    float* tmp   = dev_ptr(g_tmp);
    float* opart = dev_ptr(g_opart);
    float* lpart = dev_ptr(g_l);
    float* w_in_r  = dev_ptr(g_w_in_r);
    float* w_qkv_r = dev_ptr(g_w_qkv_r);
    float* w_ap_r  = dev_ptr(g_w_ap_r);
    float* w_ff1_r = dev_ptr(g_w_ff1_r);
    float* w_ff2_r = dev_ptr(g_w_ff2_r);
    float* w_out_r = dev_ptr(g_w_out_r);

    static bool attr_set = false;
    if (!attr_set) {
        cudaFuncSetAttribute(gemm_k, cudaFuncAttributeMaxDynamicSharedMemorySize, SMEM_GEMM);
        attr_set = true;
    }

    // fused weight rounding (single launch)
    RoundArgs ra;
    ra.src[0] = w_in;  ra.dst[0] = w_in_r;  ra.n4[0] = C_DIM * C_DIM / 4;
    ra.src[1] = w_qkv; ra.dst[1] = w_qkv_r; ra.n4[1] = C3 * C_DIM / 4;
    ra.src[2] = w_ap;  ra.dst[2] = w_ap_r;  ra.n4[2] = C_DIM * C_DIM / 4;
    ra.src[3] = w_ff1; ra.dst[3] = w_ff1_r; ra.n4[3] = FF * C_DIM / 4;
    ra.src[4] = w_ff2; ra.dst[4] = w_ff2_r; ra.n4[4] = C_DIM * FF / 4;
    ra.src[5] = w_out; ra.dst[5] = w_out_r; ra.n4[5] = C_DIM * C_DIM / 4;
    round_all_k<<<448, 256>>>(ra);

    // 1) BN + transpose
    bn_transpose_k<<<dim3(C_DIM / 32, T_TOK / 32), dim3(32, 32)>>>(
        x, bn_gamma, bn_beta, bn_mean, bn_var, tok0);
    // 2) proj_in
    gemm_k<<<dim3(C_DIM / 64, T_TOK / 128), 256, SMEM_GEMM>>>(
        tok0, w_in_r, b_in, nullptr, nullptr, tok, T_TOK, C_DIM, C_DIM, 0, 0);
    // 3) LN1
    ln_k<<<T_TOK / 8, 256>>>(tok, ln1_g, ln1_b, yt, y32);
    // 4) QKV
    gemm_k<<<dim3(C3 / 64, T_TOK / 128), 256, SMEM_GEMM>>>(
        yt, w_qkv_r, b_qkv, nullptr, nullptr, qkv, T_TOK, C3, C_DIM, 0, 1);
    // 5) attention + combine
    attn_k<<<dim3(T_TOK / 128, HEADS, KVS), 256>>>(qkv, opart, lpart);
    attn_combine_k<<<T_TOK / 8, 256>>>(opart, lpart, ov);
    // 6) attn proj + residuals
    gemm_k<<<dim3(C_DIM / 64, T_TOK / 128), 256, SMEM_GEMM>>>(
        ov, w_ap_r, b_ap, y32, tok, tok2, T_TOK, C_DIM, C_DIM, 0, 0);
    // 7) LN2
    ln_k<<<T_TOK / 8, 256>>>(tok2, ln2_g, ln2_b, z, nullptr);
    // 8) FF1 + gelu
    gemm_k<<<dim3(FF / 64, T_TOK / 128), 256, SMEM_GEMM>>>(
        z, w_ff1_r, b_ff1, nullptr, nullptr, h1, T_TOK, FF, C_DIM, 1, 1);
    // 9) FF2 + residual
    gemm_k<<<dim3(C_DIM / 64, T_TOK / 128), 256, SMEM_GEMM>>>(
        h1, w_ff2_r, b_ff2, tok2, nullptr, tok3, T_TOK, C_DIM, FF, 0, 1);
    // 10) proj_out
    gemm_k<<<dim3(C_DIM / 64, T_TOK / 128), 256, SMEM_GEMM>>>(
        tok3, w_out_r, b_out, nullptr, nullptr, tmp, T_TOK, C_DIM, C_DIM, 0, 0);
    // 11) transpose back + image residual
    out_transpose_k<<<dim3(C_DIM / 32, T_TOK / 32), dim3(32, 32)>>>(tmp, x, out);
}

// round 8
// speedup vs baseline: 18.2214x; 1.2910x over previous
#include <cuda_runtime.h>
#include <cuda_fp16.h>
#include <math.h>

#define T_TOK 4096
#define C_DIM 256
#define C3    768
#define FF    1024
#define HEADS 8
#define HD    32
#define EPS   1e-5f
#define KVS   4

// ---------------- scratch (device globals; no allocation) ----------------
__device__ __half g_tok0h[T_TOK * C_DIM];
__device__ float  g_tok  [T_TOK * C_DIM];
__device__ __half g_yh   [T_TOK * C_DIM];
__device__ float  g_y32  [T_TOK * C_DIM];
__device__ __half g_qkvh [T_TOK * C3];
__device__ __half g_ovh  [T_TOK * C_DIM];
__device__ float  g_tok2 [T_TOK * C_DIM];
__device__ __half g_zh   [T_TOK * C_DIM];
__device__ __half g_h1h  [T_TOK * FF];
__device__ __half g_tok3h[T_TOK * C_DIM];
__device__ float  g_tmp  [T_TOK * C_DIM];
__device__ float  g_opart[KVS * T_TOK * C_DIM];
__device__ float  g_l    [KVS * T_TOK * HEADS];
__device__ __half g_w_in_h [C_DIM * C_DIM];
__device__ __half g_w_qkv_h[C3 * C_DIM];
__device__ __half g_w_ap_h [C_DIM * C_DIM];
__device__ __half g_w_ff1_h[FF * C_DIM];
__device__ __half g_w_ff2_h[C_DIM * FF];
__device__ __half g_w_out_h[C_DIM * C_DIM];

// ---------------- helpers ----------------
__device__ __forceinline__ unsigned ldu(const void* p) {
    return *reinterpret_cast<const unsigned*>(p);
}
__device__ __forceinline__ unsigned pack_h2(float lo, float hi) {
    __half2 t = __floats2half2_rn(lo, hi);
    return *reinterpret_cast<unsigned*>(&t);
}
__device__ __forceinline__ unsigned ex2_h2(unsigned x) {
    unsigned y;
    asm("ex2.approx.f16x2 %0, %1;" : "=r"(y) : "r"(x));
    return y;
}
__device__ __forceinline__ void mma_f16(float c[4], const unsigned a[4], const unsigned b[2]) {
    asm volatile(
        "mma.sync.aligned.m16n8k16.row.col.f32.f16.f16.f32 "
        "{%0,%1,%2,%3}, {%4,%5,%6,%7}, {%8,%9}, {%0,%1,%2,%3};"
        : "+f"(c[0]), "+f"(c[1]), "+f"(c[2]), "+f"(c[3])
        : "r"(a[0]), "r"(a[1]), "r"(a[2]), "r"(a[3]), "r"(b[0]), "r"(b[1]));
}
__device__ __forceinline__ void cp16(void* s, const void* g) {
    unsigned sa = (unsigned)__cvta_generic_to_shared(s);
    asm volatile("cp.async.cg.shared.global [%0], [%1], 16;\n" :: "r"(sa), "l"(g));
}
#define CP_COMMIT() asm volatile("cp.async.commit_group;\n" ::: "memory")
#define CP_WAIT1()  asm volatile("cp.async.wait_group 1;\n" ::: "memory")
#define CP_WAIT0()  asm volatile("cp.async.wait_group 0;\n" ::: "memory")

// ---------------- fused weight conversion f32 -> f16 (one launch) ------------
struct CvtArgs {
    const float* src[6];
    __half* dst[6];
    int n4[6];
};
__global__ void cvt_all_k(CvtArgs a) {
#pragma unroll
    for (int s = 0; s < 6; s++) {
        const float4* sp = reinterpret_cast<const float4*>(a.src[s]);
        unsigned* dp = reinterpret_cast<unsigned*>(a.dst[s]);
        int n = a.n4[s];
        for (int i = blockIdx.x * blockDim.x + threadIdx.x; i < n; i += gridDim.x * blockDim.x) {
            float4 v = sp[i];
            dp[i * 2 + 0] = pack_h2(v.x, v.y);
            dp[i * 2 + 1] = pack_h2(v.z, v.w);
        }
    }
}

// ---------------- BN (folded) + transpose -> f16 tokens ----------------
__global__ void bn_transpose_k(const float* __restrict__ x,
                               const float* __restrict__ gamma,
                               const float* __restrict__ beta,
                               const float* __restrict__ mean,
                               const float* __restrict__ var,
                               __half* __restrict__ tok0) {
    __shared__ float sm[32][33];
    int c0 = blockIdx.x * 32, t0 = blockIdx.y * 32;
    int tx = threadIdx.x, ty = threadIdx.y;
    int c = c0 + ty;
    float a  = gamma[c] * rsqrtf(var[c] + EPS);
    float bb = beta[c] - mean[c] * a;
    sm[ty][tx] = x[c * T_TOK + t0 + tx] * a + bb;
    __syncthreads();
    tok0[(t0 + ty) * C_DIM + c0 + tx] = __float2half(sm[tx][ty]);
}

// ---------------- transpose back + image residual ----------------
__global__ void out_transpose_k(const float* __restrict__ tmp,
                                const float* __restrict__ xin,
                                float* __restrict__ out) {
    __shared__ float sm[32][33];
    int c0 = blockIdx.x * 32, t0 = blockIdx.y * 32;
    int tx = threadIdx.x, ty = threadIdx.y;
    sm[ty][tx] = tmp[(t0 + ty) * C_DIM + c0 + tx];
    __syncthreads();
    int c = c0 + ty, t = t0 + tx;
    out[c * T_TOK + t] = sm[tx][ty] + xin[c * T_TOK + t];
}

// ---------------- LayerNorm: f32 in -> f16 out (+ optional f32 copy) --------
__global__ void ln_k(const float* __restrict__ x,
                     const float* __restrict__ g,
                     const float* __restrict__ b,
                     __half* __restrict__ yh, float* __restrict__ y32) {
    int row  = blockIdx.x * 8 + (threadIdx.x >> 5);
    int lane = threadIdx.x & 31;
    const float* xr = x + row * C_DIM;
    float v[8], s = 0.f, s2 = 0.f;
#pragma unroll
    for (int i = 0; i < 8; i++) {
        v[i] = xr[lane + 32 * i];
        s += v[i]; s2 += v[i] * v[i];
    }
#pragma unroll
    for (int off = 16; off > 0; off >>= 1) {
        s  += __shfl_xor_sync(0xffffffffu, s,  off);
        s2 += __shfl_xor_sync(0xffffffffu, s2, off);
    }
    float mu = s * (1.f / C_DIM);
    float va = s2 * (1.f / C_DIM) - mu * mu;
    float r = rsqrtf(va + EPS);
#pragma unroll
    for (int i = 0; i < 8; i++) {
        int c = lane + 32 * i;
        float o = (v[i] - mu) * r * g[c] + b[c];
        yh[row * C_DIM + c] = __float2half(o);
        if (y32) y32[row * C_DIM + c] = o;
    }
}

// ---------------- fp16 tensor-core GEMM, cp.async 2-stage -------------------
// BM=128 BN=64 BK=32, 256 threads (8 warps, 4x2 grid, 32x32 warp tile).
// A [M,K] f16 row-major, W [N,K] f16 row-major. f32 accum + epilogue.
#define GROW 40                       // smem row stride (halves)
#define GSTAGE (192 * GROW)           // halves per stage
#define SMEM_GEMM (2 * GSTAGE * 2)    // bytes
__global__ __launch_bounds__(256)
void gemm_k(const __half* __restrict__ A, const __half* __restrict__ W,
            const float* __restrict__ bias,
            const float* __restrict__ add1, const float* __restrict__ add2,
            float* __restrict__ outf, __half* __restrict__ outh,
            int M, int N, int K, int act) {
    extern __shared__ __half smh[];
    const int tid = threadIdx.x;
    const int warp = tid >> 5, l = tid & 31;
    const int wm = warp >> 1, wn = warp & 1;
    const int r = l >> 2, c2 = (l & 3) * 2;
    const int m0 = blockIdx.y * 128, n0 = blockIdx.x * 64;
    const int arow = tid >> 2, ach = (tid & 3) * 8;   // A: 2 chunks/thread (via i)
    const int wrow = tid >> 2, wch = (tid & 3) * 8;   // W: 1 chunk/thread

    float acc[2][4][4];
#pragma unroll
    for (int tm = 0; tm < 2; tm++)
#pragma unroll
        for (int j = 0; j < 4; j++)
#pragma unroll
            for (int i = 0; i < 4; i++) acc[tm][j][i] = 0.f;

    const int nt = K >> 5;
#pragma unroll
    for (int t0 = 0; t0 < 2; t0++) {
        if (t0 < nt) {
            __half* As = smh + t0 * GSTAGE;
            __half* Ws = As + 128 * GROW;
#pragma unroll
            for (int i = 0; i < 2; i++) {
                int row = arow + i * 64;
                cp16(&As[row * GROW + ach], A + (size_t)(m0 + row) * K + t0 * 32 + ach);
            }
            cp16(&Ws[wrow * GROW + wch], W + (size_t)(n0 + wrow) * K + t0 * 32 + wch);
            CP_COMMIT();
        }
    }

    for (int t = 0; t < nt; t++) {
        if (t + 1 < nt) CP_WAIT1(); else CP_WAIT0();
        __syncthreads();
        __half* As = smh + (t & 1) * GSTAGE;
        __half* Ws = As + 128 * GROW;
#pragma unroll
        for (int kk = 0; kk < 2; kk++) {
            unsigned au[2][4], bu[4][2];
#pragma unroll
            for (int tm = 0; tm < 2; tm++) {
                int mr = wm * 32 + tm * 16 + r;
                au[tm][0] = ldu(&As[mr * GROW + kk * 16 + c2]);
                au[tm][1] = ldu(&As[(mr + 8) * GROW + kk * 16 + c2]);
                au[tm][2] = ldu(&As[mr * GROW + kk * 16 + 8 + c2]);
                au[tm][3] = ldu(&As[(mr + 8) * GROW + kk * 16 + 8 + c2]);
            }
#pragma unroll
            for (int j = 0; j < 4; j++) {
                int nr = wn * 32 + 8 * j + r;
                bu[j][0] = ldu(&Ws[nr * GROW + kk * 16 + c2]);
                bu[j][1] = ldu(&Ws[nr * GROW + kk * 16 + 8 + c2]);
            }
#pragma unroll
            for (int tm = 0; tm < 2; tm++)
#pragma unroll
                for (int j = 0; j < 4; j++)
                    mma_f16(acc[tm][j], au[tm], bu[j]);
        }
        __syncthreads();
        if (t + 2 < nt) {
            __half* Asn = smh + (t & 1) * GSTAGE;
            __half* Wsn = Asn + 128 * GROW;
            int k0 = (t + 2) * 32;
#pragma unroll
            for (int i = 0; i < 2; i++) {
                int row = arow + i * 64;
                cp16(&Asn[row * GROW + ach], A + (size_t)(m0 + row) * K + k0 + ach);
            }
            cp16(&Wsn[wrow * GROW + wch], W + (size_t)(n0 + wrow) * K + k0 + wch);
            CP_COMMIT();
        }
    }

    // epilogue (f32)
#pragma unroll
    for (int tm = 0; tm < 2; tm++) {
#pragma unroll
        for (int j = 0; j < 4; j++) {
            int rr0 = m0 + wm * 32 + tm * 16 + r;
            int cc = n0 + wn * 32 + 8 * j + c2;
#pragma unroll
            for (int half = 0; half < 2; half++) {
                int rr = rr0 + half * 8;
                float v0 = acc[tm][j][half * 2 + 0] + bias[cc];
                float v1 = acc[tm][j][half * 2 + 1] + bias[cc + 1];
                size_t idx = (size_t)rr * N + cc;
                if (add1) { v0 += add1[idx]; v1 += add1[idx + 1]; }
                if (add2) { v0 += add2[idx]; v1 += add2[idx + 1]; }
                if (act == 1) {
                    v0 = 0.5f * v0 * (1.0f + erff(v0 * 0.70710678118654752f));
                    v1 = 0.5f * v1 * (1.0f + erff(v1 * 0.70710678118654752f));
                }
                if (outf) { outf[idx] = v0; outf[idx + 1] = v1; }
                if (outh) *reinterpret_cast<unsigned*>(outh + idx) = pack_h2(v0, v1);
            }
        }
    }
}

// ---------------- flash attention: fp16 QK^T/PV, f16x2 exp, KVS=4 -----------
// grid (32 qblocks, 8 heads, KVS), 256 threads (8 warps x 16 q-rows).
__global__ __launch_bounds__(256)
void attn_k(const __half* __restrict__ qkv,
            float* __restrict__ opart, float* __restrict__ lpart) {
    __shared__ __half Qb[128][40];
    __shared__ __half Kb[64][40];
    __shared__ __half Vt[32][72];

    const int h = blockIdx.y, q0 = blockIdx.x * 128, split = blockIdx.z;
    const int tid = threadIdx.x;
    const int w = tid >> 5, l = tid & 31;
    const int r = l >> 2, c2 = (l & 3) * 2;
    const float K2 = 1.4426950408889634f * 0.17677669529663689f;  // log2e/sqrt(hd)
    const __half2 K2h = __float2half2_rn(K2);
    const int lrow = tid >> 2, lch = (tid & 3) * 8;

    // stage Q (f16), pre-scaled by K2
#pragma unroll
    for (int i = 0; i < 2; i++) {
        int s = tid + i * 256;
        int row = s >> 2, ch = (s & 3) * 8;
        uint4 v = *reinterpret_cast<const uint4*>(qkv + (size_t)(q0 + row) * C3 + h * HD + ch);
        __half2* hv = reinterpret_cast<__half2*>(&v);
#pragma unroll
        for (int k = 0; k < 4; k++) hv[k] = __hmul2(hv[k], K2h);
        *reinterpret_cast<uint4*>(&Qb[row][ch]) = v;
    }
    __syncthreads();
    unsigned aq[2][4];
#pragma unroll
    for (int kk = 0; kk < 2; kk++) {
        int mr = w * 16 + r;
        aq[kk][0] = ldu(&Qb[mr][kk * 16 + c2]);
        aq[kk][1] = ldu(&Qb[mr + 8][kk * 16 + c2]);
        aq[kk][2] = ldu(&Qb[mr][kk * 16 + 8 + c2]);
        aq[kk][3] = ldu(&Qb[mr + 8][kk * 16 + 8 + c2]);
    }

    float oa[4][4];
#pragma unroll
    for (int jd = 0; jd < 4; jd++)
#pragma unroll
        for (int i = 0; i < 4; i++) oa[jd][i] = 0.f;
    float l0 = 0.f, l1 = 0.f;

    const int NT = (T_TOK / KVS) / 64;
    const int kb0 = split * NT;
    uint4 kr, vr;
    {
        const __half* kp = qkv + (size_t)(kb0 * 64 + lrow) * C3 + C_DIM + h * HD + lch;
        kr = *reinterpret_cast<const uint4*>(kp);
        vr = *reinterpret_cast<const uint4*>(kp + C_DIM);
    }
    {
        *reinterpret_cast<uint4*>(&Kb[lrow][lch]) = kr;
        const __half* vh = reinterpret_cast<const __half*>(&vr);
#pragma unroll
        for (int i = 0; i < 8; i++) Vt[lch + i][lrow] = vh[i];
    }
    __syncthreads();

    for (int t = 0; t < NT; t++) {
        if (t + 1 < NT) {
            const __half* kp = qkv + (size_t)((kb0 + t + 1) * 64 + lrow) * C3 + C_DIM + h * HD + lch;
            kr = *reinterpret_cast<const uint4*>(kp);
            vr = *reinterpret_cast<const uint4*>(kp + C_DIM);
        }

        // S = Q K^T (f16, pre-scaled; warp: 16 x 64)
        float st[8][4];
#pragma unroll
        for (int j = 0; j < 8; j++) {
#pragma unroll
            for (int i = 0; i < 4; i++) st[j][i] = 0.f;
#pragma unroll
            for (int kk = 0; kk < 2; kk++) {
                unsigned bk[2];
                int nr = 8 * j + r;
                bk[0] = ldu(&Kb[nr][kk * 16 + c2]);
                bk[1] = ldu(&Kb[nr][kk * 16 + 8 + c2]);
                mma_f16(st[j], aq[kk], bk);
            }
        }
        // p = exp2(st) via f16x2 MUFU (one op per 2 scores)
        unsigned pa[8], pb[8];
#pragma unroll
        for (int j = 0; j < 8; j++) {
            pa[j] = ex2_h2(pack_h2(st[j][0], st[j][1]));
            pb[j] = ex2_h2(pack_h2(st[j][2], st[j][3]));
        }
        // l accumulation: HADD2 tree per tile, then f32
        {
            __half2 sa = *reinterpret_cast<__half2*>(&pa[0]);
            __half2 sb = *reinterpret_cast<__half2*>(&pb[0]);
#pragma unroll
            for (int j = 1; j < 8; j++) {
                sa = __hadd2(sa, *reinterpret_cast<__half2*>(&pa[j]));
                sb = __hadd2(sb, *reinterpret_cast<__half2*>(&pb[j]));
            }
            float2 fa = __half22float2(sa), fb = __half22float2(sb);
            l0 += fa.x + fa.y;
            l1 += fb.x + fb.y;
        }
        // PV: A fragments are the f16x2 p values directly
#pragma unroll
        for (int jd = 0; jd < 4; jd++) {
            int nr = 8 * jd + r;
#pragma unroll
            for (int kk = 0; kk < 4; kk++) {
                unsigned ap[4] = { pa[2 * kk], pb[2 * kk], pa[2 * kk + 1], pb[2 * kk + 1] };
                unsigned bv[2];
                bv[0] = ldu(&Vt[nr][kk * 16 + c2]);
                bv[1] = ldu(&Vt[nr][kk * 16 + 8 + c2]);
                mma_f16(oa[jd], ap, bv);
            }
        }
        __syncthreads();
        if (t + 1 < NT) {
            *reinterpret_cast<uint4*>(&Kb[lrow][lch]) = kr;
            const __half* vh = reinterpret_cast<const __half*>(&vr);
#pragma unroll
            for (int i = 0; i < 8; i++) Vt[lch + i][lrow] = vh[i];
            __syncthreads();
        }
    }

    l0 += __shfl_xor_sync(0xffffffffu, l0, 1);
    l0 += __shfl_xor_sync(0xffffffffu, l0, 2);
    l1 += __shfl_xor_sync(0xffffffffu, l1, 1);
    l1 += __shfl_xor_sync(0xffffffffu, l1, 2);

    int row0 = q0 + w * 16 + r;
    float* ob = opart + ((size_t)split * T_TOK) * C_DIM;
#pragma unroll
    for (int jd = 0; jd < 4; jd++) {
        int col = h * HD + 8 * jd + c2;
        *reinterpret_cast<float2*>(ob + (size_t)row0 * C_DIM + col) =
            make_float2(oa[jd][0], oa[jd][1]);
        *reinterpret_cast<float2*>(ob + (size_t)(row0 + 8) * C_DIM + col) =
            make_float2(oa[jd][2], oa[jd][3]);
    }
    if ((l & 3) == 0) {
        lpart[((size_t)split * T_TOK + row0) * HEADS + h] = l0;
        lpart[((size_t)split * T_TOK + row0 + 8) * HEADS + h] = l1;
    }
}

// ---------------- combine KV splits -> f16 ----------------
__global__ void attn_combine_k(const float* __restrict__ opart,
                               const float* __restrict__ lpart,
                               __half* __restrict__ ov) {
    int row  = blockIdx.x * 8 + (threadIdx.x >> 5);
    int lane = threadIdx.x & 31;
#pragma unroll
    for (int k = 0; k < 8; k++) {
        int c = lane + 32 * k;
        float lsum = 0.f, osum = 0.f;
#pragma unroll
        for (int s = 0; s < KVS; s++) {
            lsum += lpart[((size_t)s * T_TOK + row) * HEADS + k];
            osum += opart[((size_t)s * T_TOK + row) * C_DIM + c];
        }
        ov[(size_t)row * C_DIM + c] = __float2half(osum / lsum);
    }
}

// ---------------- launch ----------------
template <typename Sym>
static void* dev_ptr(const Sym& sym) {
    void* p = nullptr;
    cudaGetSymbolAddress(&p, sym);
    return p;
}

extern "C" void kernel_launch(void* const* d_in, const int* in_sizes, int n_in,
                              void* d_out, int out_size) {
    (void)in_sizes; (void)n_in; (void)out_size;
    const float* x        = (const float*)d_in[0];
    const float* bn_gamma = (const float*)d_in[1];
    const float* bn_beta  = (const float*)d_in[2];
    const float* bn_mean  = (const float*)d_in[3];
    const float* bn_var   = (const float*)d_in[4];
    const float* w_in     = (const float*)d_in[5];
    const float* b_in     = (const float*)d_in[6];
    const float* ln1_g    = (const float*)d_in[7];
    const float* ln1_b    = (const float*)d_in[8];
    const float* w_qkv    = (const float*)d_in[9];
    const float* b_qkv    = (const float*)d_in[10];
    const float* w_ap     = (const float*)d_in[11];
    const float* b_ap     = (const float*)d_in[12];
    const float* ln2_g    = (const float*)d_in[13];
    const float* ln2_b    = (const float*)d_in[14];
    const float* w_ff1    = (const float*)d_in[15];
    const float* b_ff1    = (const float*)d_in[16];
    const float* w_ff2    = (const float*)d_in[17];
    const float* b_ff2    = (const float*)d_in[18];
    const float* w_out    = (const float*)d_in[19];
    const float* b_out    = (const float*)d_in[20];
    float* out = (float*)d_out;

    __half* tok0h = (__half*)dev_ptr(g_tok0h);
    float*  tok   = (float*)dev_ptr(g_tok);
    __half* yh    = (__half*)dev_ptr(g_yh);
    float*  y32   = (float*)dev_ptr(g_y32);
    __half* qkvh  = (__half*)dev_ptr(g_qkvh);
    __half* ovh   = (__half*)dev_ptr(g_ovh);
    float*  tok2  = (float*)dev_ptr(g_tok2);
    __half* zh    = (__half*)dev_ptr(g_zh);
    __half* h1h   = (__half*)dev_ptr(g_h1h);
    __half* tok3h = (__half*)dev_ptr(g_tok3h);
    float*  tmp   = (float*)dev_ptr(g_tmp);
    float*  opart = (float*)dev_ptr(g_opart);
    float*  lpart = (float*)dev_ptr(g_l);
    __half* w_in_h  = (__half*)dev_ptr(g_w_in_h);
    __half* w_qkv_h = (__half*)dev_ptr(g_w_qkv_h);
    __half* w_ap_h  = (__half*)dev_ptr(g_w_ap_h);
    __half* w_ff1_h = (__half*)dev_ptr(g_w_ff1_h);
    __half* w_ff2_h = (__half*)dev_ptr(g_w_ff2_h);
    __half* w_out_h = (__half*)dev_ptr(g_w_out_h);

    // fused weight conversion
    CvtArgs ca;
    ca.src[0] = w_in;  ca.dst[0] = w_in_h;  ca.n4[0] = C_DIM * C_DIM / 4;
    ca.src[1] = w_qkv; ca.dst[1] = w_qkv_h; ca.n4[1] = C3 * C_DIM / 4;
    ca.src[2] = w_ap;  ca.dst[2] = w_ap_h;  ca.n4[2] = C_DIM * C_DIM / 4;
    ca.src[3] = w_ff1; ca.dst[3] = w_ff1_h; ca.n4[3] = FF * C_DIM / 4;
    ca.src[4] = w_ff2; ca.dst[4] = w_ff2_h; ca.n4[4] = C_DIM * FF / 4;
    ca.src[5] = w_out; ca.dst[5] = w_out_h; ca.n4[5] = C_DIM * C_DIM / 4;
    cvt_all_k<<<448, 256>>>(ca);

    // 1) BN + transpose
    bn_transpose_k<<<dim3(C_DIM / 32, T_TOK / 32), dim3(32, 32)>>>(
        x, bn_gamma, bn_beta, bn_mean, bn_var, tok0h);
    // 2) proj_in -> tok (f32)
    gemm_k<<<dim3(C_DIM / 64, T_TOK / 128), 256, SMEM_GEMM>>>(
        tok0h, w_in_h, b_in, nullptr, nullptr, tok, nullptr, T_TOK, C_DIM, C_DIM, 0);
    // 3) LN1 -> yh + y32
    ln_k<<<T_TOK / 8, 256>>>(tok, ln1_g, ln1_b, yh, y32);
    // 4) QKV -> qkvh (f16)
    gemm_k<<<dim3(C3 / 64, T_TOK / 128), 256, SMEM_GEMM>>>(
        yh, w_qkv_h, b_qkv, nullptr, nullptr, nullptr, qkvh, T_TOK, C3, C_DIM, 0);
    // 5) attention + combine
    attn_k<<<dim3(T_TOK / 128, HEADS, KVS), 256>>>(qkvh, opart, lpart);
    attn_combine_k<<<T_TOK / 8, 256>>>(opart, lpart, ovh);
    // 6) attn proj + y32 + tok -> tok2 (f32)
    gemm_k<<<dim3(C_DIM / 64, T_TOK / 128), 256, SMEM_GEMM>>>(
        ovh, w_ap_h, b_ap, y32, tok, tok2, nullptr, T_TOK, C_DIM, C_DIM, 0);
    // 7) LN2 -> zh
    ln_k<<<T_TOK / 8, 256>>>(tok2, ln2_g, ln2_b, zh, nullptr);
    // 8) FF1 + gelu -> h1h (f16)
    gemm_k<<<dim3(FF / 64, T_TOK / 128), 256, SMEM_GEMM>>>(
        zh, w_ff1_h, b_ff1, nullptr, nullptr, nullptr, h1h, T_TOK, FF, C_DIM, 1);
    // 9) FF2 + tok2 -> tok3h (f16)
    gemm_k<<<dim3(C_DIM / 64, T_TOK / 128), 256, SMEM_GEMM>>>(
        h1h, w_ff2_h, b_ff2, tok2, nullptr, nullptr, tok3h, T_TOK, C_DIM, FF, 0);
    // 10) proj_out -> tmp (f32)
    gemm_k<<<dim3(C_DIM / 64, T_TOK / 128), 256, SMEM_GEMM>>>(
        tok3h, w_out_h, b_out, nullptr, nullptr, tmp, nullptr, T_TOK, C_DIM, C_DIM, 0);
    // 11) transpose back + image residual
    out_transpose_k<<<dim3(C_DIM / 32, T_TOK / 32), dim3(32, 32)>>>(tmp, x, out);
}

// round 9
// speedup vs baseline: 18.5238x; 1.0166x over previous
#include <cuda_runtime.h>
#include <cuda_fp16.h>
#include <math.h>

#define T_TOK 4096
#define C_DIM 256
#define C3    768
#define FF    1024
#define HEADS 8
#define HD    32
#define EPS   1e-5f
#define KVS   4

// ---------------- scratch (device globals; no allocation) ----------------
__device__ __half g_tok0h[T_TOK * C_DIM];
__device__ float  g_tok  [T_TOK * C_DIM];
__device__ __half g_yh   [T_TOK * C_DIM];
__device__ float  g_y32  [T_TOK * C_DIM];
__device__ __half g_qkvh [T_TOK * C3];
__device__ __half g_ovh  [T_TOK * C_DIM];
__device__ float  g_tok2 [T_TOK * C_DIM];
__device__ __half g_zh   [T_TOK * C_DIM];
__device__ __half g_h1h  [T_TOK * FF];
__device__ __half g_tok3h[T_TOK * C_DIM];
__device__ float  g_tmp  [T_TOK * C_DIM];
__device__ float  g_opart[KVS * T_TOK * C_DIM];
__device__ float  g_l    [KVS * T_TOK * HEADS];
__device__ __half g_w_in_h [C_DIM * C_DIM];
__device__ __half g_w_qkv_h[C3 * C_DIM];
__device__ __half g_w_ap_h [C_DIM * C_DIM];
__device__ __half g_w_ff1_h[FF * C_DIM];
__device__ __half g_w_ff2_h[C_DIM * FF];
__device__ __half g_w_out_h[C_DIM * C_DIM];

// ---------------- helpers ----------------
__device__ __forceinline__ unsigned pack_h2(float lo, float hi) {
    __half2 t = __floats2half2_rn(lo, hi);
    return *reinterpret_cast<unsigned*>(&t);
}
__device__ __forceinline__ unsigned ex2_h2(unsigned x) {
    unsigned y;
    asm("ex2.approx.f16x2 %0, %1;" : "=r"(y) : "r"(x));
    return y;
}
__device__ __forceinline__ void mma_f16(float c[4], const unsigned a[4], const unsigned b[2]) {
    asm volatile(
        "mma.sync.aligned.m16n8k16.row.col.f32.f16.f16.f32 "
        "{%0,%1,%2,%3}, {%4,%5,%6,%7}, {%8,%9}, {%0,%1,%2,%3};"
        : "+f"(c[0]), "+f"(c[1]), "+f"(c[2]), "+f"(c[3])
        : "r"(a[0]), "r"(a[1]), "r"(a[2]), "r"(a[3]), "r"(b[0]), "r"(b[1]));
}
__device__ __forceinline__ void ldsm4(unsigned& r0, unsigned& r1, unsigned& r2, unsigned& r3,
                                      const void* p) {
    unsigned a = (unsigned)__cvta_generic_to_shared(p);
    asm volatile("ldmatrix.sync.aligned.m8n8.x4.shared.b16 {%0,%1,%2,%3}, [%4];"
                 : "=r"(r0), "=r"(r1), "=r"(r2), "=r"(r3) : "r"(a));
}
__device__ __forceinline__ void cp16(void* s, const void* g) {
    unsigned sa = (unsigned)__cvta_generic_to_shared(s);
    asm volatile("cp.async.cg.shared.global [%0], [%1], 16;\n" :: "r"(sa), "l"(g));
}
#define CP_COMMIT() asm volatile("cp.async.commit_group;\n" ::: "memory")
#define CP_WAIT1()  asm volatile("cp.async.wait_group 1;\n" ::: "memory")
#define CP_WAIT0()  asm volatile("cp.async.wait_group 0;\n" ::: "memory")

// ---------------- fused weight conversion f32 -> f16 (one launch) ------------
struct CvtArgs {
    const float* src[6];
    __half* dst[6];
    int n4[6];
};
__global__ void cvt_all_k(CvtArgs a) {
#pragma unroll
    for (int s = 0; s < 6; s++) {
        const float4* sp = reinterpret_cast<const float4*>(a.src[s]);
        unsigned* dp = reinterpret_cast<unsigned*>(a.dst[s]);
        int n = a.n4[s];
        for (int i = blockIdx.x * blockDim.x + threadIdx.x; i < n; i += gridDim.x * blockDim.x) {
            float4 v = sp[i];
            dp[i * 2 + 0] = pack_h2(v.x, v.y);
            dp[i * 2 + 1] = pack_h2(v.z, v.w);
        }
    }
}

// ---------------- BN (folded) + transpose -> f16 tokens ----------------
__global__ void bn_transpose_k(const float* __restrict__ x,
                               const float* __restrict__ gamma,
                               const float* __restrict__ beta,
                               const float* __restrict__ mean,
                               const float* __restrict__ var,
                               __half* __restrict__ tok0) {
    __shared__ float sm[32][33];
    int c0 = blockIdx.x * 32, t0 = blockIdx.y * 32;
    int tx = threadIdx.x, ty = threadIdx.y;
    int c = c0 + ty;
    float a  = gamma[c] * rsqrtf(var[c] + EPS);
    float bb = beta[c] - mean[c] * a;
    sm[ty][tx] = x[c * T_TOK + t0 + tx] * a + bb;
    __syncthreads();
    tok0[(t0 + ty) * C_DIM + c0 + tx] = __float2half(sm[tx][ty]);
}

// ---------------- transpose back + image residual ----------------
__global__ void out_transpose_k(const float* __restrict__ tmp,
                                const float* __restrict__ xin,
                                float* __restrict__ out) {
    __shared__ float sm[32][33];
    int c0 = blockIdx.x * 32, t0 = blockIdx.y * 32;
    int tx = threadIdx.x, ty = threadIdx.y;
    sm[ty][tx] = tmp[(t0 + ty) * C_DIM + c0 + tx];
    __syncthreads();
    int c = c0 + ty, t = t0 + tx;
    out[c * T_TOK + t] = sm[tx][ty] + xin[c * T_TOK + t];
}

// ---------------- LayerNorm: f32 in -> f16 out (+ optional f32 copy) --------
__global__ void ln_k(const float* __restrict__ x,
                     const float* __restrict__ g,
                     const float* __restrict__ b,
                     __half* __restrict__ yh, float* __restrict__ y32) {
    int row  = blockIdx.x * 8 + (threadIdx.x >> 5);
    int lane = threadIdx.x & 31;
    const float* xr = x + row * C_DIM;
    float v[8], s = 0.f, s2 = 0.f;
#pragma unroll
    for (int i = 0; i < 8; i++) {
        v[i] = xr[lane + 32 * i];
        s += v[i]; s2 += v[i] * v[i];
    }
#pragma unroll
    for (int off = 16; off > 0; off >>= 1) {
        s  += __shfl_xor_sync(0xffffffffu, s,  off);
        s2 += __shfl_xor_sync(0xffffffffu, s2, off);
    }
    float mu = s * (1.f / C_DIM);
    float va = s2 * (1.f / C_DIM) - mu * mu;
    float r = rsqrtf(va + EPS);
#pragma unroll
    for (int i = 0; i < 8; i++) {
        int c = lane + 32 * i;
        float o = (v[i] - mu) * r * g[c] + b[c];
        yh[row * C_DIM + c] = __float2half(o);
        if (y32) y32[row * C_DIM + c] = o;
    }
}

// ---------------- fp16 tensor-core GEMM, cp.async 2-stage, LDSM frags -------
// BM=128 BN=64 BK=32, 256 threads (8 warps, 4x2 grid, 32x32 warp tile).
#define GROW 40
#define GSTAGE (192 * GROW)
#define SMEM_GEMM (2 * GSTAGE * 2)
__global__ __launch_bounds__(256)
void gemm_k(const __half* __restrict__ A, const __half* __restrict__ W,
            const float* __restrict__ bias,
            const float* __restrict__ add1, const float* __restrict__ add2,
            float* __restrict__ outf, __half* __restrict__ outh,
            int M, int N, int K, int act) {
    extern __shared__ __half smh[];
    const int tid = threadIdx.x;
    const int warp = tid >> 5, l = tid & 31;
    const int wm = warp >> 1, wn = warp & 1;
    const int r = l >> 2, c2 = (l & 3) * 2;
    const int sub = l & 7, gq = l >> 3;          // LDSM lane decomposition
    const int m0 = blockIdx.y * 128, n0 = blockIdx.x * 64;
    const int arow = tid >> 2, ach = (tid & 3) * 8;
    const int wrow = tid >> 2, wch = (tid & 3) * 8;

    float acc[2][4][4];
#pragma unroll
    for (int tm = 0; tm < 2; tm++)
#pragma unroll
        for (int j = 0; j < 4; j++)
#pragma unroll
            for (int i = 0; i < 4; i++) acc[tm][j][i] = 0.f;

    const int nt = K >> 5;
#pragma unroll
    for (int t0 = 0; t0 < 2; t0++) {
        if (t0 < nt) {
            __half* As = smh + t0 * GSTAGE;
            __half* Ws = As + 128 * GROW;
#pragma unroll
            for (int i = 0; i < 2; i++) {
                int row = arow + i * 64;
                cp16(&As[row * GROW + ach], A + (size_t)(m0 + row) * K + t0 * 32 + ach);
            }
            cp16(&Ws[wrow * GROW + wch], W + (size_t)(n0 + wrow) * K + t0 * 32 + wch);
            CP_COMMIT();
        }
    }

    for (int t = 0; t < nt; t++) {
        if (t + 1 < nt) CP_WAIT1(); else CP_WAIT0();
        __syncthreads();
        __half* As = smh + (t & 1) * GSTAGE;
        __half* Ws = As + 128 * GROW;
#pragma unroll
        for (int kk = 0; kk < 2; kk++) {
            unsigned au[2][4], bu[4][2];
#pragma unroll
            for (int tm = 0; tm < 2; tm++) {
                // x4 tiles: (g&1)->m-half, (g>>1)->k-half  =>  a0,a1,a2,a3 order
                const __half* pa = &As[(wm * 32 + tm * 16 + (gq & 1) * 8 + sub) * GROW
                                       + kk * 16 + (gq >> 1) * 8];
                ldsm4(au[tm][0], au[tm][1], au[tm][2], au[tm][3], pa);
            }
#pragma unroll
            for (int jp = 0; jp < 2; jp++) {
                // x4 tiles: (g&1)->k-half, (g>>1)->n-tile  => b[2jp][0],b[2jp][1],b[2jp+1][0],b[2jp+1][1]
                const __half* pb = &Ws[(wn * 32 + jp * 16 + (gq >> 1) * 8 + sub) * GROW
                                       + kk * 16 + (gq & 1) * 8];
                ldsm4(bu[2 * jp][0], bu[2 * jp][1], bu[2 * jp + 1][0], bu[2 * jp + 1][1], pb);
            }
#pragma unroll
            for (int tm = 0; tm < 2; tm++)
#pragma unroll
                for (int j = 0; j < 4; j++)
                    mma_f16(acc[tm][j], au[tm], bu[j]);
        }
        __syncthreads();
        if (t + 2 < nt) {
            __half* Asn = smh + (t & 1) * GSTAGE;
            __half* Wsn = Asn + 128 * GROW;
            int k0 = (t + 2) * 32;
#pragma unroll
            for (int i = 0; i < 2; i++) {
                int row = arow + i * 64;
                cp16(&Asn[row * GROW + ach], A + (size_t)(m0 + row) * K + k0 + ach);
            }
            cp16(&Wsn[wrow * GROW + wch], W + (size_t)(n0 + wrow) * K + k0 + wch);
            CP_COMMIT();
        }
    }

    // epilogue (f32)
#pragma unroll
    for (int tm = 0; tm < 2; tm++) {
#pragma unroll
        for (int j = 0; j < 4; j++) {
            int rr0 = m0 + wm * 32 + tm * 16 + r;
            int cc = n0 + wn * 32 + 8 * j + c2;
#pragma unroll
            for (int half = 0; half < 2; half++) {
                int rr = rr0 + half * 8;
                float v0 = acc[tm][j][half * 2 + 0] + bias[cc];
                float v1 = acc[tm][j][half * 2 + 1] + bias[cc + 1];
                size_t idx = (size_t)rr * N + cc;
                if (add1) { v0 += add1[idx]; v1 += add1[idx + 1]; }
                if (add2) { v0 += add2[idx]; v1 += add2[idx + 1]; }
                if (act == 1) {
                    v0 = 0.5f * v0 * (1.0f + erff(v0 * 0.70710678118654752f));
                    v1 = 0.5f * v1 * (1.0f + erff(v1 * 0.70710678118654752f));
                }
                if (outf) { outf[idx] = v0; outf[idx + 1] = v1; }
                if (outh) *reinterpret_cast<unsigned*>(outh + idx) = pack_h2(v0, v1);
            }
        }
    }
}

// ---------------- flash attention: fp16, LDSM frags, f16x2 exp, KVS=4 -------
__global__ __launch_bounds__(256)
void attn_k(const __half* __restrict__ qkv,
            float* __restrict__ opart, float* __restrict__ lpart) {
    __shared__ __half Qb[128][40];
    __shared__ __half Kb[64][40];
    __shared__ __half Vt[32][72];

    const int h = blockIdx.y, q0 = blockIdx.x * 128, split = blockIdx.z;
    const int tid = threadIdx.x;
    const int w = tid >> 5, l = tid & 31;
    const int r = l >> 2, c2 = (l & 3) * 2;
    const int sub = l & 7, gq = l >> 3;
    const float K2 = 1.4426950408889634f * 0.17677669529663689f;
    const __half2 K2h = __float2half2_rn(K2);
    const int lrow = tid >> 2, lch = (tid & 3) * 8;

    // stage Q (f16), pre-scaled by K2
#pragma unroll
    for (int i = 0; i < 2; i++) {
        int s = tid + i * 256;
        int row = s >> 2, ch = (s & 3) * 8;
        uint4 v = *reinterpret_cast<const uint4*>(qkv + (size_t)(q0 + row) * C3 + h * HD + ch);
        __half2* hv = reinterpret_cast<__half2*>(&v);
#pragma unroll
        for (int k = 0; k < 4; k++) hv[k] = __hmul2(hv[k], K2h);
        *reinterpret_cast<uint4*>(&Qb[row][ch]) = v;
    }
    __syncthreads();
    unsigned aq[2][4];
#pragma unroll
    for (int kk = 0; kk < 2; kk++) {
        const __half* pq = &Qb[w * 16 + (gq & 1) * 8 + sub][kk * 16 + (gq >> 1) * 8];
        ldsm4(aq[kk][0], aq[kk][1], aq[kk][2], aq[kk][3], pq);
    }

    float oa[4][4];
#pragma unroll
    for (int jd = 0; jd < 4; jd++)
#pragma unroll
        for (int i = 0; i < 4; i++) oa[jd][i] = 0.f;
    float l0 = 0.f, l1 = 0.f;

    const int NT = (T_TOK / KVS) / 64;
    const int kb0 = split * NT;
    uint4 kr, vr;
    {
        const __half* kp = qkv + (size_t)(kb0 * 64 + lrow) * C3 + C_DIM + h * HD + lch;
        kr = *reinterpret_cast<const uint4*>(kp);
        vr = *reinterpret_cast<const uint4*>(kp + C_DIM);
    }
    {
        *reinterpret_cast<uint4*>(&Kb[lrow][lch]) = kr;
        const __half* vh = reinterpret_cast<const __half*>(&vr);
#pragma unroll
        for (int i = 0; i < 8; i++) Vt[lch + i][lrow] = vh[i];
    }
    __syncthreads();

    for (int t = 0; t < NT; t++) {
        if (t + 1 < NT) {
            const __half* kp = qkv + (size_t)((kb0 + t + 1) * 64 + lrow) * C3 + C_DIM + h * HD + lch;
            kr = *reinterpret_cast<const uint4*>(kp);
            vr = *reinterpret_cast<const uint4*>(kp + C_DIM);
        }

        // S = Q K^T (f16, pre-scaled; warp: 16 x 64)
        float st[8][4];
#pragma unroll
        for (int j = 0; j < 8; j++)
#pragma unroll
            for (int i = 0; i < 4; i++) st[j][i] = 0.f;
#pragma unroll
        for (int kk = 0; kk < 2; kk++) {
            unsigned bk[8][2];
#pragma unroll
            for (int jp = 0; jp < 4; jp++) {
                const __half* pk = &Kb[jp * 16 + (gq >> 1) * 8 + sub][kk * 16 + (gq & 1) * 8];
                ldsm4(bk[2 * jp][0], bk[2 * jp][1], bk[2 * jp + 1][0], bk[2 * jp + 1][1], pk);
            }
#pragma unroll
            for (int j = 0; j < 8; j++)
                mma_f16(st[j], aq[kk], bk[j]);
        }
        // p = exp2(st) via f16x2 MUFU
        unsigned pa[8], pb[8];
#pragma unroll
        for (int j = 0; j < 8; j++) {
            pa[j] = ex2_h2(pack_h2(st[j][0], st[j][1]));
            pb[j] = ex2_h2(pack_h2(st[j][2], st[j][3]));
        }
        // l accumulation: HADD2 tree then f32
        {
            __half2 sa = *reinterpret_cast<__half2*>(&pa[0]);
            __half2 sb = *reinterpret_cast<__half2*>(&pb[0]);
#pragma unroll
            for (int j = 1; j < 8; j++) {
                sa = __hadd2(sa, *reinterpret_cast<__half2*>(&pa[j]));
                sb = __hadd2(sb, *reinterpret_cast<__half2*>(&pb[j]));
            }
            float2 fa = __half22float2(sa), fb = __half22float2(sb);
            l0 += fa.x + fa.y;
            l1 += fb.x + fb.y;
        }
        // PV: A fragments are the f16x2 p values directly; V frags via LDSM
#pragma unroll
        for (int kk = 0; kk < 4; kk++) {
            unsigned bv[4][2];
#pragma unroll
            for (int jp = 0; jp < 2; jp++) {
                const __half* pv = &Vt[jp * 16 + (gq >> 1) * 8 + sub][kk * 16 + (gq & 1) * 8];
                ldsm4(bv[2 * jp][0], bv[2 * jp][1], bv[2 * jp + 1][0], bv[2 * jp + 1][1], pv);
            }
            unsigned ap[4] = { pa[2 * kk], pb[2 * kk], pa[2 * kk + 1], pb[2 * kk + 1] };
#pragma unroll
            for (int jd = 0; jd < 4; jd++)
                mma_f16(oa[jd], ap, bv[jd]);
        }
        __syncthreads();
        if (t + 1 < NT) {
            *reinterpret_cast<uint4*>(&Kb[lrow][lch]) = kr;
            const __half* vh = reinterpret_cast<const __half*>(&vr);
#pragma unroll
            for (int i = 0; i < 8; i++) Vt[lch + i][lrow] = vh[i];
            __syncthreads();
        }
    }

    l0 += __shfl_xor_sync(0xffffffffu, l0, 1);
    l0 += __shfl_xor_sync(0xffffffffu, l0, 2);
    l1 += __shfl_xor_sync(0xffffffffu, l1, 1);
    l1 += __shfl_xor_sync(0xffffffffu, l1, 2);

    int row0 = q0 + w * 16 + r;
    float* ob = opart + ((size_t)split * T_TOK) * C_DIM;
#pragma unroll
    for (int jd = 0; jd < 4; jd++) {
        int col = h * HD + 8 * jd + c2;
        *reinterpret_cast<float2*>(ob + (size_t)row0 * C_DIM + col) =
            make_float2(oa[jd][0], oa[jd][1]);
        *reinterpret_cast<float2*>(ob + (size_t)(row0 + 8) * C_DIM + col) =
            make_float2(oa[jd][2], oa[jd][3]);
    }
    if ((l & 3) == 0) {
        lpart[((size_t)split * T_TOK + row0) * HEADS + h] = l0;
        lpart[((size_t)split * T_TOK + row0 + 8) * HEADS + h] = l1;
    }
}

// ---------------- combine KV splits -> f16 ----------------
__global__ void attn_combine_k(const float* __restrict__ opart,
                               const float* __restrict__ lpart,
                               __half* __restrict__ ov) {
    int row  = blockIdx.x * 8 + (threadIdx.x >> 5);
    int lane = threadIdx.x & 31;
#pragma unroll
    for (int k = 0; k < 8; k++) {
        int c = lane + 32 * k;
        float lsum = 0.f, osum = 0.f;
#pragma unroll
        for (int s = 0; s < KVS; s++) {
            lsum += lpart[((size_t)s * T_TOK + row) * HEADS + k];
            osum += opart[((size_t)s * T_TOK + row) * C_DIM + c];
        }
        ov[(size_t)row * C_DIM + c] = __float2half(osum / lsum);
    }
}

// ---------------- launch ----------------
template <typename Sym>
static void* dev_ptr(const Sym& sym) {
    void* p = nullptr;
    cudaGetSymbolAddress(&p, sym);
    return p;
}

extern "C" void kernel_launch(void* const* d_in, const int* in_sizes, int n_in,
                              void* d_out, int out_size) {
    (void)in_sizes; (void)n_in; (void)out_size;
    const float* x        = (const float*)d_in[0];
    const float* bn_gamma = (const float*)d_in[1];
    const float* bn_beta  = (const float*)d_in[2];
    const float* bn_mean  = (const float*)d_in[3];
    const float* bn_var   = (const float*)d_in[4];
    const float* w_in     = (const float*)d_in[5];
    const float* b_in     = (const float*)d_in[6];
    const float* ln1_g    = (const float*)d_in[7];
    const float* ln1_b    = (const float*)d_in[8];
    const float* w_qkv    = (const float*)d_in[9];
    const float* b_qkv    = (const float*)d_in[10];
    const float* w_ap     = (const float*)d_in[11];
    const float* b_ap     = (const float*)d_in[12];
    const float* ln2_g    = (const float*)d_in[13];
    const float* ln2_b    = (const float*)d_in[14];
    const float* w_ff1    = (const float*)d_in[15];
    const float* b_ff1    = (const float*)d_in[16];
    const float* w_ff2    = (const float*)d_in[17];
    const float* b_ff2    = (const float*)d_in[18];
    const float* w_out    = (const float*)d_in[19];
    const float* b_out    = (const float*)d_in[20];
    float* out = (float*)d_out;

    __half* tok0h = (__half*)dev_ptr(g_tok0h);
    float*  tok   = (float*)dev_ptr(g_tok);
    __half* yh    = (__half*)dev_ptr(g_yh);
    float*  y32   = (float*)dev_ptr(g_y32);
    __half* qkvh  = (__half*)dev_ptr(g_qkvh);
    __half* ovh   = (__half*)dev_ptr(g_ovh);
    float*  tok2  = (float*)dev_ptr(g_tok2);
    __half* zh    = (__half*)dev_ptr(g_zh);
    __half* h1h   = (__half*)dev_ptr(g_h1h);
    __half* tok3h = (__half*)dev_ptr(g_tok3h);
    float*  tmp   = (float*)dev_ptr(g_tmp);
    float*  opart = (float*)dev_ptr(g_opart);
    float*  lpart = (float*)dev_ptr(g_l);
    __half* w_in_h  = (__half*)dev_ptr(g_w_in_h);
    __half* w_qkv_h = (__half*)dev_ptr(g_w_qkv_h);
    __half* w_ap_h  = (__half*)dev_ptr(g_w_ap_h);
    __half* w_ff1_h = (__half*)dev_ptr(g_w_ff1_h);
    __half* w_ff2_h = (__half*)dev_ptr(g_w_ff2_h);
    __half* w_out_h = (__half*)dev_ptr(g_w_out_h);

    // fused weight conversion
    CvtArgs ca;
    ca.src[0] = w_in;  ca.dst[0] = w_in_h;  ca.n4[0] = C_DIM * C_DIM / 4;
    ca.src[1] = w_qkv; ca.dst[1] = w_qkv_h; ca.n4[1] = C3 * C_DIM / 4;
    ca.src[2] = w_ap;  ca.dst[2] = w_ap_h;  ca.n4[2] = C_DIM * C_DIM / 4;
    ca.src[3] = w_ff1; ca.dst[3] = w_ff1_h; ca.n4[3] = FF * C_DIM / 4;
    ca.src[4] = w_ff2; ca.dst[4] = w_ff2_h; ca.n4[4] = C_DIM * FF / 4;
    ca.src[5] = w_out; ca.dst[5] = w_out_h; ca.n4[5] = C_DIM * C_DIM / 4;
    cvt_all_k<<<448, 256>>>(ca);

    // 1) BN + transpose
    bn_transpose_k<<<dim3(C_DIM / 32, T_TOK / 32), dim3(32, 32)>>>(
        x, bn_gamma, bn_beta, bn_mean, bn_var, tok0h);
    // 2) proj_in -> tok (f32)
    gemm_k<<<dim3(C_DIM / 64, T_TOK / 128), 256, SMEM_GEMM>>>(
        tok0h, w_in_h, b_in, nullptr, nullptr, tok, nullptr, T_TOK, C_DIM, C_DIM, 0);
    // 3) LN1 -> yh + y32
    ln_k<<<T_TOK / 8, 256>>>(tok, ln1_g, ln1_b, yh, y32);
    // 4) QKV -> qkvh (f16)
    gemm_k<<<dim3(C3 / 64, T_TOK / 128), 256, SMEM_GEMM>>>(
        yh, w_qkv_h, b_qkv, nullptr, nullptr, nullptr, qkvh, T_TOK, C3, C_DIM, 0);
    // 5) attention + combine
    attn_k<<<dim3(T_TOK / 128, HEADS, KVS), 256>>>(qkvh, opart, lpart);
    attn_combine_k<<<T_TOK / 8, 256>>>(opart, lpart, ovh);
    // 6) attn proj + y32 + tok -> tok2 (f32)
    gemm_k<<<dim3(C_DIM / 64, T_TOK / 128), 256, SMEM_GEMM>>>(
        ovh, w_ap_h, b_ap, y32, tok, tok2, nullptr, T_TOK, C_DIM, C_DIM, 0);
    // 7) LN2 -> zh
    ln_k<<<T_TOK / 8, 256>>>(tok2, ln2_g, ln2_b, zh, nullptr);
    // 8) FF1 + gelu -> h1h (f16)
    gemm_k<<<dim3(FF / 64, T_TOK / 128), 256, SMEM_GEMM>>>(
        zh, w_ff1_h, b_ff1, nullptr, nullptr, nullptr, h1h, T_TOK, FF, C_DIM, 1);
    // 9) FF2 + tok2 -> tok3h (f16)
    gemm_k<<<dim3(C_DIM / 64, T_TOK / 128), 256, SMEM_GEMM>>>(
        h1h, w_ff2_h, b_ff2, tok2, nullptr, nullptr, tok3h, T_TOK, C_DIM, FF, 0);
    // 10) proj_out -> tmp (f32)
    gemm_k<<<dim3(C_DIM / 64, T_TOK / 128), 256, SMEM_GEMM>>>(
        tok3h, w_out_h, b_out, nullptr, nullptr, tmp, nullptr, T_TOK, C_DIM, C_DIM, 0);
    // 11) transpose back + image residual
    out_transpose_k<<<dim3(C_DIM / 32, T_TOK / 32), dim3(32, 32)>>>(tmp, x, out);
}

// round 10
// speedup vs baseline: 21.7264x; 1.1729x over previous
#include <cuda_runtime.h>
#include <cuda_fp16.h>
#include <math.h>

#define T_TOK 4096
#define C_DIM 256
#define C3    768
#define FF    1024
#define HEADS 8
#define HD    32
#define EPS   1e-5f
#define KVS   4

// ---------------- scratch (device globals; no allocation) ----------------
__device__ __half g_tok0h[T_TOK * C_DIM];
__device__ float  g_tok  [T_TOK * C_DIM];
__device__ __half g_yh   [T_TOK * C_DIM];
__device__ float  g_y32  [T_TOK * C_DIM];
__device__ __half g_qkvh [T_TOK * C3];
__device__ __half g_ovh  [T_TOK * C_DIM];
__device__ float  g_tok2 [T_TOK * C_DIM];
__device__ __half g_zh   [T_TOK * C_DIM];
__device__ __half g_h1h  [T_TOK * FF];
__device__ __half g_tok3h[T_TOK * C_DIM];
__device__ float  g_tmp  [T_TOK * C_DIM];
__device__ float  g_opart[KVS * T_TOK * C_DIM];
__device__ float  g_l    [KVS * T_TOK * HEADS];
__device__ __half g_w_in_h [C_DIM * C_DIM];
__device__ __half g_w_qkv_h[C3 * C_DIM];
__device__ __half g_w_ap_h [C_DIM * C_DIM];
__device__ __half g_w_ff1_h[FF * C_DIM];
__device__ __half g_w_ff2_h[C_DIM * FF];
__device__ __half g_w_out_h[C_DIM * C_DIM];

// ---------------- helpers ----------------
__device__ __forceinline__ unsigned pack_h2(float lo, float hi) {
    __half2 t = __floats2half2_rn(lo, hi);
    return *reinterpret_cast<unsigned*>(&t);
}
__device__ __forceinline__ unsigned ex2_h2(unsigned x) {
    unsigned y;
    asm("ex2.approx.f16x2 %0, %1;" : "=r"(y) : "r"(x));
    return y;
}
__device__ __forceinline__ void mma_f16(float c[4], const unsigned a[4], const unsigned b[2]) {
    asm volatile(
        "mma.sync.aligned.m16n8k16.row.col.f32.f16.f16.f32 "
        "{%0,%1,%2,%3}, {%4,%5,%6,%7}, {%8,%9}, {%0,%1,%2,%3};"
        : "+f"(c[0]), "+f"(c[1]), "+f"(c[2]), "+f"(c[3])
        : "r"(a[0]), "r"(a[1]), "r"(a[2]), "r"(a[3]), "r"(b[0]), "r"(b[1]));
}
__device__ __forceinline__ void ldsm4(unsigned& r0, unsigned& r1, unsigned& r2, unsigned& r3,
                                      const void* p) {
    unsigned a = (unsigned)__cvta_generic_to_shared(p);
    asm volatile("ldmatrix.sync.aligned.m8n8.x4.shared.b16 {%0,%1,%2,%3}, [%4];"
                 : "=r"(r0), "=r"(r1), "=r"(r2), "=r"(r3) : "r"(a));
}
__device__ __forceinline__ void ldsm4t(unsigned& r0, unsigned& r1, unsigned& r2, unsigned& r3,
                                       const void* p) {
    unsigned a = (unsigned)__cvta_generic_to_shared(p);
    asm volatile("ldmatrix.sync.aligned.m8n8.x4.trans.shared.b16 {%0,%1,%2,%3}, [%4];"
                 : "=r"(r0), "=r"(r1), "=r"(r2), "=r"(r3) : "r"(a));
}
__device__ __forceinline__ void cp16(void* s, const void* g) {
    unsigned sa = (unsigned)__cvta_generic_to_shared(s);
    asm volatile("cp.async.cg.shared.global [%0], [%1], 16;\n" :: "r"(sa), "l"(g));
}
#define CP_COMMIT() asm volatile("cp.async.commit_group;\n" ::: "memory")
#define CP_WAIT2()  asm volatile("cp.async.wait_group 2;\n" ::: "memory")
#define CP_WAIT1()  asm volatile("cp.async.wait_group 1;\n" ::: "memory")
#define CP_WAIT0()  asm volatile("cp.async.wait_group 0;\n" ::: "memory")
__device__ __forceinline__ void cp_wait_dyn(int rem) {
    if (rem >= 2) CP_WAIT2();
    else if (rem == 1) CP_WAIT1();
    else CP_WAIT0();
}

// ---------------- fused weight conversion f32 -> f16 (one launch) ------------
struct CvtArgs {
    const float* src[6];
    __half* dst[6];
    int n4[6];
};
__global__ void cvt_all_k(CvtArgs a) {
#pragma unroll
    for (int s = 0; s < 6; s++) {
        const float4* sp = reinterpret_cast<const float4*>(a.src[s]);
        unsigned* dp = reinterpret_cast<unsigned*>(a.dst[s]);
        int n = a.n4[s];
        for (int i = blockIdx.x * blockDim.x + threadIdx.x; i < n; i += gridDim.x * blockDim.x) {
            float4 v = sp[i];
            dp[i * 2 + 0] = pack_h2(v.x, v.y);
            dp[i * 2 + 1] = pack_h2(v.z, v.w);
        }
    }
}

// ---------------- BN (folded) + transpose -> f16 tokens ----------------
__global__ void bn_transpose_k(const float* __restrict__ x,
                               const float* __restrict__ gamma,
                               const float* __restrict__ beta,
                               const float* __restrict__ mean,
                               const float* __restrict__ var,
                               __half* __restrict__ tok0) {
    __shared__ float sm[32][33];
    int c0 = blockIdx.x * 32, t0 = blockIdx.y * 32;
    int tx = threadIdx.x, ty = threadIdx.y;
    int c = c0 + ty;
    float a  = gamma[c] * rsqrtf(var[c] + EPS);
    float bb = beta[c] - mean[c] * a;
    sm[ty][tx] = x[c * T_TOK + t0 + tx] * a + bb;
    __syncthreads();
    tok0[(t0 + ty) * C_DIM + c0 + tx] = __float2half(sm[tx][ty]);
}

// ---------------- transpose back + image residual ----------------
__global__ void out_transpose_k(const float* __restrict__ tmp,
                                const float* __restrict__ xin,
                                float* __restrict__ out) {
    __shared__ float sm[32][33];
    int c0 = blockIdx.x * 32, t0 = blockIdx.y * 32;
    int tx = threadIdx.x, ty = threadIdx.y;
    sm[ty][tx] = tmp[(t0 + ty) * C_DIM + c0 + tx];
    __syncthreads();
    int c = c0 + ty, t = t0 + tx;
    out[c * T_TOK + t] = sm[tx][ty] + xin[c * T_TOK + t];
}

// ---------------- LayerNorm: vectorized f32 in -> f16 out (+f32 copy) -------
__global__ void ln_k(const float* __restrict__ x,
                     const float* __restrict__ g,
                     const float* __restrict__ b,
                     __half* __restrict__ yh, float* __restrict__ y32) {
    int row  = blockIdx.x * 8 + (threadIdx.x >> 5);
    int lane = threadIdx.x & 31;
    const float4* xr = reinterpret_cast<const float4*>(x + (size_t)row * C_DIM) + lane * 2;
    float4 v0 = xr[0], v1 = xr[1];
    float v[8] = { v0.x, v0.y, v0.z, v0.w, v1.x, v1.y, v1.z, v1.w };
    float s = 0.f, s2 = 0.f;
#pragma unroll
    for (int i = 0; i < 8; i++) { s += v[i]; s2 += v[i] * v[i]; }
#pragma unroll
    for (int off = 16; off > 0; off >>= 1) {
        s  += __shfl_xor_sync(0xffffffffu, s,  off);
        s2 += __shfl_xor_sync(0xffffffffu, s2, off);
    }
    float mu = s * (1.f / C_DIM);
    float va = s2 * (1.f / C_DIM) - mu * mu;
    float r = rsqrtf(va + EPS);
    const float4* gp = reinterpret_cast<const float4*>(g) + lane * 2;
    const float4* bp = reinterpret_cast<const float4*>(b) + lane * 2;
    float4 g0 = gp[0], g1 = gp[1], b0 = bp[0], b1 = bp[1];
    float gg[8] = { g0.x, g0.y, g0.z, g0.w, g1.x, g1.y, g1.z, g1.w };
    float bb[8] = { b0.x, b0.y, b0.z, b0.w, b1.x, b1.y, b1.z, b1.w };
    float o[8];
#pragma unroll
    for (int i = 0; i < 8; i++) o[i] = (v[i] - mu) * r * gg[i] + bb[i];
    uint4 ho;
    ho.x = pack_h2(o[0], o[1]); ho.y = pack_h2(o[2], o[3]);
    ho.z = pack_h2(o[4], o[5]); ho.w = pack_h2(o[6], o[7]);
    *reinterpret_cast<uint4*>(yh + (size_t)row * C_DIM + lane * 8) = ho;
    if (y32) {
        float4* yp = reinterpret_cast<float4*>(y32 + (size_t)row * C_DIM) + lane * 2;
        yp[0] = make_float4(o[0], o[1], o[2], o[3]);
        yp[1] = make_float4(o[4], o[5], o[6], o[7]);
    }
}

// ---------------- fp16 GEMM, cp.async 4-stage ring, LDSM frags --------------
// BM=128 BN=64 BK=32, 256 threads (8 warps, 4x2 grid, 32x32 warp tile).
#define GROW 40
#define GSTAGE (192 * GROW)                 // halves per stage
#define SMEM_GEMM (4 * GSTAGE * 2)          // bytes
__global__ __launch_bounds__(256)
void gemm_k(const __half* __restrict__ A, const __half* __restrict__ W,
            const float* __restrict__ bias,
            const float* __restrict__ add1, const float* __restrict__ add2,
            float* __restrict__ outf, __half* __restrict__ outh,
            int M, int N, int K, int act) {
    extern __shared__ __half smh[];
    const int tid = threadIdx.x;
    const int warp = tid >> 5, l = tid & 31;
    const int wm = warp >> 1, wn = warp & 1;
    const int r = l >> 2, c2 = (l & 3) * 2;
    const int sub = l & 7, gq = l >> 3;
    const int m0 = blockIdx.y * 128, n0 = blockIdx.x * 64;
    const int lrow = tid >> 2, lch = (tid & 3) * 8;

    float acc[2][4][4];
#pragma unroll
    for (int tm = 0; tm < 2; tm++)
#pragma unroll
        for (int j = 0; j < 4; j++)
#pragma unroll
            for (int i = 0; i < 4; i++) acc[tm][j][i] = 0.f;

    const int nt = K >> 5;
#pragma unroll
    for (int t0 = 0; t0 < 3; t0++) {
        if (t0 < nt) {
            __half* As = smh + t0 * GSTAGE;
            __half* Ws = As + 128 * GROW;
#pragma unroll
            for (int i = 0; i < 2; i++) {
                int row = lrow + i * 64;
                cp16(&As[row * GROW + lch], A + (size_t)(m0 + row) * K + t0 * 32 + lch);
            }
            cp16(&Ws[lrow * GROW + lch], W + (size_t)(n0 + lrow) * K + t0 * 32 + lch);
            CP_COMMIT();
        }
    }

    for (int t = 0; t < nt; t++) {
        cp_wait_dyn(nt - t - 1);
        __syncthreads();
        __half* As = smh + (t & 3) * GSTAGE;
        __half* Ws = As + 128 * GROW;
#pragma unroll
        for (int kk = 0; kk < 2; kk++) {
            unsigned au[2][4], bu[4][2];
#pragma unroll
            for (int tm = 0; tm < 2; tm++) {
                const __half* pa = &As[(wm * 32 + tm * 16 + (gq & 1) * 8 + sub) * GROW
                                       + kk * 16 + (gq >> 1) * 8];
                ldsm4(au[tm][0], au[tm][1], au[tm][2], au[tm][3], pa);
            }
#pragma unroll
            for (int jp = 0; jp < 2; jp++) {
                const __half* pb = &Ws[(wn * 32 + jp * 16 + (gq >> 1) * 8 + sub) * GROW
                                       + kk * 16 + (gq & 1) * 8];
                ldsm4(bu[2 * jp][0], bu[2 * jp][1], bu[2 * jp + 1][0], bu[2 * jp + 1][1], pb);
            }
#pragma unroll
            for (int tm = 0; tm < 2; tm++)
#pragma unroll
                for (int j = 0; j < 4; j++)
                    mma_f16(acc[tm][j], au[tm], bu[j]);
        }
        if (t + 3 < nt) {
            __half* Asn = smh + ((t + 3) & 3) * GSTAGE;
            __half* Wsn = Asn + 128 * GROW;
            int k0 = (t + 3) * 32;
#pragma unroll
            for (int i = 0; i < 2; i++) {
                int row = lrow + i * 64;
                cp16(&Asn[row * GROW + lch], A + (size_t)(m0 + row) * K + k0 + lch);
            }
            cp16(&Wsn[lrow * GROW + lch], W + (size_t)(n0 + lrow) * K + k0 + lch);
            CP_COMMIT();
        }
    }

    // epilogue (f32)
#pragma unroll
    for (int tm = 0; tm < 2; tm++) {
#pragma unroll
        for (int j = 0; j < 4; j++) {
            int rr0 = m0 + wm * 32 + tm * 16 + r;
            int cc = n0 + wn * 32 + 8 * j + c2;
#pragma unroll
            for (int half = 0; half < 2; half++) {
                int rr = rr0 + half * 8;
                float v0 = acc[tm][j][half * 2 + 0] + bias[cc];
                float v1 = acc[tm][j][half * 2 + 1] + bias[cc + 1];
                size_t idx = (size_t)rr * N + cc;
                if (add1) { v0 += add1[idx]; v1 += add1[idx + 1]; }
                if (add2) { v0 += add2[idx]; v1 += add2[idx + 1]; }
                if (act == 1) {
                    v0 = 0.5f * v0 * (1.0f + erff(v0 * 0.70710678118654752f));
                    v1 = 0.5f * v1 * (1.0f + erff(v1 * 0.70710678118654752f));
                }
                if (outf) { outf[idx] = v0; outf[idx + 1] = v1; }
                if (outh) *reinterpret_cast<unsigned*>(outh + idx) = pack_h2(v0, v1);
            }
        }
    }
}

// ---------------- flash attention: 4-stage cp.async K/V ring, trans-LDSM V ---
// grid (32 qblocks, 8 heads, KVS), 256 threads (8 warps x 16 q-rows).
#define AROW 40
#define AKV  (64 * AROW)                    // halves per K (or V) stage
#define SMEM_ATTN ((128 * AROW + 4 * 2 * AKV) * 2)
__global__ __launch_bounds__(256)
void attn_k(const __half* __restrict__ qkv,
            float* __restrict__ opart, float* __restrict__ lpart) {
    extern __shared__ __half sma[];
    __half* Qb = sma;                        // [128][AROW]
    __half* KV = sma + 128 * AROW;           // stages: [K 64xAROW | V 64xAROW] x4

    const int h = blockIdx.y, q0 = blockIdx.x * 128, split = blockIdx.z;
    const int tid = threadIdx.x;
    const int w = tid >> 5, l = tid & 31;
    const int r = l >> 2, c2 = (l & 3) * 2;
    const int sub = l & 7, gq = l >> 3;
    const float K2 = 1.4426950408889634f * 0.17677669529663689f;
    const __half2 K2h = __float2half2_rn(K2);
    const int lrow = tid >> 2, lch = (tid & 3) * 8;

    // stage Q (f16), pre-scaled by K2
#pragma unroll
    for (int i = 0; i < 2; i++) {
        int s = tid + i * 256;
        int row = s >> 2, ch = (s & 3) * 8;
        uint4 v = *reinterpret_cast<const uint4*>(qkv + (size_t)(q0 + row) * C3 + h * HD + ch);
        __half2* hv = reinterpret_cast<__half2*>(&v);
#pragma unroll
        for (int k = 0; k < 4; k++) hv[k] = __hmul2(hv[k], K2h);
        *reinterpret_cast<uint4*>(&Qb[row * AROW + ch]) = v;
    }

    const int NT = (T_TOK / KVS) / 64;       // 16
    const int kb0 = split * NT;
    // prologue: issue K/V tiles 0..2
#pragma unroll
    for (int t0 = 0; t0 < 3; t0++) {
        __half* Ks = KV + t0 * 2 * AKV;
        __half* Vs = Ks + AKV;
        const __half* kp = qkv + (size_t)((kb0 + t0) * 64 + lrow) * C3 + C_DIM + h * HD + lch;
        cp16(&Ks[lrow * AROW + lch], kp);
        cp16(&Vs[lrow * AROW + lch], kp + C_DIM);
        CP_COMMIT();
    }
    __syncthreads();   // Q staged (plain STS) — visible before first LDSM
    unsigned aq[2][4];
#pragma unroll
    for (int kk = 0; kk < 2; kk++) {
        const __half* pq = &Qb[(w * 16 + (gq & 1) * 8 + sub) * AROW + kk * 16 + (gq >> 1) * 8];
        ldsm4(aq[kk][0], aq[kk][1], aq[kk][2], aq[kk][3], pq);
    }

    float oa[4][4];
#pragma unroll
    for (int jd = 0; jd < 4; jd++)
#pragma unroll
        for (int i = 0; i < 4; i++) oa[jd][i] = 0.f;
    float l0 = 0.f, l1 = 0.f;

    for (int t = 0; t < NT; t++) {
        cp_wait_dyn(NT - t - 1);
        __syncthreads();
        __half* Ks = KV + (t & 3) * 2 * AKV;
        __half* Vs = Ks + AKV;

        // S = Q K^T
        float st[8][4];
#pragma unroll
        for (int j = 0; j < 8; j++)
#pragma unroll
            for (int i = 0; i < 4; i++) st[j][i] = 0.f;
#pragma unroll
        for (int kk = 0; kk < 2; kk++) {
            unsigned bk[8][2];
#pragma unroll
            for (int jp = 0; jp < 4; jp++) {
                const __half* pk = &Ks[(jp * 16 + (gq >> 1) * 8 + sub) * AROW
                                       + kk * 16 + (gq & 1) * 8];
                ldsm4(bk[2 * jp][0], bk[2 * jp][1], bk[2 * jp + 1][0], bk[2 * jp + 1][1], pk);
            }
#pragma unroll
            for (int j = 0; j < 8; j++)
                mma_f16(st[j], aq[kk], bk[j]);
        }
        // p = exp2(st) via f16x2 MUFU
        unsigned pa[8], pb[8];
#pragma unroll
        for (int j = 0; j < 8; j++) {
            pa[j] = ex2_h2(pack_h2(st[j][0], st[j][1]));
            pb[j] = ex2_h2(pack_h2(st[j][2], st[j][3]));
        }
        {
            __half2 sa = *reinterpret_cast<__half2*>(&pa[0]);
            __half2 sb = *reinterpret_cast<__half2*>(&pb[0]);
#pragma unroll
            for (int j = 1; j < 8; j++) {
                sa = __hadd2(sa, *reinterpret_cast<__half2*>(&pa[j]));
                sb = __hadd2(sb, *reinterpret_cast<__half2*>(&pb[j]));
            }
            float2 fa = __half22float2(sa), fb = __half22float2(sb);
            l0 += fa.x + fa.y;
            l1 += fb.x + fb.y;
        }
        // PV: V row-major, B frags via ldmatrix.trans
#pragma unroll
        for (int kk = 0; kk < 4; kk++) {
            unsigned bv[4][2];
#pragma unroll
            for (int jp = 0; jp < 2; jp++) {
                const __half* pv = &Vs[(kk * 16 + (gq & 1) * 8 + sub) * AROW
                                       + jp * 16 + (gq >> 1) * 8];
                ldsm4t(bv[2 * jp][0], bv[2 * jp][1], bv[2 * jp + 1][0], bv[2 * jp + 1][1], pv);
            }
            unsigned ap[4] = { pa[2 * kk], pb[2 * kk], pa[2 * kk + 1], pb[2 * kk + 1] };
#pragma unroll
            for (int jd = 0; jd < 4; jd++)
                mma_f16(oa[jd], ap, bv[jd]);
        }
        // issue tile t+3 into ring slot (t+3)&3 (free: its readers passed this iter's barrier)
        if (t + 3 < NT) {
            __half* Ksn = KV + ((t + 3) & 3) * 2 * AKV;
            __half* Vsn = Ksn + AKV;
            const __half* kp = qkv + (size_t)((kb0 + t + 3) * 64 + lrow) * C3 + C_DIM + h * HD + lch;
            cp16(&Ksn[lrow * AROW + lch], kp);
            cp16(&Vsn[lrow * AROW + lch], kp + C_DIM);
            CP_COMMIT();
        }
    }

    l0 += __shfl_xor_sync(0xffffffffu, l0, 1);
    l0 += __shfl_xor_sync(0xffffffffu, l0, 2);
    l1 += __shfl_xor_sync(0xffffffffu, l1, 1);
    l1 += __shfl_xor_sync(0xffffffffu, l1, 2);

    int row0 = q0 + w * 16 + r;
    float* ob = opart + ((size_t)split * T_TOK) * C_DIM;
#pragma unroll
    for (int jd = 0; jd < 4; jd++) {
        int col = h * HD + 8 * jd + c2;
        *reinterpret_cast<float2*>(ob + (size_t)row0 * C_DIM + col) =
            make_float2(oa[jd][0], oa[jd][1]);
        *reinterpret_cast<float2*>(ob + (size_t)(row0 + 8) * C_DIM + col) =
            make_float2(oa[jd][2], oa[jd][3]);
    }
    if ((l & 3) == 0) {
        lpart[((size_t)split * T_TOK + row0) * HEADS + h] = l0;
        lpart[((size_t)split * T_TOK + row0 + 8) * HEADS + h] = l1;
    }
}

// ---------------- combine KV splits -> f16 ----------------
__global__ void attn_combine_k(const float* __restrict__ opart,
                               const float* __restrict__ lpart,
                               __half* __restrict__ ov) {
    int row  = blockIdx.x * 8 + (threadIdx.x >> 5);
    int lane = threadIdx.x & 31;
#pragma unroll
    for (int k = 0; k < 8; k++) {
        int c = lane + 32 * k;
        float lsum = 0.f, osum = 0.f;
#pragma unroll
        for (int s = 0; s < KVS; s++) {
            lsum += lpart[((size_t)s * T_TOK + row) * HEADS + k];
            osum += opart[((size_t)s * T_TOK + row) * C_DIM + c];
        }
        ov[(size_t)row * C_DIM + c] = __float2half(osum / lsum);
    }
}

// ---------------- launch ----------------
template <typename Sym>
static void* dev_ptr(const Sym& sym) {
    void* p = nullptr;
    cudaGetSymbolAddress(&p, sym);
    return p;
}

extern "C" void kernel_launch(void* const* d_in, const int* in_sizes, int n_in,
                              void* d_out, int out_size) {
    (void)in_sizes; (void)n_in; (void)out_size;
    const float* x        = (const float*)d_in[0];
    const float* bn_gamma = (const float*)d_in[1];
    const float* bn_beta  = (const float*)d_in[2];
    const float* bn_mean  = (const float*)d_in[3];
    const float* bn_var   = (const float*)d_in[4];
    const float* w_in     = (const float*)d_in[5];
    const float* b_in     = (const float*)d_in[6];
    const float* ln1_g    = (const float*)d_in[7];
    const float* ln1_b    = (const float*)d_in[8];
    const float* w_qkv    = (const float*)d_in[9];
    const float* b_qkv    = (const float*)d_in[10];
    const float* w_ap     = (const float*)d_in[11];
    const float* b_ap     = (const float*)d_in[12];
    const float* ln2_g    = (const float*)d_in[13];
    const float* ln2_b    = (const float*)d_in[14];
    const float* w_ff1    = (const float*)d_in[15];
    const float* b_ff1    = (const float*)d_in[16];
    const float* w_ff2    = (const float*)d_in[17];
    const float* b_ff2    = (const float*)d_in[18];
    const float* w_out    = (const float*)d_in[19];
    const float* b_out    = (const float*)d_in[20];
    float* out = (float*)d_out;

    __half* tok0h = (__half*)dev_ptr(g_tok0h);
    float*  tok   = (float*)dev_ptr(g_tok);
    __half* yh    = (__half*)dev_ptr(g_yh);
    float*  y32   = (float*)dev_ptr(g_y32);
    __half* qkvh  = (__half*)dev_ptr(g_qkvh);
    __half* ovh   = (__half*)dev_ptr(g_ovh);
    float*  tok2  = (float*)dev_ptr(g_tok2);
    __half* zh    = (__half*)dev_ptr(g_zh);
    __half* h1h   = (__half*)dev_ptr(g_h1h);
    __half* tok3h = (__half*)dev_ptr(g_tok3h);
    float*  tmp   = (float*)dev_ptr(g_tmp);
    float*  opart = (float*)dev_ptr(g_opart);
    float*  lpart = (float*)dev_ptr(g_l);
    __half* w_in_h  = (__half*)dev_ptr(g_w_in_h);
    __half* w_qkv_h = (__half*)dev_ptr(g_w_qkv_h);
    __half* w_ap_h  = (__half*)dev_ptr(g_w_ap_h);
    __half* w_ff1_h = (__half*)dev_ptr(g_w_ff1_h);
    __half* w_ff2_h = (__half*)dev_ptr(g_w_ff2_h);
    __half* w_out_h = (__half*)dev_ptr(g_w_out_h);

    static bool attr_set = false;
    if (!attr_set) {
        cudaFuncSetAttribute(gemm_k, cudaFuncAttributeMaxDynamicSharedMemorySize, SMEM_GEMM);
        cudaFuncSetAttribute(attn_k, cudaFuncAttributeMaxDynamicSharedMemorySize, SMEM_ATTN);
        attr_set = true;
    }

    // fused weight conversion
    CvtArgs ca;
    ca.src[0] = w_in;  ca.dst[0] = w_in_h;  ca.n4[0] = C_DIM * C_DIM / 4;
    ca.src[1] = w_qkv; ca.dst[1] = w_qkv_h; ca.n4[1] = C3 * C_DIM / 4;
    ca.src[2] = w_ap;  ca.dst[2] = w_ap_h;  ca.n4[2] = C_DIM * C_DIM / 4;
    ca.src[3] = w_ff1; ca.dst[3] = w_ff1_h; ca.n4[3] = FF * C_DIM / 4;
    ca.src[4] = w_ff2; ca.dst[4] = w_ff2_h; ca.n4[4] = C_DIM * FF / 4;
    ca.src[5] = w_out; ca.dst[5] = w_out_h; ca.n4[5] = C_DIM * C_DIM / 4;
    cvt_all_k<<<448, 256>>>(ca);

    // 1) BN + transpose
    bn_transpose_k<<<dim3(C_DIM / 32, T_TOK / 32), dim3(32, 32)>>>(
        x, bn_gamma, bn_beta, bn_mean, bn_var, tok0h);
    // 2) proj_in -> tok (f32)
    gemm_k<<<dim3(C_DIM / 64, T_TOK / 128), 256, SMEM_GEMM>>>(
        tok0h, w_in_h, b_in, nullptr, nullptr, tok, nullptr, T_TOK, C_DIM, C_DIM, 0);
    // 3) LN1 -> yh + y32
    ln_k<<<T_TOK / 8, 256>>>(tok, ln1_g, ln1_b, yh, y32);
    // 4) QKV -> qkvh (f16)
    gemm_k<<<dim3(C3 / 64, T_TOK / 128), 256, SMEM_GEMM>>>(
        yh, w_qkv_h, b_qkv, nullptr, nullptr, nullptr, qkvh, T_TOK, C3, C_DIM, 0);
    // 5) attention + combine
    attn_k<<<dim3(T_TOK / 128, HEADS, KVS), 256, SMEM_ATTN>>>(qkvh, opart, lpart);
    attn_combine_k<<<T_TOK / 8, 256>>>(opart, lpart, ovh);
    // 6) attn proj + y32 + tok -> tok2 (f32)
    gemm_k<<<dim3(C_DIM / 64, T_TOK / 128), 256, SMEM_GEMM>>>(
        ovh, w_ap_h, b_ap, y32, tok, tok2, nullptr, T_TOK, C_DIM, C_DIM, 0);
    // 7) LN2 -> zh
    ln_k<<<T_TOK / 8, 256>>>(tok2, ln2_g, ln2_b, zh, nullptr);
    // 8) FF1 + gelu -> h1h (f16)
    gemm_k<<<dim3(FF / 64, T_TOK / 128), 256, SMEM_GEMM>>>(
        zh, w_ff1_h, b_ff1, nullptr, nullptr, nullptr, h1h, T_TOK, FF, C_DIM, 1);
    // 9) FF2 + tok2 -> tok3h (f16)
    gemm_k<<<dim3(C_DIM / 64, T_TOK / 128), 256, SMEM_GEMM>>>(
        h1h, w_ff2_h, b_ff2, tok2, nullptr, nullptr, tok3h, T_TOK, C_DIM, FF, 0);
    // 10) proj_out -> tmp (f32)
    gemm_k<<<dim3(C_DIM / 64, T_TOK / 128), 256, SMEM_GEMM>>>(
        tok3h, w_out_h, b_out, nullptr, nullptr, tmp, nullptr, T_TOK, C_DIM, C_DIM, 0);
    // 11) transpose back + image residual
    out_transpose_k<<<dim3(C_DIM / 32, T_TOK / 32), dim3(32, 32)>>>(tmp, x, out);
}